// round 10
// baseline (speedup 1.0000x reference)
#include <cuda_runtime.h>
#include <cstdint>

#define NN 50000
#define NE 800000
#define D  128
#define DE 16
#define DM 128

// ---------------------------------------------------------------------------
// Global scratch
// ---------------------------------------------------------------------------
__device__ float g_agg[NN * DM];
__device__ float g_P[NN * 256];       // P = nf @ [W_s | W_e]  (f32)
__device__ int   g_hist[NN];
__device__ int   g_off[NN];
__device__ int   g_cnt[NN];
__device__ int   g_perm[NE];
// bf16 fragment-packed weights: uint2{b0,b1} per (K16, nb, lane)
__device__ __align__(16) uint2 g_wsb[8 * 16 * 32];    // We1 rows 0..127
__device__ __align__(16) uint2 g_web[8 * 16 * 32];    // We1 rows 128..255
__device__ __align__(16) uint2 g_wefb[2 * 16 * 32];   // We1 rows 256..271 (pad 32)
__device__ __align__(16) uint2 g_w2b[8 * 16 * 32];    // We2, K=128
__device__ __align__(16) uint2 g_wn1b[16 * 16 * 32];  // Wn1, K=256
__device__ __align__(16) uint2 g_wn2b[8 * 16 * 32];   // Wn2, K=128

// ---------------------------------------------------------------------------
// helpers
// ---------------------------------------------------------------------------
__device__ __forceinline__ float siluf(float x) { return x / (1.0f + __expf(-x)); }
__device__ __forceinline__ float sigmoidf_(float x) { return 1.0f / (1.0f + __expf(-x)); }

__device__ __forceinline__ uint32_t bf2(float lo, float hi) {
    uint32_t r;
    asm("cvt.rn.bf16x2.f32 %0, %1, %2;" : "=r"(r) : "f"(hi), "f"(lo));
    return r;
}
__device__ __forceinline__ float bflo(uint32_t u) {
    return __uint_as_float(u << 16);
}
__device__ __forceinline__ float bfhi(uint32_t u) {
    return __uint_as_float(u & 0xffff0000u);
}
__device__ __forceinline__ void mma_bf16(float c[4], const uint32_t a[4],
                                         uint32_t b0, uint32_t b1) {
    asm volatile("mma.sync.aligned.m16n8k16.row.col.f32.bf16.bf16.f32 "
        "{%0,%1,%2,%3}, {%4,%5,%6,%7}, {%8,%9}, {%0,%1,%2,%3};"
        : "+f"(c[0]), "+f"(c[1]), "+f"(c[2]), "+f"(c[3])
        : "r"(a[0]), "r"(a[1]), "r"(a[2]), "r"(a[3]), "r"(b0), "r"(b1));
}

// ---------------------------------------------------------------------------
// Edge kernel SMEM (73216 B total -> 3 CTAs/SM)
//   SB   : S bf16 [128 rows][136 bf16] stride 272B          34816
//   HB   : hbuf bf16 (same shape); Aef [128][80B] aliases   34816
//   mtile: f32 [128][132] (67584B) overlays SB+HB late
// ---------------------------------------------------------------------------
#define E_SB     0
#define E_HB     34816
#define E_MISC   69632
#define E_STARTS (E_MISC)
#define E_ENDS   (E_MISC + 512)
#define E_EIDX   (E_MISC + 1024)
#define E_BE1    (E_MISC + 1536)
#define E_BE2    (E_MISC + 2048)
#define E_WIS    (E_MISC + 2560)
#define E_GATES  (E_MISC + 3072)
#define E_SMEM_BYTES (E_MISC + 3584)   // 73216

__device__ __forceinline__ void store_A(char* Ab, int tid, const float4 va[4]) {
#pragma unroll
    for (int it = 0; it < 4; it++) {
        int seg = tid + it * 256;
        int e = seg >> 3, s8 = seg & 7;
        uint2 u = make_uint2(bf2(va[it].x, va[it].y), bf2(va[it].z, va[it].w));
        *(uint2*)(Ab + e * 80 + s8 * 8) = u;
    }
}

// ---------------------------------------------------------------------------
// Edge kernel: P gather-add (bf16 S) + ef MMA -> silu -> GEMM2 -> gate -> scatter
// ---------------------------------------------------------------------------
__global__ void __launch_bounds__(256, 3)
edge_kernel(const float* __restrict__ nf, const int* __restrict__ ei,
            const float* __restrict__ ef, const float* __restrict__ P,
            const float* __restrict__ be1, const float* __restrict__ be2,
            const float* __restrict__ Wi, const float* __restrict__ bi,
            float* __restrict__ agg) {
    extern __shared__ char smem[];
    float* mtile  = (float*)smem;                 // late-phase overlay, stride 132
    char*  SB     = smem + E_SB;                  // S bf16, 272B stride
    char*  hbuf   = smem + E_HB;                  // h bf16, 272B stride
    char*  Aef    = smem + E_HB;                  // early alias (80B stride)
    int*   starts = (int*)(smem + E_STARTS);
    int*   ends   = (int*)(smem + E_ENDS);
    int*   eidx   = (int*)(smem + E_EIDX);
    float* be1s   = (float*)(smem + E_BE1);
    float* be2s   = (float*)(smem + E_BE2);
    float* wis    = (float*)(smem + E_WIS);
    float* gates  = (float*)(smem + E_GATES);

    const int tid  = threadIdx.x;
    const int lane = tid & 31;
    const int wid  = tid >> 5;
    const int wr   = wid & 3;
    const int wc   = wid >> 2;
    const int g    = lane >> 2;
    const int t    = lane & 3;
    const int e0   = blockIdx.x * 128;

    if (tid < 128) {
        int e = g_perm[e0 + tid];
        eidx[tid]   = e;
        starts[tid] = ei[e];
        ends[tid]   = ei[NE + e];
        be1s[tid]   = be1[tid];
        be2s[tid]   = be2[tid];
        wis[tid]    = Wi[tid];
    }
    __syncthreads();

    // ---- phase A: S = P_s[start] + P_e[end] -> SB (bf16); ef -> Aef ----
#pragma unroll
    for (int it = 0; it < 16; it++) {
        int seg = tid + it * 256;
        int row = seg >> 5, c4 = (seg & 31) * 4;
        int s = starts[row], e_ = ends[row];
        float4 a = *(const float4*)(P + (size_t)s * 256 + c4);
        float4 b = *(const float4*)(P + (size_t)e_ * 256 + 128 + c4);
        uint2 u = make_uint2(bf2(a.x + b.x, a.y + b.y),
                             bf2(a.z + b.z, a.w + b.w));
        *(uint2*)(SB + row * 272 + c4 * 2) = u;
    }
    {
        float4 va[4];
#pragma unroll
        for (int it = 0; it < 4; it++) {
            int seg = tid + it * 256;
            int e = seg >> 3, s8 = seg & 7;
            va[it] = (s8 < 4) ? *(const float4*)(ef + (size_t)eidx[e] * DE + s8 * 4)
                              : make_float4(0.f, 0.f, 0.f, 0.f);
        }
        store_A(Aef, tid, va);
    }
    __syncthreads();

    float acc[2][8][4];
#pragma unroll
    for (int rg = 0; rg < 2; rg++)
#pragma unroll
        for (int nb = 0; nb < 8; nb++)
#pragma unroll
            for (int i = 0; i < 4; i++) acc[rg][nb][i] = 0.0f;

    // ---- ef MMA (K=32, B-frags straight from global/L2) ----
#pragma unroll
    for (int kcl = 0; kcl < 2; kcl++) {
        uint32_t a[2][4];
#pragma unroll
        for (int rg = 0; rg < 2; rg++) {
            const char* p = Aef + (wr * 32 + rg * 16 + g) * 80 + kcl * 32 + t * 4;
            a[rg][0] = *(const uint32_t*)p;
            a[rg][1] = *(const uint32_t*)(p + 8 * 80);
            a[rg][2] = *(const uint32_t*)(p + 16);
            a[rg][3] = *(const uint32_t*)(p + 8 * 80 + 16);
        }
#pragma unroll
        for (int nb = 0; nb < 8; nb++) {
            uint2 b = g_wefb[(kcl * 16 + wc * 8 + nb) * 32 + lane];
            mma_bf16(acc[0][nb], a[0], b.x, b.y);
            mma_bf16(acc[1][nb], a[1], b.x, b.y);
        }
    }
    __syncthreads();   // Aef reads done before hbuf writes

    // ---- Epilogue 1: h = silu(acc + S + be1) -> hbuf (bf16) ----
#pragma unroll
    for (int rg = 0; rg < 2; rg++) {
        int r0 = wr * 32 + rg * 16 + g;
#pragma unroll
        for (int nb = 0; nb < 8; nb++) {
            int col = wc * 64 + nb * 8 + 2 * t;
            uint32_t s0 = *(const uint32_t*)(SB + r0 * 272 + col * 2);
            uint32_t s1 = *(const uint32_t*)(SB + (r0 + 8) * 272 + col * 2);
            float b0 = be1s[col], b1 = be1s[col + 1];
            uint32_t h0 = bf2(siluf(acc[rg][nb][0] + bflo(s0) + b0),
                              siluf(acc[rg][nb][1] + bfhi(s0) + b1));
            uint32_t h1 = bf2(siluf(acc[rg][nb][2] + bflo(s1) + b0),
                              siluf(acc[rg][nb][3] + bfhi(s1) + b1));
            *(uint32_t*)(hbuf + r0 * 272 + col * 2) = h0;
            *(uint32_t*)(hbuf + (r0 + 8) * 272 + col * 2) = h1;
            acc[rg][nb][0] = 0.f; acc[rg][nb][1] = 0.f;
            acc[rg][nb][2] = 0.f; acc[rg][nb][3] = 0.f;
        }
    }
    __syncthreads();

    // ---- GEMM2: D2 = h @ We2 (K=128, B-frags straight from global/L2) ----
#pragma unroll
    for (int K16 = 0; K16 < 8; K16++) {
        uint32_t a[2][4];
#pragma unroll
        for (int rg = 0; rg < 2; rg++) {
            const char* p = hbuf + (wr * 32 + rg * 16 + g) * 272 + K16 * 32 + t * 4;
            a[rg][0] = *(const uint32_t*)p;
            a[rg][1] = *(const uint32_t*)(p + 8 * 272);
            a[rg][2] = *(const uint32_t*)(p + 16);
            a[rg][3] = *(const uint32_t*)(p + 8 * 272 + 16);
        }
#pragma unroll
        for (int nb = 0; nb < 8; nb++) {
            uint2 b = g_w2b[(K16 * 16 + wc * 8 + nb) * 32 + lane];
            mma_bf16(acc[0][nb], a[0], b.x, b.y);
            mma_bf16(acc[1][nb], a[1], b.x, b.y);
        }
    }
    __syncthreads();   // hbuf/SB reads done before mtile overwrite

    // ---- Epilogue 2: m = D2 + be2 -> mtile (f32, overlays SB+hbuf) ----
#pragma unroll
    for (int rg = 0; rg < 2; rg++) {
        int r0 = wr * 32 + rg * 16 + g;
#pragma unroll
        for (int nb = 0; nb < 8; nb++) {
            int col = wc * 64 + nb * 8 + 2 * t;
            float b0 = be2s[col], b1 = be2s[col + 1];
            *(float2*)(mtile + r0 * 132 + col) =
                make_float2(acc[rg][nb][0] + b0, acc[rg][nb][1] + b1);
            *(float2*)(mtile + (r0 + 8) * 132 + col) =
                make_float2(acc[rg][nb][2] + b0, acc[rg][nb][3] + b1);
        }
    }
    __syncthreads();

    // gate
    if (tid < 128) {
        float s = 0.0f;
#pragma unroll 8
        for (int c = 0; c < 128; c++) s += mtile[tid * 132 + c] * wis[c];
        gates[tid] = sigmoidf_(s + bi[0]);
    }
    __syncthreads();

    // segmented gated scatter (rows sorted by start)
    {
        const int c  = tid & 127;
        const int r0 = (tid >> 7) * 64;
        float accv = 0.0f;
        int sprev = starts[r0];
        for (int r = r0; r < r0 + 64; r++) {
            int s = starts[r];
            if (s != sprev) {
                atomicAdd(agg + (size_t)sprev * DM + c, accv);
                accv = 0.0f;
                sprev = s;
            }
            accv += mtile[r * 132 + c] * gates[r];
        }
        atomicAdd(agg + (size_t)sprev * DM + c, accv);
    }
}

// ===========================================================================
// P KERNEL: P[:, half*128 : +128] = nf @ (half ? W_e : W_s)
// ===========================================================================
#define P_A 0
#define P_B 34816
#define P_SMEM_BYTES 67584

__global__ void __launch_bounds__(256, 2)
p_kernel(const float* __restrict__ nf, float* __restrict__ P) {
    extern __shared__ char smem[];
    char* Ab = smem + P_A;

    const int tid  = threadIdx.x;
    const int lane = tid & 31;
    const int wid  = tid >> 5;
    const int wr   = wid & 3;
    const int wc   = wid >> 2;
    const int g    = lane >> 2;
    const int t    = lane & 3;
    const int n0   = blockIdx.x * 128;
    const int half = blockIdx.y;

    {
        const float4* src = (const float4*)(half ? g_web : g_wsb);
        float4* dst = (float4*)(smem + P_B);
#pragma unroll
        for (int it = 0; it < 8; it++) dst[tid + it * 256] = src[tid + it * 256];
    }
#pragma unroll
    for (int it = 0; it < 8; it++) {
        int seg = tid + it * 256;
        int row = seg >> 4, c8 = seg & 15;
        int n = n0 + row; if (n >= NN) n = NN - 1;
        float4 f0 = *(const float4*)(nf + (size_t)n * D + c8 * 8);
        float4 f1 = *(const float4*)(nf + (size_t)n * D + c8 * 8 + 4);
        uint4 u = make_uint4(bf2(f0.x, f0.y), bf2(f0.z, f0.w),
                             bf2(f1.x, f1.y), bf2(f1.z, f1.w));
        *(uint4*)(Ab + row * 272 + c8 * 16) = u;
    }
    __syncthreads();

    float acc[2][8][4];
#pragma unroll
    for (int rg = 0; rg < 2; rg++)
#pragma unroll
        for (int nb = 0; nb < 8; nb++)
#pragma unroll
            for (int i = 0; i < 4; i++) acc[rg][nb][i] = 0.0f;

    {
        const uint2* Bs = (const uint2*)(smem + P_B);
#pragma unroll
        for (int K16 = 0; K16 < 8; K16++) {
            uint32_t a[2][4];
#pragma unroll
            for (int rg = 0; rg < 2; rg++) {
                const char* p = Ab + (wr * 32 + rg * 16 + g) * 272 + K16 * 32 + t * 4;
                a[rg][0] = *(const uint32_t*)p;
                a[rg][1] = *(const uint32_t*)(p + 8 * 272);
                a[rg][2] = *(const uint32_t*)(p + 16);
                a[rg][3] = *(const uint32_t*)(p + 8 * 272 + 16);
            }
#pragma unroll
            for (int nb = 0; nb < 8; nb++) {
                uint2 b = Bs[(K16 * 16 + wc * 8 + nb) * 32 + lane];
                mma_bf16(acc[0][nb], a[0], b.x, b.y);
                mma_bf16(acc[1][nb], a[1], b.x, b.y);
            }
        }
    }

#pragma unroll
    for (int rg = 0; rg < 2; rg++) {
        int r0 = wr * 32 + rg * 16 + g;
#pragma unroll
        for (int h = 0; h < 2; h++) {
            int n = n0 + r0 + 8 * h;
            if (n >= NN) continue;
#pragma unroll
            for (int nb = 0; nb < 8; nb++) {
                int col = wc * 64 + nb * 8 + 2 * t;
                float a0 = h ? acc[rg][nb][2] : acc[rg][nb][0];
                float a1 = h ? acc[rg][nb][3] : acc[rg][nb][1];
                *(float2*)(P + (size_t)n * 256 + half * 128 + col) = make_float2(a0, a1);
            }
        }
    }
}

// ===========================================================================
// INIT KERNEL: zero agg/hist/cnt + pack all weights (single launch)
// ===========================================================================
__device__ __forceinline__ uint2 pack_frag2(const float* W, int idx, int row0, int rowlim) {
    int lane = idx & 31;
    int nbk = idx >> 5;
    int k0 = (nbk >> 4) * 16;
    int n = (nbk & 15) * 8 + (lane >> 2);
    int t2 = (lane & 3) * 2;
    int r = row0 + k0 + t2;
    float v00 = (r     < rowlim) ? W[(size_t)r * 128 + n] : 0.0f;
    float v01 = (r + 1 < rowlim) ? W[(size_t)(r + 1) * 128 + n] : 0.0f;
    float v10 = (r + 8 < rowlim) ? W[(size_t)(r + 8) * 128 + n] : 0.0f;
    float v11 = (r + 9 < rowlim) ? W[(size_t)(r + 9) * 128 + n] : 0.0f;
    return make_uint2(bf2(v00, v01), bf2(v10, v11));
}

__global__ void init_kernel(const float* __restrict__ We1, const float* __restrict__ We2,
                            const float* __restrict__ Wn1, const float* __restrict__ Wn2) {
    int i = blockIdx.x * 256 + threadIdx.x;   // grid: 400 blocks -> 102400 threads
    if (i < 4096)        g_wsb[i] = pack_frag2(We1, i, 0, 272);
    else if (i < 8192)   g_web[i - 4096] = pack_frag2(We1, i - 4096, 128, 272);
    else if (i < 9216)   g_wefb[i - 8192] = pack_frag2(We1, i - 8192, 256, 272);
    else if (i < 13312)  g_w2b[i - 9216] = pack_frag2(We2, i - 9216, 0, 128);
    else if (i < 21504)  g_wn1b[i - 13312] = pack_frag2(Wn1, i - 13312, 0, 256);
    else if (i < 25600)  g_wn2b[i - 21504] = pack_frag2(Wn2, i - 21504, 0, 128);
    // zero agg (1.6M float4), hist, cnt
    float4 z4 = make_float4(0.f, 0.f, 0.f, 0.f);
    for (int j = i; j < NN * DM / 4; j += 102400)
        ((float4*)g_agg)[j] = z4;
    if (i < NN) { g_hist[i] = 0; g_cnt[i] = 0; }
}

// ===========================================================================
// Counting sort
// ===========================================================================
__global__ void hist_kernel(const int* __restrict__ ei) {
    int e = blockIdx.x * 256 + threadIdx.x;
    if (e < NE) atomicAdd(&g_hist[ei[e]], 1);
}

__global__ void scan_kernel() {
    const int CH = 49;
    __shared__ int ws[32];
    int t = threadIdx.x;
    int base = t * CH;
    int sum = 0;
#pragma unroll 7
    for (int i = 0; i < CH; i++) {
        int idx = base + i;
        if (idx < NN) sum += g_hist[idx];
    }
    int lane = t & 31, wid = t >> 5;
    int v = sum;
#pragma unroll
    for (int o = 1; o < 32; o <<= 1) {
        int u = __shfl_up_sync(0xffffffffu, v, o);
        if (lane >= o) v += u;
    }
    if (lane == 31) ws[wid] = v;
    __syncthreads();
    if (wid == 0) {
        int w = ws[lane];
#pragma unroll
        for (int o = 1; o < 32; o <<= 1) {
            int u = __shfl_up_sync(0xffffffffu, w, o);
            if (lane >= o) w += u;
        }
        ws[lane] = w;
    }
    __syncthreads();
    int pre = v - sum + (wid > 0 ? ws[wid - 1] : 0);
    int run = pre;
    for (int i = 0; i < CH; i++) {
        int idx = base + i;
        if (idx < NN) {
            int h = g_hist[idx];
            g_off[idx] = run;
            run += h;
        }
    }
}

__global__ void permute_kernel(const int* __restrict__ ei) {
    int e = blockIdx.x * 256 + threadIdx.x;
    if (e < NE) {
        int s = ei[e];
        int pos = g_off[s] + atomicAdd(&g_cnt[s], 1);
        g_perm[pos] = e;
    }
}

// ===========================================================================
// NODE KERNEL — bf16 mma, fp32 residual (validated R7-R9)
// ===========================================================================
#define N_A0  0
#define N_A1  10240
#define N_B0  20480
#define N_B1  28672
#define N_HB  36864
#define N_BN1 71680
#define N_BN2 72192
#define N_SMEM_BYTES 72704

__global__ void __launch_bounds__(256, 2)
node_kernel(const float* __restrict__ nf, const float* __restrict__ agg,
            const float* __restrict__ bn1, const float* __restrict__ bn2,
            float* __restrict__ out) {
    extern __shared__ char smem[];
    char*  hbuf  = smem + N_HB;
    float* bn1s  = (float*)(smem + N_BN1);
    float* bn2s  = (float*)(smem + N_BN2);

    const int tid  = threadIdx.x;
    const int lane = tid & 31;
    const int wid  = tid >> 5;
    const int wr   = wid & 3;
    const int wc   = wid >> 2;
    const int g    = lane >> 2;
    const int t    = lane & 3;
    const int n0   = blockIdx.x * 128;

    if (tid < 128) { bn1s[tid] = bn1[tid]; bn2s[tid] = bn2[tid]; }

    float acc[2][8][4];
#pragma unroll
    for (int rg = 0; rg < 2; rg++)
#pragma unroll
        for (int nb = 0; nb < 8; nb++)
#pragma unroll
            for (int i = 0; i < 4; i++) acc[rg][nb][i] = 0.0f;

    {
        float4 va[4], vb[2];
        const float4* w1 = (const float4*)g_wn1b;
#pragma unroll
        for (int it = 0; it < 4; it++) {
            int seg = tid + it * 256;
            int e = seg >> 3, s8 = seg & 7;
            int n = n0 + e; if (n >= NN) n = NN - 1;
            va[it] = *(const float4*)(nf + (size_t)n * D + s8 * 4);
        }
#pragma unroll
        for (int it = 0; it < 2; it++) vb[it] = w1[tid + it * 256];
        store_A(smem + N_A0, tid, va);
        {
            float4* dst = (float4*)(smem + N_B0);
#pragma unroll
            for (int it = 0; it < 2; it++) dst[tid + it * 256] = vb[it];
        }
        __syncthreads();

        for (int c = 0; c < 8; c++) {
            const int buf = c & 1;
            if (c < 7) {
                int cn = c + 1;
#pragma unroll
                for (int it = 0; it < 4; it++) {
                    int seg = tid + it * 256;
                    int e = seg >> 3, s8 = seg & 7;
                    int n = n0 + e; if (n >= NN) n = NN - 1;
                    const float* src = (cn < 4)
                        ? nf  + (size_t)n * D  + cn * 32 + s8 * 4
                        : agg + (size_t)n * DM + (cn - 4) * 32 + s8 * 4;
                    va[it] = *(const float4*)src;
                }
#pragma unroll
                for (int it = 0; it < 2; it++)
                    vb[it] = w1[cn * 512 + tid + it * 256];
            }
            const char* Ab = smem + (buf ? N_A1 : N_A0);
            const uint2* Bs = (const uint2*)(smem + (buf ? N_B1 : N_B0));
#pragma unroll
            for (int kcl = 0; kcl < 2; kcl++) {
                uint32_t a[2][4];
#pragma unroll
                for (int rg = 0; rg < 2; rg++) {
                    const char* p = Ab + (wr * 32 + rg * 16 + g) * 80 + kcl * 32 + t * 4;
                    a[rg][0] = *(const uint32_t*)p;
                    a[rg][1] = *(const uint32_t*)(p + 8 * 80);
                    a[rg][2] = *(const uint32_t*)(p + 16);
                    a[rg][3] = *(const uint32_t*)(p + 8 * 80 + 16);
                }
#pragma unroll
                for (int nb = 0; nb < 8; nb++) {
                    uint2 b = Bs[(kcl * 16 + wc * 8 + nb) * 32 + lane];
                    mma_bf16(acc[0][nb], a[0], b.x, b.y);
                    mma_bf16(acc[1][nb], a[1], b.x, b.y);
                }
            }
            __syncthreads();
            if (c < 7) {
                store_A(smem + (((c + 1) & 1) ? N_A1 : N_A0), tid, va);
                float4* dst = (float4*)(smem + (((c + 1) & 1) ? N_B1 : N_B0));
#pragma unroll
                for (int it = 0; it < 2; it++) dst[tid + it * 256] = vb[it];
                __syncthreads();
            }
        }
    }

    {
        const float4* src = (const float4*)g_wn2b;
        float4* dst = (float4*)(smem + N_A0);
#pragma unroll
        for (int it = 0; it < 8; it++) dst[tid + it * 256] = src[tid + it * 256];
    }
#pragma unroll
    for (int rg = 0; rg < 2; rg++) {
        int row0 = wr * 32 + rg * 16 + g;
#pragma unroll
        for (int nb = 0; nb < 8; nb++) {
            int col = wc * 64 + nb * 8 + 2 * t;
            float b0 = bn1s[col], b1 = bn1s[col + 1];
            uint32_t h0 = bf2(siluf(acc[rg][nb][0] + b0), siluf(acc[rg][nb][1] + b1));
            uint32_t h1 = bf2(siluf(acc[rg][nb][2] + b0), siluf(acc[rg][nb][3] + b1));
            *(uint32_t*)(hbuf + row0 * 272 + col * 2) = h0;
            *(uint32_t*)(hbuf + (row0 + 8) * 272 + col * 2) = h1;
            acc[rg][nb][0] = 0.f; acc[rg][nb][1] = 0.f;
            acc[rg][nb][2] = 0.f; acc[rg][nb][3] = 0.f;
        }
    }
    __syncthreads();

    {
        const uint2* B2 = (const uint2*)(smem + N_A0);
#pragma unroll
        for (int K16 = 0; K16 < 8; K16++) {
            uint32_t a[2][4];
#pragma unroll
            for (int rg = 0; rg < 2; rg++) {
                const char* p = hbuf + (wr * 32 + rg * 16 + g) * 272 + K16 * 32 + t * 4;
                a[rg][0] = *(const uint32_t*)p;
                a[rg][1] = *(const uint32_t*)(p + 8 * 272);
                a[rg][2] = *(const uint32_t*)(p + 16);
                a[rg][3] = *(const uint32_t*)(p + 8 * 272 + 16);
            }
#pragma unroll
            for (int nb = 0; nb < 8; nb++) {
                uint2 b = B2[(K16 * 16 + wc * 8 + nb) * 32 + lane];
                mma_bf16(acc[0][nb], a[0], b.x, b.y);
                mma_bf16(acc[1][nb], a[1], b.x, b.y);
            }
        }
    }

#pragma unroll
    for (int rg = 0; rg < 2; rg++) {
        int r0 = wr * 32 + rg * 16 + g;
#pragma unroll
        for (int h = 0; h < 2; h++) {
            int n = n0 + r0 + 8 * h;
            if (n >= NN) continue;
#pragma unroll
            for (int nb = 0; nb < 8; nb++) {
                int col = wc * 64 + nb * 8 + 2 * t;
                float2 res = *(const float2*)(nf + (size_t)n * D + col);
                float a0 = (h ? acc[rg][nb][2] : acc[rg][nb][0]) + bn2s[col] + res.x;
                float a1 = (h ? acc[rg][nb][3] : acc[rg][nb][1]) + bn2s[col + 1] + res.y;
                *(float2*)(out + (size_t)n * D + col) = make_float2(a0, a1);
            }
        }
    }
}

// ---------------------------------------------------------------------------
__global__ void idx_to_float_kernel(const int4* __restrict__ ei,
                                    float4* __restrict__ out) {
    int i = blockIdx.x * blockDim.x + threadIdx.x;
    if (i < (2 * NE) / 4) {
        int4 v = ei[i];
        out[i] = make_float4((float)v.x, (float)v.y, (float)v.z, (float)v.w);
    }
}

// ---------------------------------------------------------------------------
extern "C" void kernel_launch(void* const* d_in, const int* in_sizes, int n_in,
                              void* d_out, int out_size) {
    const float* nf  = (const float*)d_in[0];
    const int*   ei  = (const int*)d_in[1];
    const float* ef  = (const float*)d_in[2];
    const float* We1 = (const float*)d_in[3];
    const float* be1 = (const float*)d_in[4];
    const float* We2 = (const float*)d_in[5];
    const float* be2 = (const float*)d_in[6];
    const float* Wi  = (const float*)d_in[7];
    const float* bi  = (const float*)d_in[8];
    const float* Wn1 = (const float*)d_in[9];
    const float* bn1 = (const float*)d_in[10];
    const float* Wn2 = (const float*)d_in[11];
    const float* bn2 = (const float*)d_in[12];
    float* out = (float*)d_out;

    cudaFuncSetAttribute(edge_kernel, cudaFuncAttributeMaxDynamicSharedMemorySize, E_SMEM_BYTES);
    cudaFuncSetAttribute(node_kernel, cudaFuncAttributeMaxDynamicSharedMemorySize, N_SMEM_BYTES);
    cudaFuncSetAttribute(p_kernel, cudaFuncAttributeMaxDynamicSharedMemorySize, P_SMEM_BYTES);

    void *aggp, *pp;
    cudaGetSymbolAddress(&aggp, g_agg);
    cudaGetSymbolAddress(&pp, g_P);

    // launch order puts edge_kernel at index 5 for ncu -s 5 -c 1
    init_kernel<<<400, 256>>>(We1, We2, Wn1, Wn2);
    hist_kernel<<<NE / 256, 256>>>(ei);
    scan_kernel<<<1, 1024>>>();
    permute_kernel<<<NE / 256, 256>>>(ei);
    p_kernel<<<dim3((NN + 127) / 128, 2), 256, P_SMEM_BYTES>>>(nf, (float*)pp);

    edge_kernel<<<NE / 128, 256, E_SMEM_BYTES>>>(nf, ei, ef, (const float*)pp,
                                                 be1, be2, Wi, bi, (float*)aggp);
    node_kernel<<<(NN + 127) / 128, 256, N_SMEM_BYTES>>>(nf, (const float*)aggp,
                                                         bn1, bn2, out);

    idx_to_float_kernel<<<((2 * NE / 4) + 255) / 256, 256>>>(
        (const int4*)ei, (float4*)(out + (size_t)NN * D));
    cudaMemcpyAsync(out + (size_t)NN * D + 2ull * NE, d_in[2],
                    (size_t)NE * DE * sizeof(float), cudaMemcpyDeviceToDevice);
}

// round 11
// speedup vs baseline: 1.0516x; 1.0516x over previous
#include <cuda_runtime.h>
#include <cstdint>

#define NN 50000
#define NE 800000
#define D  128
#define DE 16
#define DM 128

// ---------------------------------------------------------------------------
// Global scratch (g_hist/g_cnt/g_agg are zero at module load; each call
// re-zeros them at the END for the next call -> deterministic every call)
// ---------------------------------------------------------------------------
__device__ float g_agg[NN * DM];
__device__ float g_P[NN * 256];
__device__ int   g_hist[NN];
__device__ int   g_off[NN];
__device__ int   g_cnt[NN];
__device__ int   g_perm[NE];
__device__ __align__(16) uint2 g_wsb[8 * 16 * 32];    // We1 rows 0..127
__device__ __align__(16) uint2 g_web[8 * 16 * 32];    // We1 rows 128..255
__device__ __align__(16) uint2 g_wefb[2 * 16 * 32];   // We1 rows 256..271 (pad 32)
__device__ __align__(16) uint2 g_w2b[8 * 16 * 32];    // We2
__device__ __align__(16) uint2 g_wn1b[16 * 16 * 32];  // Wn1
__device__ __align__(16) uint2 g_wn2b[8 * 16 * 32];   // Wn2

// ---------------------------------------------------------------------------
// helpers
// ---------------------------------------------------------------------------
__device__ __forceinline__ float siluf(float x) { return x / (1.0f + __expf(-x)); }
__device__ __forceinline__ float sigmoidf_(float x) { return 1.0f / (1.0f + __expf(-x)); }

__device__ __forceinline__ uint32_t bf2(float lo, float hi) {
    uint32_t r;
    asm("cvt.rn.bf16x2.f32 %0, %1, %2;" : "=r"(r) : "f"(hi), "f"(lo));
    return r;
}
__device__ __forceinline__ float bflo(uint32_t u) { return __uint_as_float(u << 16); }
__device__ __forceinline__ float bfhi(uint32_t u) { return __uint_as_float(u & 0xffff0000u); }
__device__ __forceinline__ void mma_bf16(float c[4], const uint32_t a[4],
                                         uint32_t b0, uint32_t b1) {
    asm volatile("mma.sync.aligned.m16n8k16.row.col.f32.bf16.bf16.f32 "
        "{%0,%1,%2,%3}, {%4,%5,%6,%7}, {%8,%9}, {%0,%1,%2,%3};"
        : "+f"(c[0]), "+f"(c[1]), "+f"(c[2]), "+f"(c[3])
        : "r"(a[0]), "r"(a[1]), "r"(a[2]), "r"(a[3]), "r"(b0), "r"(b1));
}

__device__ __forceinline__ void store_A(char* Ab, int tid, const float4 va[4]) {
#pragma unroll
    for (int it = 0; it < 4; it++) {
        int seg = tid + it * 256;
        int e = seg >> 3, s8 = seg & 7;
        uint2 u = make_uint2(bf2(va[it].x, va[it].y), bf2(va[it].z, va[it].w));
        *(uint2*)(Ab + e * 80 + s8 * 8) = u;
    }
}

// ---------------------------------------------------------------------------
// Edge kernel SMEM (114176 B -> 2 CTAs/SM)
//   SB  bf16 [128 x 272B]      0..34816
//   HB  bf16 [128 x 272B]      34816..69632  (Aef aliases early)
//   W2S 32768                  69632..102400
//   WEF 8192                   102400..110592
//   mtile f32 [128][132] = 67584 overlays SB+HB late
// ---------------------------------------------------------------------------
#define E_SB     0
#define E_HB     34816
#define E_W2S    69632
#define E_WEF    102400
#define E_MISC   110592
#define E_STARTS (E_MISC)
#define E_ENDS   (E_MISC + 512)
#define E_EIDX   (E_MISC + 1024)
#define E_BE1    (E_MISC + 1536)
#define E_BE2    (E_MISC + 2048)
#define E_WIS    (E_MISC + 2560)
#define E_GATES  (E_MISC + 3072)
#define E_SMEM_BYTES (E_MISC + 3584)   // 114176

__global__ void __launch_bounds__(256, 2)
edge_kernel(const float* __restrict__ nf, const int* __restrict__ ei,
            const float* __restrict__ ef, const float* __restrict__ P,
            const float* __restrict__ be1, const float* __restrict__ be2,
            const float* __restrict__ Wi, const float* __restrict__ bi,
            float* __restrict__ agg) {
    extern __shared__ char smem[];
    float* mtile  = (float*)smem;
    char*  SB     = smem + E_SB;
    char*  hbuf   = smem + E_HB;
    char*  Aef    = smem + E_HB;
    int*   starts = (int*)(smem + E_STARTS);
    int*   ends   = (int*)(smem + E_ENDS);
    int*   eidx   = (int*)(smem + E_EIDX);
    float* be1s   = (float*)(smem + E_BE1);
    float* be2s   = (float*)(smem + E_BE2);
    float* wis    = (float*)(smem + E_WIS);
    float* gates  = (float*)(smem + E_GATES);

    const int tid  = threadIdx.x;
    const int lane = tid & 31;
    const int wid  = tid >> 5;
    const int wr   = wid & 3;
    const int wc   = wid >> 2;
    const int g    = lane >> 2;
    const int t    = lane & 3;
    const int e0   = blockIdx.x * 128;

    if (tid < 128) {
        int e = g_perm[e0 + tid];
        eidx[tid]   = e;
        starts[tid] = ei[e];
        ends[tid]   = ei[NE + e];
        be1s[tid]   = be1[tid];
        be2s[tid]   = be2[tid];
        wis[tid]    = Wi[tid];
    }
    __syncthreads();

    // ---- phase A: stage W2+Wef, P gather-add -> SB (bf16), ef -> Aef ----
    {
        const float4* w2 = (const float4*)g_w2b;
        float4* d2 = (float4*)(smem + E_W2S);
#pragma unroll
        for (int it = 0; it < 8; it++) d2[tid + it * 256] = w2[tid + it * 256];
        const float4* wf = (const float4*)g_wefb;
        float4* df = (float4*)(smem + E_WEF);
#pragma unroll
        for (int it = 0; it < 2; it++) df[tid + it * 256] = wf[tid + it * 256];
    }
#pragma unroll
    for (int it = 0; it < 16; it++) {
        int seg = tid + it * 256;
        int row = seg >> 5, c4 = (seg & 31) * 4;
        int s = starts[row], e_ = ends[row];
        float4 a = *(const float4*)(P + (size_t)s * 256 + c4);
        float4 b = *(const float4*)(P + (size_t)e_ * 256 + 128 + c4);
        uint2 u = make_uint2(bf2(a.x + b.x, a.y + b.y),
                             bf2(a.z + b.z, a.w + b.w));
        *(uint2*)(SB + row * 272 + c4 * 2) = u;
    }
    {
        float4 va[4];
#pragma unroll
        for (int it = 0; it < 4; it++) {
            int seg = tid + it * 256;
            int e = seg >> 3, s8 = seg & 7;
            va[it] = (s8 < 4) ? *(const float4*)(ef + (size_t)eidx[e] * DE + s8 * 4)
                              : make_float4(0.f, 0.f, 0.f, 0.f);
        }
        store_A(Aef, tid, va);
    }
    __syncthreads();

    float acc[2][8][4];
#pragma unroll
    for (int rg = 0; rg < 2; rg++)
#pragma unroll
        for (int nb = 0; nb < 8; nb++)
#pragma unroll
            for (int i = 0; i < 4; i++) acc[rg][nb][i] = 0.0f;

    // ---- ef MMA (K=32) ----
    {
        const uint2* Bs = (const uint2*)(smem + E_WEF);
#pragma unroll
        for (int kcl = 0; kcl < 2; kcl++) {
            uint32_t a[2][4];
#pragma unroll
            for (int rg = 0; rg < 2; rg++) {
                const char* p = Aef + (wr * 32 + rg * 16 + g) * 80 + kcl * 32 + t * 4;
                a[rg][0] = *(const uint32_t*)p;
                a[rg][1] = *(const uint32_t*)(p + 8 * 80);
                a[rg][2] = *(const uint32_t*)(p + 16);
                a[rg][3] = *(const uint32_t*)(p + 8 * 80 + 16);
            }
#pragma unroll
            for (int nb = 0; nb < 8; nb++) {
                uint2 b = Bs[(kcl * 16 + wc * 8 + nb) * 32 + lane];
                mma_bf16(acc[0][nb], a[0], b.x, b.y);
                mma_bf16(acc[1][nb], a[1], b.x, b.y);
            }
        }
    }
    __syncthreads();   // Aef dead before hbuf writes

    // ---- Epilogue 1: h = silu(acc + S + be1) -> hbuf (bf16) ----
#pragma unroll
    for (int rg = 0; rg < 2; rg++) {
        int r0 = wr * 32 + rg * 16 + g;
#pragma unroll
        for (int nb = 0; nb < 8; nb++) {
            int col = wc * 64 + nb * 8 + 2 * t;
            uint32_t s0 = *(const uint32_t*)(SB + r0 * 272 + col * 2);
            uint32_t s1 = *(const uint32_t*)(SB + (r0 + 8) * 272 + col * 2);
            float b0 = be1s[col], b1 = be1s[col + 1];
            uint32_t h0 = bf2(siluf(acc[rg][nb][0] + bflo(s0) + b0),
                              siluf(acc[rg][nb][1] + bfhi(s0) + b1));
            uint32_t h1 = bf2(siluf(acc[rg][nb][2] + bflo(s1) + b0),
                              siluf(acc[rg][nb][3] + bfhi(s1) + b1));
            *(uint32_t*)(hbuf + r0 * 272 + col * 2) = h0;
            *(uint32_t*)(hbuf + (r0 + 8) * 272 + col * 2) = h1;
            acc[rg][nb][0] = 0.f; acc[rg][nb][1] = 0.f;
            acc[rg][nb][2] = 0.f; acc[rg][nb][3] = 0.f;
        }
    }
    __syncthreads();

    // ---- GEMM2: D2 = h @ We2 (K=128, B from smem) ----
    {
        const uint2* B2 = (const uint2*)(smem + E_W2S);
#pragma unroll
        for (int K16 = 0; K16 < 8; K16++) {
            uint32_t a[2][4];
#pragma unroll
            for (int rg = 0; rg < 2; rg++) {
                const char* p = hbuf + (wr * 32 + rg * 16 + g) * 272 + K16 * 32 + t * 4;
                a[rg][0] = *(const uint32_t*)p;
                a[rg][1] = *(const uint32_t*)(p + 8 * 272);
                a[rg][2] = *(const uint32_t*)(p + 16);
                a[rg][3] = *(const uint32_t*)(p + 8 * 272 + 16);
            }
#pragma unroll
            for (int nb = 0; nb < 8; nb++) {
                uint2 b = B2[(K16 * 16 + wc * 8 + nb) * 32 + lane];
                mma_bf16(acc[0][nb], a[0], b.x, b.y);
                mma_bf16(acc[1][nb], a[1], b.x, b.y);
            }
        }
    }
    __syncthreads();   // SB+hbuf dead before mtile overwrite

    // ---- Epilogue 2: m = D2 + be2 -> mtile ----
#pragma unroll
    for (int rg = 0; rg < 2; rg++) {
        int r0 = wr * 32 + rg * 16 + g;
#pragma unroll
        for (int nb = 0; nb < 8; nb++) {
            int col = wc * 64 + nb * 8 + 2 * t;
            float b0 = be2s[col], b1 = be2s[col + 1];
            *(float2*)(mtile + r0 * 132 + col) =
                make_float2(acc[rg][nb][0] + b0, acc[rg][nb][1] + b1);
            *(float2*)(mtile + (r0 + 8) * 132 + col) =
                make_float2(acc[rg][nb][2] + b0, acc[rg][nb][3] + b1);
        }
    }
    __syncthreads();

    // gate
    if (tid < 128) {
        float s = 0.0f;
#pragma unroll 8
        for (int c = 0; c < 128; c++) s += mtile[tid * 132 + c] * wis[c];
        gates[tid] = sigmoidf_(s + bi[0]);
    }
    __syncthreads();

    // segmented gated scatter (rows sorted by start)
    {
        const int c  = tid & 127;
        const int r0 = (tid >> 7) * 64;
        float accv = 0.0f;
        int sprev = starts[r0];
        for (int r = r0; r < r0 + 64; r++) {
            int s = starts[r];
            if (s != sprev) {
                atomicAdd(agg + (size_t)sprev * DM + c, accv);
                accv = 0.0f;
                sprev = s;
            }
            accv += mtile[r * 132 + c] * gates[r];
        }
        atomicAdd(agg + (size_t)sprev * DM + c, accv);
    }
}

// ===========================================================================
// Launch 1: hist + weight pack (hist/cnt/agg pre-zeroed by previous call)
// ===========================================================================
__device__ __forceinline__ uint2 pack_frag2(const float* W, int idx, int row0, int rowlim) {
    int lane = idx & 31;
    int nbk = idx >> 5;
    int k0 = (nbk >> 4) * 16;
    int n = (nbk & 15) * 8 + (lane >> 2);
    int t2 = (lane & 3) * 2;
    int r = row0 + k0 + t2;
    float v00 = (r     < rowlim) ? W[(size_t)r * 128 + n] : 0.0f;
    float v01 = (r + 1 < rowlim) ? W[(size_t)(r + 1) * 128 + n] : 0.0f;
    float v10 = (r + 8 < rowlim) ? W[(size_t)(r + 8) * 128 + n] : 0.0f;
    float v11 = (r + 9 < rowlim) ? W[(size_t)(r + 9) * 128 + n] : 0.0f;
    return make_uint2(bf2(v00, v01), bf2(v10, v11));
}

__global__ void hist_pack_kernel(const int* __restrict__ ei,
                                 const float* __restrict__ We1, const float* __restrict__ We2,
                                 const float* __restrict__ Wn1, const float* __restrict__ Wn2) {
    int i = blockIdx.x * 256 + threadIdx.x;     // grid 3125 -> 800000 threads
    if (i < 4096)        g_wsb[i] = pack_frag2(We1, i, 0, 272);
    else if (i < 8192)   g_web[i - 4096] = pack_frag2(We1, i - 4096, 128, 272);
    else if (i < 9216)   g_wefb[i - 8192] = pack_frag2(We1, i - 8192, 256, 272);
    else if (i < 13312)  g_w2b[i - 9216] = pack_frag2(We2, i - 9216, 0, 128);
    else if (i < 21504)  g_wn1b[i - 13312] = pack_frag2(Wn1, i - 13312, 0, 256);
    else if (i < 25600)  g_wn2b[i - 21504] = pack_frag2(Wn2, i - 21504, 0, 128);
    if (i < NE) atomicAdd(&g_hist[ei[i]], 1);
}

// ===========================================================================
// Launch 2: scan
// ===========================================================================
__global__ void scan_kernel() {
    const int CH = 49;
    __shared__ int ws[32];
    int t = threadIdx.x;
    int base = t * CH;
    int sum = 0;
#pragma unroll 7
    for (int i = 0; i < CH; i++) {
        int idx = base + i;
        if (idx < NN) sum += g_hist[idx];
    }
    int lane = t & 31, wid = t >> 5;
    int v = sum;
#pragma unroll
    for (int o = 1; o < 32; o <<= 1) {
        int u = __shfl_up_sync(0xffffffffu, v, o);
        if (lane >= o) v += u;
    }
    if (lane == 31) ws[wid] = v;
    __syncthreads();
    if (wid == 0) {
        int w = ws[lane];
#pragma unroll
        for (int o = 1; o < 32; o <<= 1) {
            int u = __shfl_up_sync(0xffffffffu, w, o);
            if (lane >= o) w += u;
        }
        ws[lane] = w;
    }
    __syncthreads();
    int pre = v - sum + (wid > 0 ? ws[wid - 1] : 0);
    int run = pre;
    for (int i = 0; i < CH; i++) {
        int idx = base + i;
        if (idx < NN) {
            int h = g_hist[idx];
            g_off[idx] = run;
            run += h;
        }
    }
}

// ===========================================================================
// Launch 3: fused permute + P GEMM
//   blocks [0, 782)  : P half-tiles (n0 = (b%391)*128, half = b/391)
//   blocks [782, 3907): permute
// ===========================================================================
#define PP_PBLK 782
#define P_A 0
#define P_B 34816
#define P_SMEM_BYTES 67584

__global__ void __launch_bounds__(256, 2)
pp_kernel(const int* __restrict__ ei, const float* __restrict__ nf,
          float* __restrict__ P) {
    extern __shared__ char smem[];
    const int tid = threadIdx.x;

    if (blockIdx.x >= PP_PBLK) {
        int e = (blockIdx.x - PP_PBLK) * 256 + tid;
        if (e < NE) {
            int s = ei[e];
            int pos = g_off[s] + atomicAdd(&g_cnt[s], 1);
            g_perm[pos] = e;
        }
        return;
    }

    char* Ab = smem + P_A;
    const int lane = tid & 31;
    const int wid  = tid >> 5;
    const int wr   = wid & 3;
    const int wc   = wid >> 2;
    const int g    = lane >> 2;
    const int t    = lane & 3;
    const int n0   = (blockIdx.x % 391) * 128;
    const int half = blockIdx.x / 391;

    {
        const float4* src = (const float4*)(half ? g_web : g_wsb);
        float4* dst = (float4*)(smem + P_B);
#pragma unroll
        for (int it = 0; it < 8; it++) dst[tid + it * 256] = src[tid + it * 256];
    }
#pragma unroll
    for (int it = 0; it < 8; it++) {
        int seg = tid + it * 256;
        int row = seg >> 4, c8 = seg & 15;
        int n = n0 + row; if (n >= NN) n = NN - 1;
        float4 f0 = *(const float4*)(nf + (size_t)n * D + c8 * 8);
        float4 f1 = *(const float4*)(nf + (size_t)n * D + c8 * 8 + 4);
        uint4 u = make_uint4(bf2(f0.x, f0.y), bf2(f0.z, f0.w),
                             bf2(f1.x, f1.y), bf2(f1.z, f1.w));
        *(uint4*)(Ab + row * 272 + c8 * 16) = u;
    }
    __syncthreads();

    float acc[2][8][4];
#pragma unroll
    for (int rg = 0; rg < 2; rg++)
#pragma unroll
        for (int nb = 0; nb < 8; nb++)
#pragma unroll
            for (int i = 0; i < 4; i++) acc[rg][nb][i] = 0.0f;

    {
        const uint2* Bs = (const uint2*)(smem + P_B);
#pragma unroll
        for (int K16 = 0; K16 < 8; K16++) {
            uint32_t a[2][4];
#pragma unroll
            for (int rg = 0; rg < 2; rg++) {
                const char* p = Ab + (wr * 32 + rg * 16 + g) * 272 + K16 * 32 + t * 4;
                a[rg][0] = *(const uint32_t*)p;
                a[rg][1] = *(const uint32_t*)(p + 8 * 272);
                a[rg][2] = *(const uint32_t*)(p + 16);
                a[rg][3] = *(const uint32_t*)(p + 8 * 272 + 16);
            }
#pragma unroll
            for (int nb = 0; nb < 8; nb++) {
                uint2 b = Bs[(K16 * 16 + wc * 8 + nb) * 32 + lane];
                mma_bf16(acc[0][nb], a[0], b.x, b.y);
                mma_bf16(acc[1][nb], a[1], b.x, b.y);
            }
        }
    }

#pragma unroll
    for (int rg = 0; rg < 2; rg++) {
        int r0 = wr * 32 + rg * 16 + g;
#pragma unroll
        for (int h = 0; h < 2; h++) {
            int n = n0 + r0 + 8 * h;
            if (n >= NN) continue;
#pragma unroll
            for (int nb = 0; nb < 8; nb++) {
                int col = wc * 64 + nb * 8 + 2 * t;
                float a0 = h ? acc[rg][nb][2] : acc[rg][nb][0];
                float a1 = h ? acc[rg][nb][3] : acc[rg][nb][1];
                *(float2*)(P + (size_t)n * 256 + half * 128 + col) = make_float2(a0, a1);
            }
        }
    }
}

// ===========================================================================
// Launch 5: node kernel — bf16 mma, fp32 residual (validated R7-R10)
// ===========================================================================
#define N_A0  0
#define N_A1  10240
#define N_B0  20480
#define N_B1  28672
#define N_HB  36864
#define N_BN1 71680
#define N_BN2 72192
#define N_SMEM_BYTES 72704

__global__ void __launch_bounds__(256, 2)
node_kernel(const float* __restrict__ nf, const float* __restrict__ agg,
            const float* __restrict__ bn1, const float* __restrict__ bn2,
            float* __restrict__ out) {
    extern __shared__ char smem[];
    char*  hbuf  = smem + N_HB;
    float* bn1s  = (float*)(smem + N_BN1);
    float* bn2s  = (float*)(smem + N_BN2);

    const int tid  = threadIdx.x;
    const int lane = tid & 31;
    const int wid  = tid >> 5;
    const int wr   = wid & 3;
    const int wc   = wid >> 2;
    const int g    = lane >> 2;
    const int t    = lane & 3;
    const int n0   = blockIdx.x * 128;

    if (tid < 128) { bn1s[tid] = bn1[tid]; bn2s[tid] = bn2[tid]; }

    float acc[2][8][4];
#pragma unroll
    for (int rg = 0; rg < 2; rg++)
#pragma unroll
        for (int nb = 0; nb < 8; nb++)
#pragma unroll
            for (int i = 0; i < 4; i++) acc[rg][nb][i] = 0.0f;

    {
        float4 va[4], vb[2];
        const float4* w1 = (const float4*)g_wn1b;
#pragma unroll
        for (int it = 0; it < 4; it++) {
            int seg = tid + it * 256;
            int e = seg >> 3, s8 = seg & 7;
            int n = n0 + e; if (n >= NN) n = NN - 1;
            va[it] = *(const float4*)(nf + (size_t)n * D + s8 * 4);
        }
#pragma unroll
        for (int it = 0; it < 2; it++) vb[it] = w1[tid + it * 256];
        store_A(smem + N_A0, tid, va);
        {
            float4* dst = (float4*)(smem + N_B0);
#pragma unroll
            for (int it = 0; it < 2; it++) dst[tid + it * 256] = vb[it];
        }
        __syncthreads();

        for (int c = 0; c < 8; c++) {
            const int buf = c & 1;
            if (c < 7) {
                int cn = c + 1;
#pragma unroll
                for (int it = 0; it < 4; it++) {
                    int seg = tid + it * 256;
                    int e = seg >> 3, s8 = seg & 7;
                    int n = n0 + e; if (n >= NN) n = NN - 1;
                    const float* src = (cn < 4)
                        ? nf  + (size_t)n * D  + cn * 32 + s8 * 4
                        : agg + (size_t)n * DM + (cn - 4) * 32 + s8 * 4;
                    va[it] = *(const float4*)src;
                }
#pragma unroll
                for (int it = 0; it < 2; it++)
                    vb[it] = w1[cn * 512 + tid + it * 256];
            }
            const char* Ab = smem + (buf ? N_A1 : N_A0);
            const uint2* Bs = (const uint2*)(smem + (buf ? N_B1 : N_B0));
#pragma unroll
            for (int kcl = 0; kcl < 2; kcl++) {
                uint32_t a[2][4];
#pragma unroll
                for (int rg = 0; rg < 2; rg++) {
                    const char* p = Ab + (wr * 32 + rg * 16 + g) * 80 + kcl * 32 + t * 4;
                    a[rg][0] = *(const uint32_t*)p;
                    a[rg][1] = *(const uint32_t*)(p + 8 * 80);
                    a[rg][2] = *(const uint32_t*)(p + 16);
                    a[rg][3] = *(const uint32_t*)(p + 8 * 80 + 16);
                }
#pragma unroll
                for (int nb = 0; nb < 8; nb++) {
                    uint2 b = Bs[(kcl * 16 + wc * 8 + nb) * 32 + lane];
                    mma_bf16(acc[0][nb], a[0], b.x, b.y);
                    mma_bf16(acc[1][nb], a[1], b.x, b.y);
                }
            }
            __syncthreads();
            if (c < 7) {
                store_A(smem + (((c + 1) & 1) ? N_A1 : N_A0), tid, va);
                float4* dst = (float4*)(smem + (((c + 1) & 1) ? N_B1 : N_B0));
#pragma unroll
                for (int it = 0; it < 2; it++) dst[tid + it * 256] = vb[it];
                __syncthreads();
            }
        }
    }

    {
        const float4* src = (const float4*)g_wn2b;
        float4* dst = (float4*)(smem + N_A0);
#pragma unroll
        for (int it = 0; it < 8; it++) dst[tid + it * 256] = src[tid + it * 256];
    }
#pragma unroll
    for (int rg = 0; rg < 2; rg++) {
        int row0 = wr * 32 + rg * 16 + g;
#pragma unroll
        for (int nb = 0; nb < 8; nb++) {
            int col = wc * 64 + nb * 8 + 2 * t;
            float b0 = bn1s[col], b1 = bn1s[col + 1];
            uint32_t h0 = bf2(siluf(acc[rg][nb][0] + b0), siluf(acc[rg][nb][1] + b1));
            uint32_t h1 = bf2(siluf(acc[rg][nb][2] + b0), siluf(acc[rg][nb][3] + b1));
            *(uint32_t*)(hbuf + row0 * 272 + col * 2) = h0;
            *(uint32_t*)(hbuf + (row0 + 8) * 272 + col * 2) = h1;
            acc[rg][nb][0] = 0.f; acc[rg][nb][1] = 0.f;
            acc[rg][nb][2] = 0.f; acc[rg][nb][3] = 0.f;
        }
    }
    __syncthreads();

    {
        const uint2* B2 = (const uint2*)(smem + N_A0);
#pragma unroll
        for (int K16 = 0; K16 < 8; K16++) {
            uint32_t a[2][4];
#pragma unroll
            for (int rg = 0; rg < 2; rg++) {
                const char* p = hbuf + (wr * 32 + rg * 16 + g) * 272 + K16 * 32 + t * 4;
                a[rg][0] = *(const uint32_t*)p;
                a[rg][1] = *(const uint32_t*)(p + 8 * 272);
                a[rg][2] = *(const uint32_t*)(p + 16);
                a[rg][3] = *(const uint32_t*)(p + 8 * 272 + 16);
            }
#pragma unroll
            for (int nb = 0; nb < 8; nb++) {
                uint2 b = B2[(K16 * 16 + wc * 8 + nb) * 32 + lane];
                mma_bf16(acc[0][nb], a[0], b.x, b.y);
                mma_bf16(acc[1][nb], a[1], b.x, b.y);
            }
        }
    }

#pragma unroll
    for (int rg = 0; rg < 2; rg++) {
        int r0 = wr * 32 + rg * 16 + g;
#pragma unroll
        for (int h = 0; h < 2; h++) {
            int n = n0 + r0 + 8 * h;
            if (n >= NN) continue;
#pragma unroll
            for (int nb = 0; nb < 8; nb++) {
                int col = wc * 64 + nb * 8 + 2 * t;
                float2 res = *(const float2*)(nf + (size_t)n * D + col);
                float a0 = (h ? acc[rg][nb][2] : acc[rg][nb][0]) + bn2s[col] + res.x;
                float a1 = (h ? acc[rg][nb][3] : acc[rg][nb][1]) + bn2s[col + 1] + res.y;
                *(float2*)(out + (size_t)n * D + col) = make_float2(a0, a1);
            }
        }
    }
}

// ===========================================================================
// Launch 6: idx passthrough + cleanup (zero agg/hist/cnt for NEXT call)
// ===========================================================================
__global__ void idx_cleanup_kernel(const int4* __restrict__ ei,
                                   float4* __restrict__ out) {
    int i = blockIdx.x * blockDim.x + threadIdx.x;   // grid 1563*256 = 400128
    if (i < (2 * NE) / 4) {
        int4 v = ei[i];
        out[i] = make_float4((float)v.x, (float)v.y, (float)v.z, (float)v.w);
    }
    float4 z4 = make_float4(0.f, 0.f, 0.f, 0.f);
    for (int j = i; j < NN * DM / 4; j += 400128)
        ((float4*)g_agg)[j] = z4;
    if (i < NN) { g_hist[i] = 0; g_cnt[i] = 0; }
}

// ---------------------------------------------------------------------------
extern "C" void kernel_launch(void* const* d_in, const int* in_sizes, int n_in,
                              void* d_out, int out_size) {
    const float* nf  = (const float*)d_in[0];
    const int*   ei  = (const int*)d_in[1];
    const float* ef  = (const float*)d_in[2];
    const float* We1 = (const float*)d_in[3];
    const float* be1 = (const float*)d_in[4];
    const float* We2 = (const float*)d_in[5];
    const float* be2 = (const float*)d_in[6];
    const float* Wi  = (const float*)d_in[7];
    const float* bi  = (const float*)d_in[8];
    const float* Wn1 = (const float*)d_in[9];
    const float* bn1 = (const float*)d_in[10];
    const float* Wn2 = (const float*)d_in[11];
    const float* bn2 = (const float*)d_in[12];
    float* out = (float*)d_out;

    cudaFuncSetAttribute(edge_kernel, cudaFuncAttributeMaxDynamicSharedMemorySize, E_SMEM_BYTES);
    cudaFuncSetAttribute(node_kernel, cudaFuncAttributeMaxDynamicSharedMemorySize, N_SMEM_BYTES);
    cudaFuncSetAttribute(pp_kernel, cudaFuncAttributeMaxDynamicSharedMemorySize, P_SMEM_BYTES);

    void *aggp, *pp;
    cudaGetSymbolAddress(&aggp, g_agg);
    cudaGetSymbolAddress(&pp, g_P);

    // agg/hist/cnt are zero at module load and re-zeroed by idx_cleanup_kernel
    // at the end of each call -> every call sees identical state.
    hist_pack_kernel<<<3125, 256>>>(ei, We1, We2, Wn1, Wn2);          // k1
    scan_kernel<<<1, 1024>>>();                                       // k2
    pp_kernel<<<PP_PBLK + 3125, 256, P_SMEM_BYTES>>>(ei, nf, (float*)pp); // k3
    edge_kernel<<<NE / 128, 256, E_SMEM_BYTES>>>(nf, ei, ef, (const float*)pp,
                                                 be1, be2, Wi, bi, (float*)aggp); // k4
    node_kernel<<<(NN + 127) / 128, 256, N_SMEM_BYTES>>>(nf, (const float*)aggp,
                                                         bn1, bn2, out);          // k5
    idx_cleanup_kernel<<<1563, 256>>>((const int4*)ei,
                                      (float4*)(out + (size_t)NN * D));           // k6
    cudaMemcpyAsync(out + (size_t)NN * D + 2ull * NE, d_in[2],
                    (size_t)NE * DE * sizeof(float), cudaMemcpyDeviceToDevice);
}

// round 12
// speedup vs baseline: 1.1784x; 1.1206x over previous
#include <cuda_runtime.h>
#include <cstdint>

#define NN 50000
#define NE 800000
#define D  128
#define DE 16
#define DM 128

// ---------------------------------------------------------------------------
// Global scratch (g_hist/g_cnt/g_agg zero at module load; each call re-zeros
// them at the END for the next call)
// ---------------------------------------------------------------------------
__device__ float g_agg[NN * DM];
__device__ float g_P[NN * 256];
__device__ int   g_hist[NN];
__device__ int   g_off[NN];
__device__ int   g_cnt[NN];
__device__ int   g_perm[NE];
__device__ __align__(16) uint2 g_wsb[8 * 16 * 32];    // We1 rows 0..127
__device__ __align__(16) uint2 g_web[8 * 16 * 32];    // We1 rows 128..255
__device__ __align__(16) uint2 g_wefb[2 * 16 * 32];   // We1 rows 256..271 (pad 32)
__device__ __align__(16) uint2 g_w2b[8 * 16 * 32];    // We2
__device__ __align__(16) uint2 g_wn1b[16 * 16 * 32];  // Wn1
__device__ __align__(16) uint2 g_wn2b[8 * 16 * 32];   // Wn2

// ---------------------------------------------------------------------------
// helpers
// ---------------------------------------------------------------------------
__device__ __forceinline__ float siluf(float x) { return x / (1.0f + __expf(-x)); }
__device__ __forceinline__ float sigmoidf_(float x) { return 1.0f / (1.0f + __expf(-x)); }

__device__ __forceinline__ uint32_t bf2(float lo, float hi) {
    uint32_t r;
    asm("cvt.rn.bf16x2.f32 %0, %1, %2;" : "=r"(r) : "f"(hi), "f"(lo));
    return r;
}
__device__ __forceinline__ float bflo(uint32_t u) { return __uint_as_float(u << 16); }
__device__ __forceinline__ float bfhi(uint32_t u) { return __uint_as_float(u & 0xffff0000u); }
__device__ __forceinline__ void mma_bf16(float c[4], const uint32_t a[4],
                                         uint32_t b0, uint32_t b1) {
    asm volatile("mma.sync.aligned.m16n8k16.row.col.f32.bf16.bf16.f32 "
        "{%0,%1,%2,%3}, {%4,%5,%6,%7}, {%8,%9}, {%0,%1,%2,%3};"
        : "+f"(c[0]), "+f"(c[1]), "+f"(c[2]), "+f"(c[3])
        : "r"(a[0]), "r"(a[1]), "r"(a[2]), "r"(a[3]), "r"(b0), "r"(b1));
}

__device__ __forceinline__ void store_A(char* Ab, int tid, const float4 va[4]) {
#pragma unroll
    for (int it = 0; it < 4; it++) {
        int seg = tid + it * 256;
        int e = seg >> 3, s8 = seg & 7;
        uint2 u = make_uint2(bf2(va[it].x, va[it].y), bf2(va[it].z, va[it].w));
        *(uint2*)(Ab + e * 80 + s8 * 8) = u;
    }
}

// ===========================================================================
// EDGE KERNEL — 64-edge tiles, 3 CTAs/SM, acc=32 regs/thread
// SMEM (53248 B):
//   SB  bf16 [64 x 272B] : S, then h in place        0..17408
//   WA  32768            : Aef(5120)+WEF(8192) early; W2S later
//   mtile f32 [64][132] = 33792 overlays SB+WA-front late
//   misc @ 50176
// ===========================================================================
#define E_SB     0
#define E_WA     17408
#define E_WEF    (E_WA + 5120)
#define E_MISC   50176
#define E_STARTS (E_MISC)
#define E_ENDS   (E_MISC + 256)
#define E_EIDX   (E_MISC + 512)
#define E_BE1    (E_MISC + 768)
#define E_BE2    (E_MISC + 1280)
#define E_WIS    (E_MISC + 1792)
#define E_GATES  (E_MISC + 2304)
#define E_GPART  (E_MISC + 2560)
#define E_SMEM_BYTES (E_MISC + 3072)    // 53248

__global__ void __launch_bounds__(256, 3)
edge_kernel(const float* __restrict__ nf, const int* __restrict__ ei,
            const float* __restrict__ ef, const float* __restrict__ P,
            const float* __restrict__ be1, const float* __restrict__ be2,
            const float* __restrict__ Wi, const float* __restrict__ bi,
            float* __restrict__ agg) {
    extern __shared__ char smem[];
    float* mtile  = (float*)smem;                 // [64][132] f32, late overlay
    char*  SB     = smem + E_SB;                  // 272B row stride, bf16
    char*  Aef    = smem + E_WA;                  // 80B row stride, early
    int*   starts = (int*)(smem + E_STARTS);
    int*   ends   = (int*)(smem + E_ENDS);
    int*   eidx   = (int*)(smem + E_EIDX);
    float* be1s   = (float*)(smem + E_BE1);
    float* be2s   = (float*)(smem + E_BE2);
    float* wis    = (float*)(smem + E_WIS);
    float* gates  = (float*)(smem + E_GATES);
    float* gpart  = (float*)(smem + E_GPART);

    const int tid  = threadIdx.x;
    const int lane = tid & 31;
    const int wid  = tid >> 5;
    const int wr   = wid & 3;        // row group: rows wr*16 .. +15
    const int wc   = wid >> 2;       // col half: cols wc*64 .. +63
    const int g    = lane >> 2;
    const int t    = lane & 3;
    const int e0   = blockIdx.x * 64;
    const float bi0 = __ldg(bi);

    if (tid < 64) {
        int e = g_perm[e0 + tid];
        eidx[tid]   = e;
        starts[tid] = ei[e];
        ends[tid]   = ei[NE + e];
    }
    if (tid < 128) {
        be1s[tid] = be1[tid];
        be2s[tid] = be2[tid];
        wis[tid]  = Wi[tid];
    }
    __syncthreads();

    // ---- phase A: stage WEF + Aef; P gather-add -> SB (bf16) ----
    {
        const float4* wf = (const float4*)g_wefb;
        float4* df = (float4*)(smem + E_WEF);
#pragma unroll
        for (int it = 0; it < 2; it++) df[tid + it * 256] = wf[tid + it * 256];
    }
#pragma unroll
    for (int it = 0; it < 2; it++) {
        int seg = tid + it * 256;              // 0..511
        int e = seg >> 3, s8 = seg & 7;
        float4 v = (s8 < 4) ? *(const float4*)(ef + (size_t)eidx[e] * DE + s8 * 4)
                            : make_float4(0.f, 0.f, 0.f, 0.f);
        uint2 u = make_uint2(bf2(v.x, v.y), bf2(v.z, v.w));
        *(uint2*)(Aef + e * 80 + s8 * 8) = u;
    }
#pragma unroll
    for (int it = 0; it < 8; it++) {
        int seg = tid + it * 256;              // 0..2047
        int row = seg >> 5, c4 = (seg & 31) * 4;
        int s = starts[row], e_ = ends[row];
        float4 a = *(const float4*)(P + (size_t)s * 256 + c4);
        float4 b = *(const float4*)(P + (size_t)e_ * 256 + 128 + c4);
        uint2 u = make_uint2(bf2(a.x + b.x, a.y + b.y),
                             bf2(a.z + b.z, a.w + b.w));
        *(uint2*)(SB + row * 272 + c4 * 2) = u;
    }
    __syncthreads();

    float acc[8][4];
#pragma unroll
    for (int nb = 0; nb < 8; nb++)
#pragma unroll
        for (int i = 0; i < 4; i++) acc[nb][i] = 0.0f;

    // ---- ef MMA (K=32) ----
    {
        const uint2* Bs = (const uint2*)(smem + E_WEF);
#pragma unroll
        for (int kcl = 0; kcl < 2; kcl++) {
            uint32_t a[4];
            const char* p = Aef + (wr * 16 + g) * 80 + kcl * 32 + t * 4;
            a[0] = *(const uint32_t*)p;
            a[1] = *(const uint32_t*)(p + 8 * 80);
            a[2] = *(const uint32_t*)(p + 16);
            a[3] = *(const uint32_t*)(p + 8 * 80 + 16);
#pragma unroll
            for (int nb = 0; nb < 8; nb++) {
                uint2 b = Bs[(kcl * 16 + wc * 8 + nb) * 32 + lane];
                mma_bf16(acc[nb], a, b.x, b.y);
            }
        }
    }
    __syncthreads();   // Aef/WEF dead

    // ---- Epilogue 1: h = silu(acc + S + be1), IN PLACE over SB ----
    {
        const int r0 = wr * 16 + g;
#pragma unroll
        for (int nb = 0; nb < 8; nb++) {
            int col = wc * 64 + nb * 8 + 2 * t;
            uint32_t s0 = *(const uint32_t*)(SB + r0 * 272 + col * 2);
            uint32_t s1 = *(const uint32_t*)(SB + (r0 + 8) * 272 + col * 2);
            float b0 = be1s[col], b1 = be1s[col + 1];
            uint32_t h0 = bf2(siluf(acc[nb][0] + bflo(s0) + b0),
                              siluf(acc[nb][1] + bfhi(s0) + b1));
            uint32_t h1 = bf2(siluf(acc[nb][2] + bflo(s1) + b0),
                              siluf(acc[nb][3] + bfhi(s1) + b1));
            *(uint32_t*)(SB + r0 * 272 + col * 2) = h0;
            *(uint32_t*)(SB + (r0 + 8) * 272 + col * 2) = h1;
            acc[nb][0] = 0.f; acc[nb][1] = 0.f;
            acc[nb][2] = 0.f; acc[nb][3] = 0.f;
        }
    }
    __syncthreads();

    // ---- stage W2 (32KB) into WA ----
    {
        const float4* w2 = (const float4*)g_w2b;
        float4* d2 = (float4*)(smem + E_WA);
#pragma unroll
        for (int it = 0; it < 8; it++) d2[tid + it * 256] = w2[tid + it * 256];
    }
    __syncthreads();

    // ---- GEMM2: D2 = h @ We2 (K=128) ----
    {
        const uint2* B2 = (const uint2*)(smem + E_WA);
#pragma unroll
        for (int K16 = 0; K16 < 8; K16++) {
            uint32_t a[4];
            const char* p = SB + (wr * 16 + g) * 272 + K16 * 32 + t * 4;
            a[0] = *(const uint32_t*)p;
            a[1] = *(const uint32_t*)(p + 8 * 272);
            a[2] = *(const uint32_t*)(p + 16);
            a[3] = *(const uint32_t*)(p + 8 * 272 + 16);
#pragma unroll
            for (int nb = 0; nb < 8; nb++) {
                uint2 b = B2[(K16 * 16 + wc * 8 + nb) * 32 + lane];
                mma_bf16(acc[nb], a, b.x, b.y);
            }
        }
    }
    __syncthreads();   // SB (h) + W2S dead before mtile overwrite

    // ---- Epilogue 2: m = D2 + be2 -> mtile; gate partials from regs ----
    {
        const int r0 = wr * 16 + g;
        float p0 = 0.f, p1 = 0.f;
#pragma unroll
        for (int nb = 0; nb < 8; nb++) {
            int col = wc * 64 + nb * 8 + 2 * t;
            float b0 = be2s[col], b1 = be2s[col + 1];
            float m0x = acc[nb][0] + b0, m0y = acc[nb][1] + b1;
            float m1x = acc[nb][2] + b0, m1y = acc[nb][3] + b1;
            *(float2*)(mtile + r0 * 132 + col) = make_float2(m0x, m0y);
            *(float2*)(mtile + (r0 + 8) * 132 + col) = make_float2(m1x, m1y);
            float w0 = wis[col], w1 = wis[col + 1];
            p0 += m0x * w0 + m0y * w1;
            p1 += m1x * w0 + m1y * w1;
        }
        // reduce over quad (t = 0..3)
        p0 += __shfl_xor_sync(0xffffffffu, p0, 1);
        p0 += __shfl_xor_sync(0xffffffffu, p0, 2);
        p1 += __shfl_xor_sync(0xffffffffu, p1, 1);
        p1 += __shfl_xor_sync(0xffffffffu, p1, 2);
        if (t == 0) {
            gpart[r0 * 2 + wc] = p0;
            gpart[(r0 + 8) * 2 + wc] = p1;
        }
    }
    __syncthreads();
    if (tid < 64)
        gates[tid] = sigmoidf_(gpart[2 * tid] + gpart[2 * tid + 1] + bi0);
    __syncthreads();

    // ---- segmented gated scatter (rows sorted by start) ----
    {
        const int c  = tid & 127;
        const int r0 = (tid >> 7) * 32;
        float accv = 0.0f;
        int sprev = starts[r0];
        for (int r = r0; r < r0 + 32; r++) {
            int s = starts[r];
            if (s != sprev) {
                atomicAdd(agg + (size_t)sprev * DM + c, accv);
                accv = 0.0f;
                sprev = s;
            }
            accv += mtile[r * 132 + c] * gates[r];
        }
        atomicAdd(agg + (size_t)sprev * DM + c, accv);
    }
}

// ===========================================================================
// Launch 1: hist + weight pack
// ===========================================================================
__device__ __forceinline__ uint2 pack_frag2(const float* W, int idx, int row0, int rowlim) {
    int lane = idx & 31;
    int nbk = idx >> 5;
    int k0 = (nbk >> 4) * 16;
    int n = (nbk & 15) * 8 + (lane >> 2);
    int t2 = (lane & 3) * 2;
    int r = row0 + k0 + t2;
    float v00 = (r     < rowlim) ? W[(size_t)r * 128 + n] : 0.0f;
    float v01 = (r + 1 < rowlim) ? W[(size_t)(r + 1) * 128 + n] : 0.0f;
    float v10 = (r + 8 < rowlim) ? W[(size_t)(r + 8) * 128 + n] : 0.0f;
    float v11 = (r + 9 < rowlim) ? W[(size_t)(r + 9) * 128 + n] : 0.0f;
    return make_uint2(bf2(v00, v01), bf2(v10, v11));
}

__global__ void hist_pack_kernel(const int* __restrict__ ei,
                                 const float* __restrict__ We1, const float* __restrict__ We2,
                                 const float* __restrict__ Wn1, const float* __restrict__ Wn2) {
    int i = blockIdx.x * 256 + threadIdx.x;
    if (i < 4096)        g_wsb[i] = pack_frag2(We1, i, 0, 272);
    else if (i < 8192)   g_web[i - 4096] = pack_frag2(We1, i - 4096, 128, 272);
    else if (i < 9216)   g_wefb[i - 8192] = pack_frag2(We1, i - 8192, 256, 272);
    else if (i < 13312)  g_w2b[i - 9216] = pack_frag2(We2, i - 9216, 0, 128);
    else if (i < 21504)  g_wn1b[i - 13312] = pack_frag2(Wn1, i - 13312, 0, 256);
    else if (i < 25600)  g_wn2b[i - 21504] = pack_frag2(Wn2, i - 21504, 0, 128);
    if (i < NE) atomicAdd(&g_hist[ei[i]], 1);
}

// ===========================================================================
// Launch 2: scan
// ===========================================================================
__global__ void scan_kernel() {
    const int CH = 49;
    __shared__ int ws[32];
    int t = threadIdx.x;
    int base = t * CH;
    int sum = 0;
#pragma unroll 7
    for (int i = 0; i < CH; i++) {
        int idx = base + i;
        if (idx < NN) sum += g_hist[idx];
    }
    int lane = t & 31, wid = t >> 5;
    int v = sum;
#pragma unroll
    for (int o = 1; o < 32; o <<= 1) {
        int u = __shfl_up_sync(0xffffffffu, v, o);
        if (lane >= o) v += u;
    }
    if (lane == 31) ws[wid] = v;
    __syncthreads();
    if (wid == 0) {
        int w = ws[lane];
#pragma unroll
        for (int o = 1; o < 32; o <<= 1) {
            int u = __shfl_up_sync(0xffffffffu, w, o);
            if (lane >= o) w += u;
        }
        ws[lane] = w;
    }
    __syncthreads();
    int pre = v - sum + (wid > 0 ? ws[wid - 1] : 0);
    int run = pre;
    for (int i = 0; i < CH; i++) {
        int idx = base + i;
        if (idx < NN) {
            int h = g_hist[idx];
            g_off[idx] = run;
            run += h;
        }
    }
}

// ===========================================================================
// Launch 3: fused permute + P GEMM
// ===========================================================================
#define PP_PBLK 782
#define P_A 0
#define P_B 34816
#define P_SMEM_BYTES 67584

__global__ void __launch_bounds__(256, 2)
pp_kernel(const int* __restrict__ ei, const float* __restrict__ nf,
          float* __restrict__ P) {
    extern __shared__ char smem[];
    const int tid = threadIdx.x;

    if (blockIdx.x >= PP_PBLK) {
        int e = (blockIdx.x - PP_PBLK) * 256 + tid;
        if (e < NE) {
            int s = ei[e];
            int pos = g_off[s] + atomicAdd(&g_cnt[s], 1);
            g_perm[pos] = e;
        }
        return;
    }

    char* Ab = smem + P_A;
    const int lane = tid & 31;
    const int wid  = tid >> 5;
    const int wr   = wid & 3;
    const int wc   = wid >> 2;
    const int g    = lane >> 2;
    const int t    = lane & 3;
    const int n0   = (blockIdx.x % 391) * 128;
    const int half = blockIdx.x / 391;

    {
        const float4* src = (const float4*)(half ? g_web : g_wsb);
        float4* dst = (float4*)(smem + P_B);
#pragma unroll
        for (int it = 0; it < 8; it++) dst[tid + it * 256] = src[tid + it * 256];
    }
#pragma unroll
    for (int it = 0; it < 8; it++) {
        int seg = tid + it * 256;
        int row = seg >> 4, c8 = seg & 15;
        int n = n0 + row; if (n >= NN) n = NN - 1;
        float4 f0 = *(const float4*)(nf + (size_t)n * D + c8 * 8);
        float4 f1 = *(const float4*)(nf + (size_t)n * D + c8 * 8 + 4);
        uint4 u = make_uint4(bf2(f0.x, f0.y), bf2(f0.z, f0.w),
                             bf2(f1.x, f1.y), bf2(f1.z, f1.w));
        *(uint4*)(Ab + row * 272 + c8 * 16) = u;
    }
    __syncthreads();

    float acc[2][8][4];
#pragma unroll
    for (int rg = 0; rg < 2; rg++)
#pragma unroll
        for (int nb = 0; nb < 8; nb++)
#pragma unroll
            for (int i = 0; i < 4; i++) acc[rg][nb][i] = 0.0f;

    {
        const uint2* Bs = (const uint2*)(smem + P_B);
#pragma unroll
        for (int K16 = 0; K16 < 8; K16++) {
            uint32_t a[2][4];
#pragma unroll
            for (int rg = 0; rg < 2; rg++) {
                const char* p = Ab + (wr * 32 + rg * 16 + g) * 272 + K16 * 32 + t * 4;
                a[rg][0] = *(const uint32_t*)p;
                a[rg][1] = *(const uint32_t*)(p + 8 * 272);
                a[rg][2] = *(const uint32_t*)(p + 16);
                a[rg][3] = *(const uint32_t*)(p + 8 * 272 + 16);
            }
#pragma unroll
            for (int nb = 0; nb < 8; nb++) {
                uint2 b = Bs[(K16 * 16 + wc * 8 + nb) * 32 + lane];
                mma_bf16(acc[0][nb], a[0], b.x, b.y);
                mma_bf16(acc[1][nb], a[1], b.x, b.y);
            }
        }
    }

#pragma unroll
    for (int rg = 0; rg < 2; rg++) {
        int r0 = wr * 32 + rg * 16 + g;
#pragma unroll
        for (int h = 0; h < 2; h++) {
            int n = n0 + r0 + 8 * h;
            if (n >= NN) continue;
#pragma unroll
            for (int nb = 0; nb < 8; nb++) {
                int col = wc * 64 + nb * 8 + 2 * t;
                float a0 = h ? acc[rg][nb][2] : acc[rg][nb][0];
                float a1 = h ? acc[rg][nb][3] : acc[rg][nb][1];
                *(float2*)(P + (size_t)n * 256 + half * 128 + col) = make_float2(a0, a1);
            }
        }
    }
}

// ===========================================================================
// Launch 5: node kernel — bf16 mma, fp32 residual (validated R7-R11)
// ===========================================================================
#define N_A0  0
#define N_A1  10240
#define N_B0  20480
#define N_B1  28672
#define N_HB  36864
#define N_BN1 71680
#define N_BN2 72192
#define N_SMEM_BYTES 72704

__global__ void __launch_bounds__(256, 2)
node_kernel(const float* __restrict__ nf, const float* __restrict__ agg,
            const float* __restrict__ bn1, const float* __restrict__ bn2,
            float* __restrict__ out) {
    extern __shared__ char smem[];
    char*  hbuf  = smem + N_HB;
    float* bn1s  = (float*)(smem + N_BN1);
    float* bn2s  = (float*)(smem + N_BN2);

    const int tid  = threadIdx.x;
    const int lane = tid & 31;
    const int wid  = tid >> 5;
    const int wr   = wid & 3;
    const int wc   = wid >> 2;
    const int g    = lane >> 2;
    const int t    = lane & 3;
    const int n0   = blockIdx.x * 128;

    if (tid < 128) { bn1s[tid] = bn1[tid]; bn2s[tid] = bn2[tid]; }

    float acc[2][8][4];
#pragma unroll
    for (int rg = 0; rg < 2; rg++)
#pragma unroll
        for (int nb = 0; nb < 8; nb++)
#pragma unroll
            for (int i = 0; i < 4; i++) acc[rg][nb][i] = 0.0f;

    {
        float4 va[4], vb[2];
        const float4* w1 = (const float4*)g_wn1b;
#pragma unroll
        for (int it = 0; it < 4; it++) {
            int seg = tid + it * 256;
            int e = seg >> 3, s8 = seg & 7;
            int n = n0 + e; if (n >= NN) n = NN - 1;
            va[it] = *(const float4*)(nf + (size_t)n * D + s8 * 4);
        }
#pragma unroll
        for (int it = 0; it < 2; it++) vb[it] = w1[tid + it * 256];
        store_A(smem + N_A0, tid, va);
        {
            float4* dst = (float4*)(smem + N_B0);
#pragma unroll
            for (int it = 0; it < 2; it++) dst[tid + it * 256] = vb[it];
        }
        __syncthreads();

        for (int c = 0; c < 8; c++) {
            const int buf = c & 1;
            if (c < 7) {
                int cn = c + 1;
#pragma unroll
                for (int it = 0; it < 4; it++) {
                    int seg = tid + it * 256;
                    int e = seg >> 3, s8 = seg & 7;
                    int n = n0 + e; if (n >= NN) n = NN - 1;
                    const float* src = (cn < 4)
                        ? nf  + (size_t)n * D  + cn * 32 + s8 * 4
                        : agg + (size_t)n * DM + (cn - 4) * 32 + s8 * 4;
                    va[it] = *(const float4*)src;
                }
#pragma unroll
                for (int it = 0; it < 2; it++)
                    vb[it] = w1[cn * 512 + tid + it * 256];
            }
            const char* Ab = smem + (buf ? N_A1 : N_A0);
            const uint2* Bs = (const uint2*)(smem + (buf ? N_B1 : N_B0));
#pragma unroll
            for (int kcl = 0; kcl < 2; kcl++) {
                uint32_t a[2][4];
#pragma unroll
                for (int rg = 0; rg < 2; rg++) {
                    const char* p = Ab + (wr * 32 + rg * 16 + g) * 80 + kcl * 32 + t * 4;
                    a[rg][0] = *(const uint32_t*)p;
                    a[rg][1] = *(const uint32_t*)(p + 8 * 80);
                    a[rg][2] = *(const uint32_t*)(p + 16);
                    a[rg][3] = *(const uint32_t*)(p + 8 * 80 + 16);
                }
#pragma unroll
                for (int nb = 0; nb < 8; nb++) {
                    uint2 b = Bs[(kcl * 16 + wc * 8 + nb) * 32 + lane];
                    mma_bf16(acc[0][nb], a[0], b.x, b.y);
                    mma_bf16(acc[1][nb], a[1], b.x, b.y);
                }
            }
            __syncthreads();
            if (c < 7) {
                store_A(smem + (((c + 1) & 1) ? N_A1 : N_A0), tid, va);
                float4* dst = (float4*)(smem + (((c + 1) & 1) ? N_B1 : N_B0));
#pragma unroll
                for (int it = 0; it < 2; it++) dst[tid + it * 256] = vb[it];
                __syncthreads();
            }
        }
    }

    {
        const float4* src = (const float4*)g_wn2b;
        float4* dst = (float4*)(smem + N_A0);
#pragma unroll
        for (int it = 0; it < 8; it++) dst[tid + it * 256] = src[tid + it * 256];
    }
#pragma unroll
    for (int rg = 0; rg < 2; rg++) {
        int row0 = wr * 32 + rg * 16 + g;
#pragma unroll
        for (int nb = 0; nb < 8; nb++) {
            int col = wc * 64 + nb * 8 + 2 * t;
            float b0 = bn1s[col], b1 = bn1s[col + 1];
            uint32_t h0 = bf2(siluf(acc[rg][nb][0] + b0), siluf(acc[rg][nb][1] + b1));
            uint32_t h1 = bf2(siluf(acc[rg][nb][2] + b0), siluf(acc[rg][nb][3] + b1));
            *(uint32_t*)(hbuf + row0 * 272 + col * 2) = h0;
            *(uint32_t*)(hbuf + (row0 + 8) * 272 + col * 2) = h1;
            acc[rg][nb][0] = 0.f; acc[rg][nb][1] = 0.f;
            acc[rg][nb][2] = 0.f; acc[rg][nb][3] = 0.f;
        }
    }
    __syncthreads();

    {
        const uint2* B2 = (const uint2*)(smem + N_A0);
#pragma unroll
        for (int K16 = 0; K16 < 8; K16++) {
            uint32_t a[2][4];
#pragma unroll
            for (int rg = 0; rg < 2; rg++) {
                const char* p = hbuf + (wr * 32 + rg * 16 + g) * 272 + K16 * 32 + t * 4;
                a[rg][0] = *(const uint32_t*)p;
                a[rg][1] = *(const uint32_t*)(p + 8 * 272);
                a[rg][2] = *(const uint32_t*)(p + 16);
                a[rg][3] = *(const uint32_t*)(p + 8 * 272 + 16);
            }
#pragma unroll
            for (int nb = 0; nb < 8; nb++) {
                uint2 b = B2[(K16 * 16 + wc * 8 + nb) * 32 + lane];
                mma_bf16(acc[0][nb], a[0], b.x, b.y);
                mma_bf16(acc[1][nb], a[1], b.x, b.y);
            }
        }
    }

#pragma unroll
    for (int rg = 0; rg < 2; rg++) {
        int r0 = wr * 32 + rg * 16 + g;
#pragma unroll
        for (int h = 0; h < 2; h++) {
            int n = n0 + r0 + 8 * h;
            if (n >= NN) continue;
#pragma unroll
            for (int nb = 0; nb < 8; nb++) {
                int col = wc * 64 + nb * 8 + 2 * t;
                float2 res = *(const float2*)(nf + (size_t)n * D + col);
                float a0 = (h ? acc[rg][nb][2] : acc[rg][nb][0]) + bn2s[col] + res.x;
                float a1 = (h ? acc[rg][nb][3] : acc[rg][nb][1]) + bn2s[col + 1] + res.y;
                *(float2*)(out + (size_t)n * D + col) = make_float2(a0, a1);
            }
        }
    }
}

// ===========================================================================
// Launch 6: idx passthrough + cleanup for next call
// ===========================================================================
__global__ void idx_cleanup_kernel(const int4* __restrict__ ei,
                                   float4* __restrict__ out) {
    int i = blockIdx.x * blockDim.x + threadIdx.x;
    if (i < (2 * NE) / 4) {
        int4 v = ei[i];
        out[i] = make_float4((float)v.x, (float)v.y, (float)v.z, (float)v.w);
    }
    float4 z4 = make_float4(0.f, 0.f, 0.f, 0.f);
    for (int j = i; j < NN * DM / 4; j += 400128)
        ((float4*)g_agg)[j] = z4;
    if (i < NN) { g_hist[i] = 0; g_cnt[i] = 0; }
}

// ---------------------------------------------------------------------------
extern "C" void kernel_launch(void* const* d_in, const int* in_sizes, int n_in,
                              void* d_out, int out_size) {
    const float* nf  = (const float*)d_in[0];
    const int*   ei  = (const int*)d_in[1];
    const float* ef  = (const float*)d_in[2];
    const float* We1 = (const float*)d_in[3];
    const float* be1 = (const float*)d_in[4];
    const float* We2 = (const float*)d_in[5];
    const float* be2 = (const float*)d_in[6];
    const float* Wi  = (const float*)d_in[7];
    const float* bi  = (const float*)d_in[8];
    const float* Wn1 = (const float*)d_in[9];
    const float* bn1 = (const float*)d_in[10];
    const float* Wn2 = (const float*)d_in[11];
    const float* bn2 = (const float*)d_in[12];
    float* out = (float*)d_out;

    cudaFuncSetAttribute(edge_kernel, cudaFuncAttributeMaxDynamicSharedMemorySize, E_SMEM_BYTES);
    cudaFuncSetAttribute(node_kernel, cudaFuncAttributeMaxDynamicSharedMemorySize, N_SMEM_BYTES);
    cudaFuncSetAttribute(pp_kernel, cudaFuncAttributeMaxDynamicSharedMemorySize, P_SMEM_BYTES);

    void *aggp, *pp;
    cudaGetSymbolAddress(&aggp, g_agg);
    cudaGetSymbolAddress(&pp, g_P);

    hist_pack_kernel<<<3125, 256>>>(ei, We1, We2, Wn1, Wn2);              // k1
    scan_kernel<<<1, 1024>>>();                                           // k2
    pp_kernel<<<PP_PBLK + 3125, 256, P_SMEM_BYTES>>>(ei, nf, (float*)pp); // k3
    edge_kernel<<<NE / 64, 256, E_SMEM_BYTES>>>(nf, ei, ef, (const float*)pp,
                                                be1, be2, Wi, bi, (float*)aggp); // k4
    node_kernel<<<(NN + 127) / 128, 256, N_SMEM_BYTES>>>(nf, (const float*)aggp,
                                                         bn1, bn2, out);          // k5
    idx_cleanup_kernel<<<1563, 256>>>((const int4*)ei,
                                      (float4*)(out + (size_t)NN * D));           // k6
    cudaMemcpyAsync(out + (size_t)NN * D + 2ull * NE, d_in[2],
                    (size_t)NE * DE * sizeof(float), cudaMemcpyDeviceToDevice);
}

// round 13
// speedup vs baseline: 1.3303x; 1.1289x over previous
#include <cuda_runtime.h>
#include <cstdint>

#define NN 50000
#define NE 800000
#define D  128
#define DE 16
#define DM 128

// ---------------------------------------------------------------------------
// Global scratch (g_hist/g_cnt/g_agg zero at module load; each call re-zeros
// them at the END for the next call)
// ---------------------------------------------------------------------------
__device__ float g_agg[NN * DM];
__device__ float g_P[NN * 256];
__device__ int   g_hist[NN];
__device__ int   g_off[NN];
__device__ int   g_cnt[NN];
__device__ int   g_perm[NE];
__device__ __align__(16) uint2 g_wsb[8 * 16 * 32];    // We1 rows 0..127
__device__ __align__(16) uint2 g_web[8 * 16 * 32];    // We1 rows 128..255
__device__ __align__(16) uint2 g_wefb[2 * 16 * 32];   // We1 rows 256..271 (pad 32)
__device__ __align__(16) uint2 g_w2b[8 * 16 * 32];    // We2
__device__ __align__(16) uint2 g_wn1b[16 * 16 * 32];  // Wn1
__device__ __align__(16) uint2 g_wn2b[8 * 16 * 32];   // Wn2

// ---------------------------------------------------------------------------
// helpers
// ---------------------------------------------------------------------------
__device__ __forceinline__ float siluf(float x) { return x / (1.0f + __expf(-x)); }
__device__ __forceinline__ float sigmoidf_(float x) { return 1.0f / (1.0f + __expf(-x)); }

__device__ __forceinline__ uint32_t bf2(float lo, float hi) {
    uint32_t r;
    asm("cvt.rn.bf16x2.f32 %0, %1, %2;" : "=r"(r) : "f"(hi), "f"(lo));
    return r;
}
__device__ __forceinline__ float bflo(uint32_t u) { return __uint_as_float(u << 16); }
__device__ __forceinline__ float bfhi(uint32_t u) { return __uint_as_float(u & 0xffff0000u); }
__device__ __forceinline__ void mma_bf16(float c[4], const uint32_t a[4],
                                         uint32_t b0, uint32_t b1) {
    asm volatile("mma.sync.aligned.m16n8k16.row.col.f32.bf16.bf16.f32 "
        "{%0,%1,%2,%3}, {%4,%5,%6,%7}, {%8,%9}, {%0,%1,%2,%3};"
        : "+f"(c[0]), "+f"(c[1]), "+f"(c[2]), "+f"(c[3])
        : "r"(a[0]), "r"(a[1]), "r"(a[2]), "r"(a[3]), "r"(b0), "r"(b1));
}

__device__ __forceinline__ void store_A(char* Ab, int tid, const float4 va[4]) {
#pragma unroll
    for (int it = 0; it < 4; it++) {
        int seg = tid + it * 256;
        int e = seg >> 3, s8 = seg & 7;
        uint2 u = make_uint2(bf2(va[it].x, va[it].y), bf2(va[it].z, va[it].w));
        *(uint2*)(Ab + e * 80 + s8 * 8) = u;
    }
}

// ===========================================================================
// EDGE KERNEL — 64-edge tiles, 4 CTAs/SM target, acc=32 regs/thread
// SMEM (53248 B):
//   SB  bf16 [64 x 272B] : S, then h in place        0..17408
//   WA  32768            : Aef(5120)+WEF(8192) early; W2S later
//   mtile f32 [64][132] = 33792 overlays SB+WA-front late
//   misc @ 50176
// ===========================================================================
#define E_SB     0
#define E_WA     17408
#define E_WEF    (E_WA + 5120)
#define E_MISC   50176
#define E_STARTS (E_MISC)
#define E_ENDS   (E_MISC + 256)
#define E_EIDX   (E_MISC + 512)
#define E_BE1    (E_MISC + 768)
#define E_BE2    (E_MISC + 1280)
#define E_WIS    (E_MISC + 1792)
#define E_GATES  (E_MISC + 2304)
#define E_GPART  (E_MISC + 2560)
#define E_SMEM_BYTES (E_MISC + 3072)    // 53248

__global__ void __launch_bounds__(256, 4)
edge_kernel(const float* __restrict__ nf, const int* __restrict__ ei,
            const float* __restrict__ ef, const float* __restrict__ P,
            const float* __restrict__ be1, const float* __restrict__ be2,
            const float* __restrict__ Wi, const float* __restrict__ bi,
            float* __restrict__ agg) {
    extern __shared__ char smem[];
    float* mtile  = (float*)smem;                 // [64][132] f32, late overlay
    char*  SB     = smem + E_SB;                  // 272B row stride, bf16
    char*  Aef    = smem + E_WA;                  // 80B row stride, early
    int*   starts = (int*)(smem + E_STARTS);
    int*   ends   = (int*)(smem + E_ENDS);
    int*   eidx   = (int*)(smem + E_EIDX);
    float* be1s   = (float*)(smem + E_BE1);
    float* be2s   = (float*)(smem + E_BE2);
    float* wis    = (float*)(smem + E_WIS);
    float* gates  = (float*)(smem + E_GATES);
    float* gpart  = (float*)(smem + E_GPART);

    const int tid  = threadIdx.x;
    const int lane = tid & 31;
    const int wid  = tid >> 5;
    const int wr   = wid & 3;        // row group: rows wr*16 .. +15
    const int wc   = wid >> 2;       // col half: cols wc*64 .. +63
    const int g    = lane >> 2;
    const int t    = lane & 3;
    const int e0   = blockIdx.x * 64;
    const float bi0 = __ldg(bi);

    if (tid < 64) {
        int e = g_perm[e0 + tid];
        eidx[tid]   = e;
        starts[tid] = ei[e];
        ends[tid]   = ei[NE + e];
    }
    if (tid < 128) {
        be1s[tid] = be1[tid];
        be2s[tid] = be2[tid];
        wis[tid]  = Wi[tid];
    }
    __syncthreads();

    // ---- phase A: stage WEF (one K16 block) + Aef; P gather-add -> SB ----
    {
        const float4* wf = (const float4*)g_wefb;
        float4* df = (float4*)(smem + E_WEF);
        if (tid < 256) df[tid] = wf[tid];      // 4096B = K16 block 0 only
    }
#pragma unroll
    for (int it = 0; it < 2; it++) {
        int seg = tid + it * 256;              // 0..511
        int e = seg >> 3, s8 = seg & 7;
        float4 v = (s8 < 4) ? *(const float4*)(ef + (size_t)eidx[e] * DE + s8 * 4)
                            : make_float4(0.f, 0.f, 0.f, 0.f);
        uint2 u = make_uint2(bf2(v.x, v.y), bf2(v.z, v.w));
        *(uint2*)(Aef + e * 80 + s8 * 8) = u;
    }
#pragma unroll
    for (int it = 0; it < 8; it++) {
        int seg = tid + it * 256;              // 0..2047
        int row = seg >> 5, c4 = (seg & 31) * 4;
        int s = starts[row], e_ = ends[row];
        float4 a = *(const float4*)(P + (size_t)s * 256 + c4);
        float4 b = *(const float4*)(P + (size_t)e_ * 256 + 128 + c4);
        uint2 u = make_uint2(bf2(a.x + b.x, a.y + b.y),
                             bf2(a.z + b.z, a.w + b.w));
        *(uint2*)(SB + row * 272 + c4 * 2) = u;
    }
    __syncthreads();

    float acc[8][4];
#pragma unroll
    for (int nb = 0; nb < 8; nb++)
#pragma unroll
        for (int i = 0; i < 4; i++) acc[nb][i] = 0.0f;

    // ---- ef MMA (K=16: single K16 block; rows 272..287 of We1 are zero) ----
    {
        const uint2* Bs = (const uint2*)(smem + E_WEF);
        uint32_t a[4];
        const char* p = Aef + (wr * 16 + g) * 80 + t * 4;
        a[0] = *(const uint32_t*)p;
        a[1] = *(const uint32_t*)(p + 8 * 80);
        a[2] = *(const uint32_t*)(p + 16);
        a[3] = *(const uint32_t*)(p + 8 * 80 + 16);
#pragma unroll
        for (int nb = 0; nb < 8; nb++) {
            uint2 b = Bs[(wc * 8 + nb) * 32 + lane];
            mma_bf16(acc[nb], a, b.x, b.y);
        }
    }
    __syncthreads();   // Aef/WEF dead

    // ---- Epilogue 1: h = silu(acc + S + be1), IN PLACE over SB ----
    {
        const int r0 = wr * 16 + g;
#pragma unroll
        for (int nb = 0; nb < 8; nb++) {
            int col = wc * 64 + nb * 8 + 2 * t;
            uint32_t s0 = *(const uint32_t*)(SB + r0 * 272 + col * 2);
            uint32_t s1 = *(const uint32_t*)(SB + (r0 + 8) * 272 + col * 2);
            float b0 = be1s[col], b1 = be1s[col + 1];
            uint32_t h0 = bf2(siluf(acc[nb][0] + bflo(s0) + b0),
                              siluf(acc[nb][1] + bfhi(s0) + b1));
            uint32_t h1 = bf2(siluf(acc[nb][2] + bflo(s1) + b0),
                              siluf(acc[nb][3] + bfhi(s1) + b1));
            *(uint32_t*)(SB + r0 * 272 + col * 2) = h0;
            *(uint32_t*)(SB + (r0 + 8) * 272 + col * 2) = h1;
            acc[nb][0] = 0.f; acc[nb][1] = 0.f;
            acc[nb][2] = 0.f; acc[nb][3] = 0.f;
        }
    }
    __syncthreads();

    // ---- stage W2 (32KB) into WA ----
    {
        const float4* w2 = (const float4*)g_w2b;
        float4* d2 = (float4*)(smem + E_WA);
#pragma unroll
        for (int it = 0; it < 8; it++) d2[tid + it * 256] = w2[tid + it * 256];
    }
    __syncthreads();

    // ---- GEMM2: D2 = h @ We2 (K=128) ----
    {
        const uint2* B2 = (const uint2*)(smem + E_WA);
#pragma unroll
        for (int K16 = 0; K16 < 8; K16++) {
            uint32_t a[4];
            const char* p = SB + (wr * 16 + g) * 272 + K16 * 32 + t * 4;
            a[0] = *(const uint32_t*)p;
            a[1] = *(const uint32_t*)(p + 8 * 272);
            a[2] = *(const uint32_t*)(p + 16);
            a[3] = *(const uint32_t*)(p + 8 * 272 + 16);
#pragma unroll
            for (int nb = 0; nb < 8; nb++) {
                uint2 b = B2[(K16 * 16 + wc * 8 + nb) * 32 + lane];
                mma_bf16(acc[nb], a, b.x, b.y);
            }
        }
    }
    __syncthreads();   // SB (h) + W2S dead before mtile overwrite

    // ---- Epilogue 2: m = D2 + be2 -> mtile; gate partials from regs ----
    {
        const int r0 = wr * 16 + g;
        float p0 = 0.f, p1 = 0.f;
#pragma unroll
        for (int nb = 0; nb < 8; nb++) {
            int col = wc * 64 + nb * 8 + 2 * t;
            float b0 = be2s[col], b1 = be2s[col + 1];
            float m0x = acc[nb][0] + b0, m0y = acc[nb][1] + b1;
            float m1x = acc[nb][2] + b0, m1y = acc[nb][3] + b1;
            *(float2*)(mtile + r0 * 132 + col) = make_float2(m0x, m0y);
            *(float2*)(mtile + (r0 + 8) * 132 + col) = make_float2(m1x, m1y);
            float w0 = wis[col], w1 = wis[col + 1];
            p0 += m0x * w0 + m0y * w1;
            p1 += m1x * w0 + m1y * w1;
        }
        p0 += __shfl_xor_sync(0xffffffffu, p0, 1);
        p0 += __shfl_xor_sync(0xffffffffu, p0, 2);
        p1 += __shfl_xor_sync(0xffffffffu, p1, 1);
        p1 += __shfl_xor_sync(0xffffffffu, p1, 2);
        if (t == 0) {
            gpart[r0 * 2 + wc] = p0;
            gpart[(r0 + 8) * 2 + wc] = p1;
        }
    }
    __syncthreads();
    if (tid < 64)
        gates[tid] = sigmoidf_(gpart[2 * tid] + gpart[2 * tid + 1] + bi0);
    __syncthreads();

    // ---- segmented gated scatter (rows sorted by start) ----
    {
        const int c  = tid & 127;
        const int r0 = (tid >> 7) * 32;
        float accv = 0.0f;
        int sprev = starts[r0];
        for (int r = r0; r < r0 + 32; r++) {
            int s = starts[r];
            if (s != sprev) {
                atomicAdd(agg + (size_t)sprev * DM + c, accv);
                accv = 0.0f;
                sprev = s;
            }
            accv += mtile[r * 132 + c] * gates[r];
        }
        atomicAdd(agg + (size_t)sprev * DM + c, accv);
    }
}

// ===========================================================================
// Launch 1: hist + weight pack
// ===========================================================================
__device__ __forceinline__ uint2 pack_frag2(const float* W, int idx, int row0, int rowlim) {
    int lane = idx & 31;
    int nbk = idx >> 5;
    int k0 = (nbk >> 4) * 16;
    int n = (nbk & 15) * 8 + (lane >> 2);
    int t2 = (lane & 3) * 2;
    int r = row0 + k0 + t2;
    float v00 = (r     < rowlim) ? W[(size_t)r * 128 + n] : 0.0f;
    float v01 = (r + 1 < rowlim) ? W[(size_t)(r + 1) * 128 + n] : 0.0f;
    float v10 = (r + 8 < rowlim) ? W[(size_t)(r + 8) * 128 + n] : 0.0f;
    float v11 = (r + 9 < rowlim) ? W[(size_t)(r + 9) * 128 + n] : 0.0f;
    return make_uint2(bf2(v00, v01), bf2(v10, v11));
}

__global__ void hist_pack_kernel(const int* __restrict__ ei,
                                 const float* __restrict__ We1, const float* __restrict__ We2,
                                 const float* __restrict__ Wn1, const float* __restrict__ Wn2) {
    int i = blockIdx.x * 256 + threadIdx.x;
    if (i < 4096)        g_wsb[i] = pack_frag2(We1, i, 0, 272);
    else if (i < 8192)   g_web[i - 4096] = pack_frag2(We1, i - 4096, 128, 272);
    else if (i < 9216)   g_wefb[i - 8192] = pack_frag2(We1, i - 8192, 256, 272);
    else if (i < 13312)  g_w2b[i - 9216] = pack_frag2(We2, i - 9216, 0, 128);
    else if (i < 21504)  g_wn1b[i - 13312] = pack_frag2(Wn1, i - 13312, 0, 256);
    else if (i < 25600)  g_wn2b[i - 21504] = pack_frag2(Wn2, i - 21504, 0, 128);
    if (i < NE) atomicAdd(&g_hist[ei[i]], 1);
}

// ===========================================================================
// Launch 2: scan
// ===========================================================================
__global__ void scan_kernel() {
    const int CH = 49;
    __shared__ int ws[32];
    int t = threadIdx.x;
    int base = t * CH;
    int sum = 0;
#pragma unroll 7
    for (int i = 0; i < CH; i++) {
        int idx = base + i;
        if (idx < NN) sum += g_hist[idx];
    }
    int lane = t & 31, wid = t >> 5;
    int v = sum;
#pragma unroll
    for (int o = 1; o < 32; o <<= 1) {
        int u = __shfl_up_sync(0xffffffffu, v, o);
        if (lane >= o) v += u;
    }
    if (lane == 31) ws[wid] = v;
    __syncthreads();
    if (wid == 0) {
        int w = ws[lane];
#pragma unroll
        for (int o = 1; o < 32; o <<= 1) {
            int u = __shfl_up_sync(0xffffffffu, w, o);
            if (lane >= o) w += u;
        }
        ws[lane] = w;
    }
    __syncthreads();
    int pre = v - sum + (wid > 0 ? ws[wid - 1] : 0);
    int run = pre;
    for (int i = 0; i < CH; i++) {
        int idx = base + i;
        if (idx < NN) {
            int h = g_hist[idx];
            g_off[idx] = run;
            run += h;
        }
    }
}

// ===========================================================================
// Launch 3: fused permute + P GEMM
// ===========================================================================
#define PP_PBLK 782
#define P_A 0
#define P_B 34816
#define P_SMEM_BYTES 67584

__global__ void __launch_bounds__(256, 2)
pp_kernel(const int* __restrict__ ei, const float* __restrict__ nf,
          float* __restrict__ P) {
    extern __shared__ char smem[];
    const int tid = threadIdx.x;

    if (blockIdx.x >= PP_PBLK) {
        int e = (blockIdx.x - PP_PBLK) * 256 + tid;
        if (e < NE) {
            int s = ei[e];
            int pos = g_off[s] + atomicAdd(&g_cnt[s], 1);
            g_perm[pos] = e;
        }
        return;
    }

    char* Ab = smem + P_A;
    const int lane = tid & 31;
    const int wid  = tid >> 5;
    const int wr   = wid & 3;
    const int wc   = wid >> 2;
    const int g    = lane >> 2;
    const int t    = lane & 3;
    const int n0   = (blockIdx.x % 391) * 128;
    const int half = blockIdx.x / 391;

    {
        const float4* src = (const float4*)(half ? g_web : g_wsb);
        float4* dst = (float4*)(smem + P_B);
#pragma unroll
        for (int it = 0; it < 8; it++) dst[tid + it * 256] = src[tid + it * 256];
    }
#pragma unroll
    for (int it = 0; it < 8; it++) {
        int seg = tid + it * 256;
        int row = seg >> 4, c8 = seg & 15;
        int n = n0 + row; if (n >= NN) n = NN - 1;
        float4 f0 = *(const float4*)(nf + (size_t)n * D + c8 * 8);
        float4 f1 = *(const float4*)(nf + (size_t)n * D + c8 * 8 + 4);
        uint4 u = make_uint4(bf2(f0.x, f0.y), bf2(f0.z, f0.w),
                             bf2(f1.x, f1.y), bf2(f1.z, f1.w));
        *(uint4*)(Ab + row * 272 + c8 * 16) = u;
    }
    __syncthreads();

    float acc[2][8][4];
#pragma unroll
    for (int rg = 0; rg < 2; rg++)
#pragma unroll
        for (int nb = 0; nb < 8; nb++)
#pragma unroll
            for (int i = 0; i < 4; i++) acc[rg][nb][i] = 0.0f;

    {
        const uint2* Bs = (const uint2*)(smem + P_B);
#pragma unroll
        for (int K16 = 0; K16 < 8; K16++) {
            uint32_t a[2][4];
#pragma unroll
            for (int rg = 0; rg < 2; rg++) {
                const char* p = Ab + (wr * 32 + rg * 16 + g) * 272 + K16 * 32 + t * 4;
                a[rg][0] = *(const uint32_t*)p;
                a[rg][1] = *(const uint32_t*)(p + 8 * 272);
                a[rg][2] = *(const uint32_t*)(p + 16);
                a[rg][3] = *(const uint32_t*)(p + 8 * 272 + 16);
            }
#pragma unroll
            for (int nb = 0; nb < 8; nb++) {
                uint2 b = Bs[(K16 * 16 + wc * 8 + nb) * 32 + lane];
                mma_bf16(acc[0][nb], a[0], b.x, b.y);
                mma_bf16(acc[1][nb], a[1], b.x, b.y);
            }
        }
    }

#pragma unroll
    for (int rg = 0; rg < 2; rg++) {
        int r0 = wr * 32 + rg * 16 + g;
#pragma unroll
        for (int h = 0; h < 2; h++) {
            int n = n0 + r0 + 8 * h;
            if (n >= NN) continue;
#pragma unroll
            for (int nb = 0; nb < 8; nb++) {
                int col = wc * 64 + nb * 8 + 2 * t;
                float a0 = h ? acc[rg][nb][2] : acc[rg][nb][0];
                float a1 = h ? acc[rg][nb][3] : acc[rg][nb][1];
                *(float2*)(P + (size_t)n * 256 + half * 128 + col) = make_float2(a0, a1);
            }
        }
    }
}

// ===========================================================================
// Launch 5: node kernel — bf16 mma, fp32 residual (validated R7-R12)
// ===========================================================================
#define N_A0  0
#define N_A1  10240
#define N_B0  20480
#define N_B1  28672
#define N_HB  36864
#define N_BN1 71680
#define N_BN2 72192
#define N_SMEM_BYTES 72704

__global__ void __launch_bounds__(256, 2)
node_kernel(const float* __restrict__ nf, const float* __restrict__ agg,
            const float* __restrict__ bn1, const float* __restrict__ bn2,
            float* __restrict__ out) {
    extern __shared__ char smem[];
    char*  hbuf  = smem + N_HB;
    float* bn1s  = (float*)(smem + N_BN1);
    float* bn2s  = (float*)(smem + N_BN2);

    const int tid  = threadIdx.x;
    const int lane = tid & 31;
    const int wid  = tid >> 5;
    const int wr   = wid & 3;
    const int wc   = wid >> 2;
    const int g    = lane >> 2;
    const int t    = lane & 3;
    const int n0   = blockIdx.x * 128;

    if (tid < 128) { bn1s[tid] = bn1[tid]; bn2s[tid] = bn2[tid]; }

    float acc[2][8][4];
#pragma unroll
    for (int rg = 0; rg < 2; rg++)
#pragma unroll
        for (int nb = 0; nb < 8; nb++)
#pragma unroll
            for (int i = 0; i < 4; i++) acc[rg][nb][i] = 0.0f;

    {
        float4 va[4], vb[2];
        const float4* w1 = (const float4*)g_wn1b;
#pragma unroll
        for (int it = 0; it < 4; it++) {
            int seg = tid + it * 256;
            int e = seg >> 3, s8 = seg & 7;
            int n = n0 + e; if (n >= NN) n = NN - 1;
            va[it] = *(const float4*)(nf + (size_t)n * D + s8 * 4);
        }
#pragma unroll
        for (int it = 0; it < 2; it++) vb[it] = w1[tid + it * 256];
        store_A(smem + N_A0, tid, va);
        {
            float4* dst = (float4*)(smem + N_B0);
#pragma unroll
            for (int it = 0; it < 2; it++) dst[tid + it * 256] = vb[it];
        }
        __syncthreads();

        for (int c = 0; c < 8; c++) {
            const int buf = c & 1;
            if (c < 7) {
                int cn = c + 1;
#pragma unroll
                for (int it = 0; it < 4; it++) {
                    int seg = tid + it * 256;
                    int e = seg >> 3, s8 = seg & 7;
                    int n = n0 + e; if (n >= NN) n = NN - 1;
                    const float* src = (cn < 4)
                        ? nf  + (size_t)n * D  + cn * 32 + s8 * 4
                        : agg + (size_t)n * DM + (cn - 4) * 32 + s8 * 4;
                    va[it] = *(const float4*)src;
                }
#pragma unroll
                for (int it = 0; it < 2; it++)
                    vb[it] = w1[cn * 512 + tid + it * 256];
            }
            const char* Ab = smem + (buf ? N_A1 : N_A0);
            const uint2* Bs = (const uint2*)(smem + (buf ? N_B1 : N_B0));
#pragma unroll
            for (int kcl = 0; kcl < 2; kcl++) {
                uint32_t a[2][4];
#pragma unroll
                for (int rg = 0; rg < 2; rg++) {
                    const char* p = Ab + (wr * 32 + rg * 16 + g) * 80 + kcl * 32 + t * 4;
                    a[rg][0] = *(const uint32_t*)p;
                    a[rg][1] = *(const uint32_t*)(p + 8 * 80);
                    a[rg][2] = *(const uint32_t*)(p + 16);
                    a[rg][3] = *(const uint32_t*)(p + 8 * 80 + 16);
                }
#pragma unroll
                for (int nb = 0; nb < 8; nb++) {
                    uint2 b = Bs[(kcl * 16 + wc * 8 + nb) * 32 + lane];
                    mma_bf16(acc[0][nb], a[0], b.x, b.y);
                    mma_bf16(acc[1][nb], a[1], b.x, b.y);
                }
            }
            __syncthreads();
            if (c < 7) {
                store_A(smem + (((c + 1) & 1) ? N_A1 : N_A0), tid, va);
                float4* dst = (float4*)(smem + (((c + 1) & 1) ? N_B1 : N_B0));
#pragma unroll
                for (int it = 0; it < 2; it++) dst[tid + it * 256] = vb[it];
                __syncthreads();
            }
        }
    }

    {
        const float4* src = (const float4*)g_wn2b;
        float4* dst = (float4*)(smem + N_A0);
#pragma unroll
        for (int it = 0; it < 8; it++) dst[tid + it * 256] = src[tid + it * 256];
    }
#pragma unroll
    for (int rg = 0; rg < 2; rg++) {
        int row0 = wr * 32 + rg * 16 + g;
#pragma unroll
        for (int nb = 0; nb < 8; nb++) {
            int col = wc * 64 + nb * 8 + 2 * t;
            float b0 = bn1s[col], b1 = bn1s[col + 1];
            uint32_t h0 = bf2(siluf(acc[rg][nb][0] + b0), siluf(acc[rg][nb][1] + b1));
            uint32_t h1 = bf2(siluf(acc[rg][nb][2] + b0), siluf(acc[rg][nb][3] + b1));
            *(uint32_t*)(hbuf + row0 * 272 + col * 2) = h0;
            *(uint32_t*)(hbuf + (row0 + 8) * 272 + col * 2) = h1;
            acc[rg][nb][0] = 0.f; acc[rg][nb][1] = 0.f;
            acc[rg][nb][2] = 0.f; acc[rg][nb][3] = 0.f;
        }
    }
    __syncthreads();

    {
        const uint2* B2 = (const uint2*)(smem + N_A0);
#pragma unroll
        for (int K16 = 0; K16 < 8; K16++) {
            uint32_t a[2][4];
#pragma unroll
            for (int rg = 0; rg < 2; rg++) {
                const char* p = hbuf + (wr * 32 + rg * 16 + g) * 272 + K16 * 32 + t * 4;
                a[rg][0] = *(const uint32_t*)p;
                a[rg][1] = *(const uint32_t*)(p + 8 * 272);
                a[rg][2] = *(const uint32_t*)(p + 16);
                a[rg][3] = *(const uint32_t*)(p + 8 * 272 + 16);
            }
#pragma unroll
            for (int nb = 0; nb < 8; nb++) {
                uint2 b = B2[(K16 * 16 + wc * 8 + nb) * 32 + lane];
                mma_bf16(acc[0][nb], a[0], b.x, b.y);
                mma_bf16(acc[1][nb], a[1], b.x, b.y);
            }
        }
    }

#pragma unroll
    for (int rg = 0; rg < 2; rg++) {
        int r0 = wr * 32 + rg * 16 + g;
#pragma unroll
        for (int h = 0; h < 2; h++) {
            int n = n0 + r0 + 8 * h;
            if (n >= NN) continue;
#pragma unroll
            for (int nb = 0; nb < 8; nb++) {
                int col = wc * 64 + nb * 8 + 2 * t;
                float2 res = *(const float2*)(nf + (size_t)n * D + col);
                float a0 = (h ? acc[rg][nb][2] : acc[rg][nb][0]) + bn2s[col] + res.x;
                float a1 = (h ? acc[rg][nb][3] : acc[rg][nb][1]) + bn2s[col + 1] + res.y;
                *(float2*)(out + (size_t)n * D + col) = make_float2(a0, a1);
            }
        }
    }
}

// ===========================================================================
// Launch 6: idx passthrough + cleanup for next call
// ===========================================================================
__global__ void idx_cleanup_kernel(const int4* __restrict__ ei,
                                   float4* __restrict__ out) {
    int i = blockIdx.x * blockDim.x + threadIdx.x;
    if (i < (2 * NE) / 4) {
        int4 v = ei[i];
        out[i] = make_float4((float)v.x, (float)v.y, (float)v.z, (float)v.w);
    }
    float4 z4 = make_float4(0.f, 0.f, 0.f, 0.f);
    for (int j = i; j < NN * DM / 4; j += 400128)
        ((float4*)g_agg)[j] = z4;
    if (i < NN) { g_hist[i] = 0; g_cnt[i] = 0; }
}

// ---------------------------------------------------------------------------
extern "C" void kernel_launch(void* const* d_in, const int* in_sizes, int n_in,
                              void* d_out, int out_size) {
    const float* nf  = (const float*)d_in[0];
    const int*   ei  = (const int*)d_in[1];
    const float* ef  = (const float*)d_in[2];
    const float* We1 = (const float*)d_in[3];
    const float* be1 = (const float*)d_in[4];
    const float* We2 = (const float*)d_in[5];
    const float* be2 = (const float*)d_in[6];
    const float* Wi  = (const float*)d_in[7];
    const float* bi  = (const float*)d_in[8];
    const float* Wn1 = (const float*)d_in[9];
    const float* bn1 = (const float*)d_in[10];
    const float* Wn2 = (const float*)d_in[11];
    const float* bn2 = (const float*)d_in[12];
    float* out = (float*)d_out;

    cudaFuncSetAttribute(edge_kernel, cudaFuncAttributeMaxDynamicSharedMemorySize, E_SMEM_BYTES);
    cudaFuncSetAttribute(node_kernel, cudaFuncAttributeMaxDynamicSharedMemorySize, N_SMEM_BYTES);
    cudaFuncSetAttribute(pp_kernel, cudaFuncAttributeMaxDynamicSharedMemorySize, P_SMEM_BYTES);

    void *aggp, *pp;
    cudaGetSymbolAddress(&aggp, g_agg);
    cudaGetSymbolAddress(&pp, g_P);

    hist_pack_kernel<<<3125, 256>>>(ei, We1, We2, Wn1, Wn2);              // k1
    scan_kernel<<<1, 1024>>>();                                           // k2
    pp_kernel<<<PP_PBLK + 3125, 256, P_SMEM_BYTES>>>(ei, nf, (float*)pp); // k3
    edge_kernel<<<NE / 64, 256, E_SMEM_BYTES>>>(nf, ei, ef, (const float*)pp,
                                                be1, be2, Wi, bi, (float*)aggp); // k4
    node_kernel<<<(NN + 127) / 128, 256, N_SMEM_BYTES>>>(nf, (const float*)aggp,
                                                         bn1, bn2, out);          // k5
    idx_cleanup_kernel<<<1563, 256>>>((const int4*)ei,
                                      (float4*)(out + (size_t)NN * D));           // k6
    cudaMemcpyAsync(out + (size_t)NN * D + 2ull * NE, d_in[2],
                    (size_t)NE * DE * sizeof(float), cudaMemcpyDeviceToDevice);
}

// round 14
// speedup vs baseline: 1.3400x; 1.0073x over previous
#include <cuda_runtime.h>
#include <cstdint>

#define NN 50000
#define NE 800000
#define D  128
#define DE 16
#define DM 128

// ---------------------------------------------------------------------------
// Global scratch (g_hist/g_cnt/g_agg zero at module load; each call re-zeros
// them at the END for the next call)
// ---------------------------------------------------------------------------
__device__ float g_agg[NN * DM];
__device__ float g_P[NN * 256];
__device__ int   g_hist[NN];
__device__ int   g_off[NN];
__device__ int   g_cnt[NN];
__device__ int   g_perm[NE];
__device__ __align__(16) uint2 g_wsb[8 * 16 * 32];    // We1 rows 0..127
__device__ __align__(16) uint2 g_web[8 * 16 * 32];    // We1 rows 128..255
__device__ __align__(16) uint2 g_wefb[2 * 16 * 32];   // We1 rows 256..271 (pad 32)
__device__ __align__(16) uint2 g_w2b[8 * 16 * 32];    // We2
__device__ __align__(16) uint2 g_wn1b[16 * 16 * 32];  // Wn1
__device__ __align__(16) uint2 g_wn2b[8 * 16 * 32];   // Wn2

// ---------------------------------------------------------------------------
// helpers
// ---------------------------------------------------------------------------
__device__ __forceinline__ float siluf(float x) { return x / (1.0f + __expf(-x)); }
__device__ __forceinline__ float sigmoidf_(float x) { return 1.0f / (1.0f + __expf(-x)); }

__device__ __forceinline__ uint32_t bf2(float lo, float hi) {
    uint32_t r;
    asm("cvt.rn.bf16x2.f32 %0, %1, %2;" : "=r"(r) : "f"(hi), "f"(lo));
    return r;
}
__device__ __forceinline__ float bflo(uint32_t u) { return __uint_as_float(u << 16); }
__device__ __forceinline__ float bfhi(uint32_t u) { return __uint_as_float(u & 0xffff0000u); }
__device__ __forceinline__ void mma_bf16(float c[4], const uint32_t a[4],
                                         uint32_t b0, uint32_t b1) {
    asm volatile("mma.sync.aligned.m16n8k16.row.col.f32.bf16.bf16.f32 "
        "{%0,%1,%2,%3}, {%4,%5,%6,%7}, {%8,%9}, {%0,%1,%2,%3};"
        : "+f"(c[0]), "+f"(c[1]), "+f"(c[2]), "+f"(c[3])
        : "r"(a[0]), "r"(a[1]), "r"(a[2]), "r"(a[3]), "r"(b0), "r"(b1));
}
// ldmatrix x4: A fragment (16 rows x 16 bf16) for m16n8k16
__device__ __forceinline__ void ldsm_x4(uint32_t a[4], uint32_t saddr) {
    asm volatile("ldmatrix.sync.aligned.m8n8.x4.shared.b16 {%0,%1,%2,%3}, [%4];"
        : "=r"(a[0]), "=r"(a[1]), "=r"(a[2]), "=r"(a[3]) : "r"(saddr));
}
__device__ __forceinline__ uint32_t smem_u32(const void* p) {
    return (uint32_t)__cvta_generic_to_shared(p);
}

__device__ __forceinline__ void store_A(char* Ab, int tid, const float4 va[4]) {
#pragma unroll
    for (int it = 0; it < 4; it++) {
        int seg = tid + it * 256;
        int e = seg >> 3, s8 = seg & 7;
        uint2 u = make_uint2(bf2(va[it].x, va[it].y), bf2(va[it].z, va[it].w));
        *(uint2*)(Ab + e * 80 + s8 * 8) = u;
    }
}

// ===========================================================================
// EDGE KERNEL — 64-edge tiles, 4 CTAs/SM, warp = 32 rows x 32 cols
// SMEM (53760 B):
//   SB  bf16 [64 x 272B] : S, then h in place        0..17408
//   WA  32768            : Aef(5120)+WEF(8192) early; W2S later
//   mtile f32 [64][132] = 33792 overlays SB+WA-front late
//   misc @ 50176 (3584)
// ===========================================================================
#define E_SB     0
#define E_WA     17408
#define E_WEF    (E_WA + 5120)
#define E_MISC   50176
#define E_STARTS (E_MISC)
#define E_ENDS   (E_MISC + 256)
#define E_EIDX   (E_MISC + 512)
#define E_BE1    (E_MISC + 768)
#define E_BE2    (E_MISC + 1280)
#define E_WIS    (E_MISC + 1792)
#define E_GATES  (E_MISC + 2304)
#define E_GPART  (E_MISC + 2560)          // 64 rows x 4 quarters = 1024B
#define E_SMEM_BYTES (E_MISC + 3584)      // 53760

__global__ void __launch_bounds__(256, 4)
edge_kernel(const float* __restrict__ nf, const int* __restrict__ ei,
            const float* __restrict__ ef, const float* __restrict__ P,
            const float* __restrict__ be1, const float* __restrict__ be2,
            const float* __restrict__ Wi, const float* __restrict__ bi,
            float* __restrict__ agg) {
    extern __shared__ char smem[];
    float* mtile  = (float*)smem;                 // [64][132] f32, late overlay
    char*  SB     = smem + E_SB;                  // 272B row stride, bf16
    char*  Aef    = smem + E_WA;                  // 80B row stride, early
    int*   starts = (int*)(smem + E_STARTS);
    int*   ends   = (int*)(smem + E_ENDS);
    int*   eidx   = (int*)(smem + E_EIDX);
    float* be1s   = (float*)(smem + E_BE1);
    float* be2s   = (float*)(smem + E_BE2);
    float* wis    = (float*)(smem + E_WIS);
    float* gates  = (float*)(smem + E_GATES);
    float* gpart  = (float*)(smem + E_GPART);

    const int tid  = threadIdx.x;
    const int lane = tid & 31;
    const int wid  = tid >> 5;
    const int wr   = wid & 1;        // row half: rows wr*32 .. +31
    const int wc   = wid >> 1;       // col quarter: cols wc*32 .. +31
    const int g    = lane >> 2;
    const int t    = lane & 3;
    const int e0   = blockIdx.x * 64;
    const float bi0 = __ldg(bi);
    // ldmatrix per-lane row/offset selector
    const int lm_row = lane & 15;
    const int lm_off = (lane >> 4) << 4;

    if (tid < 64) {
        int e = g_perm[e0 + tid];
        eidx[tid]   = e;
        starts[tid] = ei[e];
        ends[tid]   = ei[NE + e];
    }
    if (tid < 128) {
        be1s[tid] = be1[tid];
        be2s[tid] = be2[tid];
        wis[tid]  = Wi[tid];
    }
    __syncthreads();

    // ---- phase A: stage WEF (one K16 block) + Aef; P gather-add -> SB ----
    {
        const float4* wf = (const float4*)g_wefb;
        float4* df = (float4*)(smem + E_WEF);
        if (tid < 256) df[tid] = wf[tid];      // 4096B = K16 block 0 only
    }
#pragma unroll
    for (int it = 0; it < 2; it++) {
        int seg = tid + it * 256;              // 0..511
        int e = seg >> 3, s8 = seg & 7;
        float4 v = (s8 < 4) ? *(const float4*)(ef + (size_t)eidx[e] * DE + s8 * 4)
                            : make_float4(0.f, 0.f, 0.f, 0.f);
        uint2 u = make_uint2(bf2(v.x, v.y), bf2(v.z, v.w));
        *(uint2*)(Aef + e * 80 + s8 * 8) = u;
    }
#pragma unroll
    for (int it = 0; it < 8; it++) {
        int seg = tid + it * 256;              // 0..2047
        int row = seg >> 5, c4 = (seg & 31) * 4;
        int s = starts[row], e_ = ends[row];
        float4 a = *(const float4*)(P + (size_t)s * 256 + c4);
        float4 b = *(const float4*)(P + (size_t)e_ * 256 + 128 + c4);
        uint2 u = make_uint2(bf2(a.x + b.x, a.y + b.y),
                             bf2(a.z + b.z, a.w + b.w));
        *(uint2*)(SB + row * 272 + c4 * 2) = u;
    }
    __syncthreads();

    float acc[2][4][4];
#pragma unroll
    for (int rg = 0; rg < 2; rg++)
#pragma unroll
        for (int nb = 0; nb < 4; nb++)
#pragma unroll
            for (int i = 0; i < 4; i++) acc[rg][nb][i] = 0.0f;

    // ---- ef MMA (K=16, rows 272..287 of We1 are zero) ----
    {
        const uint2* Bs = (const uint2*)(smem + E_WEF);
        uint32_t a[2][4];
#pragma unroll
        for (int rg = 0; rg < 2; rg++) {
            uint32_t sa = smem_u32(Aef + (wr * 32 + rg * 16 + lm_row) * 80 + lm_off);
            ldsm_x4(a[rg], sa);
        }
#pragma unroll
        for (int nb = 0; nb < 4; nb++) {
            uint2 b = Bs[(wc * 4 + nb) * 32 + lane];
            mma_bf16(acc[0][nb], a[0], b.x, b.y);
            mma_bf16(acc[1][nb], a[1], b.x, b.y);
        }
    }
    __syncthreads();   // Aef/WEF dead

    // ---- Epilogue 1: h = silu(acc + S + be1), IN PLACE over SB ----
#pragma unroll
    for (int rg = 0; rg < 2; rg++) {
        const int r0 = wr * 32 + rg * 16 + g;
#pragma unroll
        for (int nb = 0; nb < 4; nb++) {
            int col = wc * 32 + nb * 8 + 2 * t;
            uint32_t s0 = *(const uint32_t*)(SB + r0 * 272 + col * 2);
            uint32_t s1 = *(const uint32_t*)(SB + (r0 + 8) * 272 + col * 2);
            float b0 = be1s[col], b1 = be1s[col + 1];
            uint32_t h0 = bf2(siluf(acc[rg][nb][0] + bflo(s0) + b0),
                              siluf(acc[rg][nb][1] + bfhi(s0) + b1));
            uint32_t h1 = bf2(siluf(acc[rg][nb][2] + bflo(s1) + b0),
                              siluf(acc[rg][nb][3] + bfhi(s1) + b1));
            *(uint32_t*)(SB + r0 * 272 + col * 2) = h0;
            *(uint32_t*)(SB + (r0 + 8) * 272 + col * 2) = h1;
            acc[rg][nb][0] = 0.f; acc[rg][nb][1] = 0.f;
            acc[rg][nb][2] = 0.f; acc[rg][nb][3] = 0.f;
        }
    }
    __syncthreads();

    // ---- stage W2 (32KB) into WA ----
    {
        const float4* w2 = (const float4*)g_w2b;
        float4* d2 = (float4*)(smem + E_WA);
#pragma unroll
        for (int it = 0; it < 8; it++) d2[tid + it * 256] = w2[tid + it * 256];
    }
    __syncthreads();

    // ---- GEMM2: D2 = h @ We2 (K=128, ldmatrix A, 4-nb B) ----
    {
        const uint2* B2 = (const uint2*)(smem + E_WA);
#pragma unroll
        for (int K16 = 0; K16 < 8; K16++) {
            uint32_t a[2][4];
#pragma unroll
            for (int rg = 0; rg < 2; rg++) {
                uint32_t sa = smem_u32(SB + (wr * 32 + rg * 16 + lm_row) * 272
                                       + K16 * 32 + lm_off);
                ldsm_x4(a[rg], sa);
            }
#pragma unroll
            for (int nb = 0; nb < 4; nb++) {
                uint2 b = B2[(K16 * 16 + wc * 4 + nb) * 32 + lane];
                mma_bf16(acc[0][nb], a[0], b.x, b.y);
                mma_bf16(acc[1][nb], a[1], b.x, b.y);
            }
        }
    }
    __syncthreads();   // SB (h) + W2S dead before mtile overwrite

    // ---- Epilogue 2: m = D2 + be2 -> mtile; gate partials from regs ----
#pragma unroll
    for (int rg = 0; rg < 2; rg++) {
        const int r0 = wr * 32 + rg * 16 + g;
        float p0 = 0.f, p1 = 0.f;
#pragma unroll
        for (int nb = 0; nb < 4; nb++) {
            int col = wc * 32 + nb * 8 + 2 * t;
            float b0 = be2s[col], b1 = be2s[col + 1];
            float m0x = acc[rg][nb][0] + b0, m0y = acc[rg][nb][1] + b1;
            float m1x = acc[rg][nb][2] + b0, m1y = acc[rg][nb][3] + b1;
            *(float2*)(mtile + r0 * 132 + col) = make_float2(m0x, m0y);
            *(float2*)(mtile + (r0 + 8) * 132 + col) = make_float2(m1x, m1y);
            float w0 = wis[col], w1 = wis[col + 1];
            p0 += m0x * w0 + m0y * w1;
            p1 += m1x * w0 + m1y * w1;
        }
        p0 += __shfl_xor_sync(0xffffffffu, p0, 1);
        p0 += __shfl_xor_sync(0xffffffffu, p0, 2);
        p1 += __shfl_xor_sync(0xffffffffu, p1, 1);
        p1 += __shfl_xor_sync(0xffffffffu, p1, 2);
        if (t == 0) {
            gpart[r0 * 4 + wc] = p0;
            gpart[(r0 + 8) * 4 + wc] = p1;
        }
    }
    __syncthreads();
    if (tid < 64)
        gates[tid] = sigmoidf_(gpart[4 * tid] + gpart[4 * tid + 1]
                               + gpart[4 * tid + 2] + gpart[4 * tid + 3] + bi0);
    __syncthreads();

    // ---- segmented gated scatter (rows sorted by start) ----
    {
        const int c  = tid & 127;
        const int r0 = (tid >> 7) * 32;
        float accv = 0.0f;
        int sprev = starts[r0];
        for (int r = r0; r < r0 + 32; r++) {
            int s = starts[r];
            if (s != sprev) {
                atomicAdd(agg + (size_t)sprev * DM + c, accv);
                accv = 0.0f;
                sprev = s;
            }
            accv += mtile[r * 132 + c] * gates[r];
        }
        atomicAdd(agg + (size_t)sprev * DM + c, accv);
    }
}

// ===========================================================================
// Launch 1: hist + weight pack
// ===========================================================================
__device__ __forceinline__ uint2 pack_frag2(const float* W, int idx, int row0, int rowlim) {
    int lane = idx & 31;
    int nbk = idx >> 5;
    int k0 = (nbk >> 4) * 16;
    int n = (nbk & 15) * 8 + (lane >> 2);
    int t2 = (lane & 3) * 2;
    int r = row0 + k0 + t2;
    float v00 = (r     < rowlim) ? W[(size_t)r * 128 + n] : 0.0f;
    float v01 = (r + 1 < rowlim) ? W[(size_t)(r + 1) * 128 + n] : 0.0f;
    float v10 = (r + 8 < rowlim) ? W[(size_t)(r + 8) * 128 + n] : 0.0f;
    float v11 = (r + 9 < rowlim) ? W[(size_t)(r + 9) * 128 + n] : 0.0f;
    return make_uint2(bf2(v00, v01), bf2(v10, v11));
}

__global__ void hist_pack_kernel(const int* __restrict__ ei,
                                 const float* __restrict__ We1, const float* __restrict__ We2,
                                 const float* __restrict__ Wn1, const float* __restrict__ Wn2) {
    int i = blockIdx.x * 256 + threadIdx.x;
    if (i < 4096)        g_wsb[i] = pack_frag2(We1, i, 0, 272);
    else if (i < 8192)   g_web[i - 4096] = pack_frag2(We1, i - 4096, 128, 272);
    else if (i < 9216)   g_wefb[i - 8192] = pack_frag2(We1, i - 8192, 256, 272);
    else if (i < 13312)  g_w2b[i - 9216] = pack_frag2(We2, i - 9216, 0, 128);
    else if (i < 21504)  g_wn1b[i - 13312] = pack_frag2(Wn1, i - 13312, 0, 256);
    else if (i < 25600)  g_wn2b[i - 21504] = pack_frag2(Wn2, i - 21504, 0, 128);
    if (i < NE) atomicAdd(&g_hist[ei[i]], 1);
}

// ===========================================================================
// Launch 2: scan
// ===========================================================================
__global__ void scan_kernel() {
    const int CH = 49;
    __shared__ int ws[32];
    int t = threadIdx.x;
    int base = t * CH;
    int sum = 0;
#pragma unroll 7
    for (int i = 0; i < CH; i++) {
        int idx = base + i;
        if (idx < NN) sum += g_hist[idx];
    }
    int lane = t & 31, wid = t >> 5;
    int v = sum;
#pragma unroll
    for (int o = 1; o < 32; o <<= 1) {
        int u = __shfl_up_sync(0xffffffffu, v, o);
        if (lane >= o) v += u;
    }
    if (lane == 31) ws[wid] = v;
    __syncthreads();
    if (wid == 0) {
        int w = ws[lane];
#pragma unroll
        for (int o = 1; o < 32; o <<= 1) {
            int u = __shfl_up_sync(0xffffffffu, w, o);
            if (lane >= o) w += u;
        }
        ws[lane] = w;
    }
    __syncthreads();
    int pre = v - sum + (wid > 0 ? ws[wid - 1] : 0);
    int run = pre;
    for (int i = 0; i < CH; i++) {
        int idx = base + i;
        if (idx < NN) {
            int h = g_hist[idx];
            g_off[idx] = run;
            run += h;
        }
    }
}

// ===========================================================================
// Launch 3: fused permute + P GEMM
// ===========================================================================
#define PP_PBLK 782
#define P_A 0
#define P_B 34816
#define P_SMEM_BYTES 67584

__global__ void __launch_bounds__(256, 2)
pp_kernel(const int* __restrict__ ei, const float* __restrict__ nf,
          float* __restrict__ P) {
    extern __shared__ char smem[];
    const int tid = threadIdx.x;

    if (blockIdx.x >= PP_PBLK) {
        int e = (blockIdx.x - PP_PBLK) * 256 + tid;
        if (e < NE) {
            int s = ei[e];
            int pos = g_off[s] + atomicAdd(&g_cnt[s], 1);
            g_perm[pos] = e;
        }
        return;
    }

    char* Ab = smem + P_A;
    const int lane = tid & 31;
    const int wid  = tid >> 5;
    const int wr   = wid & 3;
    const int wc   = wid >> 2;
    const int g    = lane >> 2;
    const int t    = lane & 3;
    const int n0   = (blockIdx.x % 391) * 128;
    const int half = blockIdx.x / 391;

    {
        const float4* src = (const float4*)(half ? g_web : g_wsb);
        float4* dst = (float4*)(smem + P_B);
#pragma unroll
        for (int it = 0; it < 8; it++) dst[tid + it * 256] = src[tid + it * 256];
    }
#pragma unroll
    for (int it = 0; it < 8; it++) {
        int seg = tid + it * 256;
        int row = seg >> 4, c8 = seg & 15;
        int n = n0 + row; if (n >= NN) n = NN - 1;
        float4 f0 = *(const float4*)(nf + (size_t)n * D + c8 * 8);
        float4 f1 = *(const float4*)(nf + (size_t)n * D + c8 * 8 + 4);
        uint4 u = make_uint4(bf2(f0.x, f0.y), bf2(f0.z, f0.w),
                             bf2(f1.x, f1.y), bf2(f1.z, f1.w));
        *(uint4*)(Ab + row * 272 + c8 * 16) = u;
    }
    __syncthreads();

    float acc[2][8][4];
#pragma unroll
    for (int rg = 0; rg < 2; rg++)
#pragma unroll
        for (int nb = 0; nb < 8; nb++)
#pragma unroll
            for (int i = 0; i < 4; i++) acc[rg][nb][i] = 0.0f;

    {
        const uint2* Bs = (const uint2*)(smem + P_B);
#pragma unroll
        for (int K16 = 0; K16 < 8; K16++) {
            uint32_t a[2][4];
#pragma unroll
            for (int rg = 0; rg < 2; rg++) {
                const char* p = Ab + (wr * 32 + rg * 16 + g) * 272 + K16 * 32 + t * 4;
                a[rg][0] = *(const uint32_t*)p;
                a[rg][1] = *(const uint32_t*)(p + 8 * 272);
                a[rg][2] = *(const uint32_t*)(p + 16);
                a[rg][3] = *(const uint32_t*)(p + 8 * 272 + 16);
            }
#pragma unroll
            for (int nb = 0; nb < 8; nb++) {
                uint2 b = Bs[(K16 * 16 + wc * 8 + nb) * 32 + lane];
                mma_bf16(acc[0][nb], a[0], b.x, b.y);
                mma_bf16(acc[1][nb], a[1], b.x, b.y);
            }
        }
    }

#pragma unroll
    for (int rg = 0; rg < 2; rg++) {
        int r0 = wr * 32 + rg * 16 + g;
#pragma unroll
        for (int h = 0; h < 2; h++) {
            int n = n0 + r0 + 8 * h;
            if (n >= NN) continue;
#pragma unroll
            for (int nb = 0; nb < 8; nb++) {
                int col = wc * 64 + nb * 8 + 2 * t;
                float a0 = h ? acc[rg][nb][2] : acc[rg][nb][0];
                float a1 = h ? acc[rg][nb][3] : acc[rg][nb][1];
                *(float2*)(P + (size_t)n * 256 + half * 128 + col) = make_float2(a0, a1);
            }
        }
    }
}

// ===========================================================================
// Launch 5: node kernel — bf16 mma, fp32 residual (validated R7-R13)
// ===========================================================================
#define N_A0  0
#define N_A1  10240
#define N_B0  20480
#define N_B1  28672
#define N_HB  36864
#define N_BN1 71680
#define N_BN2 72192
#define N_SMEM_BYTES 72704

__global__ void __launch_bounds__(256, 2)
node_kernel(const float* __restrict__ nf, const float* __restrict__ agg,
            const float* __restrict__ bn1, const float* __restrict__ bn2,
            float* __restrict__ out) {
    extern __shared__ char smem[];
    char*  hbuf  = smem + N_HB;
    float* bn1s  = (float*)(smem + N_BN1);
    float* bn2s  = (float*)(smem + N_BN2);

    const int tid  = threadIdx.x;
    const int lane = tid & 31;
    const int wid  = tid >> 5;
    const int wr   = wid & 3;
    const int wc   = wid >> 2;
    const int g    = lane >> 2;
    const int t    = lane & 3;
    const int n0   = blockIdx.x * 128;

    if (tid < 128) { bn1s[tid] = bn1[tid]; bn2s[tid] = bn2[tid]; }

    float acc[2][8][4];
#pragma unroll
    for (int rg = 0; rg < 2; rg++)
#pragma unroll
        for (int nb = 0; nb < 8; nb++)
#pragma unroll
            for (int i = 0; i < 4; i++) acc[rg][nb][i] = 0.0f;

    {
        float4 va[4], vb[2];
        const float4* w1 = (const float4*)g_wn1b;
#pragma unroll
        for (int it = 0; it < 4; it++) {
            int seg = tid + it * 256;
            int e = seg >> 3, s8 = seg & 7;
            int n = n0 + e; if (n >= NN) n = NN - 1;
            va[it] = *(const float4*)(nf + (size_t)n * D + s8 * 4);
        }
#pragma unroll
        for (int it = 0; it < 2; it++) vb[it] = w1[tid + it * 256];
        store_A(smem + N_A0, tid, va);
        {
            float4* dst = (float4*)(smem + N_B0);
#pragma unroll
            for (int it = 0; it < 2; it++) dst[tid + it * 256] = vb[it];
        }
        __syncthreads();

        for (int c = 0; c < 8; c++) {
            const int buf = c & 1;
            if (c < 7) {
                int cn = c + 1;
#pragma unroll
                for (int it = 0; it < 4; it++) {
                    int seg = tid + it * 256;
                    int e = seg >> 3, s8 = seg & 7;
                    int n = n0 + e; if (n >= NN) n = NN - 1;
                    const float* src = (cn < 4)
                        ? nf  + (size_t)n * D  + cn * 32 + s8 * 4
                        : agg + (size_t)n * DM + (cn - 4) * 32 + s8 * 4;
                    va[it] = *(const float4*)src;
                }
#pragma unroll
                for (int it = 0; it < 2; it++)
                    vb[it] = w1[cn * 512 + tid + it * 256];
            }
            const char* Ab = smem + (buf ? N_A1 : N_A0);
            const uint2* Bs = (const uint2*)(smem + (buf ? N_B1 : N_B0));
#pragma unroll
            for (int kcl = 0; kcl < 2; kcl++) {
                uint32_t a[2][4];
#pragma unroll
                for (int rg = 0; rg < 2; rg++) {
                    const char* p = Ab + (wr * 32 + rg * 16 + g) * 80 + kcl * 32 + t * 4;
                    a[rg][0] = *(const uint32_t*)p;
                    a[rg][1] = *(const uint32_t*)(p + 8 * 80);
                    a[rg][2] = *(const uint32_t*)(p + 16);
                    a[rg][3] = *(const uint32_t*)(p + 8 * 80 + 16);
                }
#pragma unroll
                for (int nb = 0; nb < 8; nb++) {
                    uint2 b = Bs[(kcl * 16 + wc * 8 + nb) * 32 + lane];
                    mma_bf16(acc[0][nb], a[0], b.x, b.y);
                    mma_bf16(acc[1][nb], a[1], b.x, b.y);
                }
            }
            __syncthreads();
            if (c < 7) {
                store_A(smem + (((c + 1) & 1) ? N_A1 : N_A0), tid, va);
                float4* dst = (float4*)(smem + (((c + 1) & 1) ? N_B1 : N_B0));
#pragma unroll
                for (int it = 0; it < 2; it++) dst[tid + it * 256] = vb[it];
                __syncthreads();
            }
        }
    }

    {
        const float4* src = (const float4*)g_wn2b;
        float4* dst = (float4*)(smem + N_A0);
#pragma unroll
        for (int it = 0; it < 8; it++) dst[tid + it * 256] = src[tid + it * 256];
    }
#pragma unroll
    for (int rg = 0; rg < 2; rg++) {
        int row0 = wr * 32 + rg * 16 + g;
#pragma unroll
        for (int nb = 0; nb < 8; nb++) {
            int col = wc * 64 + nb * 8 + 2 * t;
            float b0 = bn1s[col], b1 = bn1s[col + 1];
            uint32_t h0 = bf2(siluf(acc[rg][nb][0] + b0), siluf(acc[rg][nb][1] + b1));
            uint32_t h1 = bf2(siluf(acc[rg][nb][2] + b0), siluf(acc[rg][nb][3] + b1));
            *(uint32_t*)(hbuf + row0 * 272 + col * 2) = h0;
            *(uint32_t*)(hbuf + (row0 + 8) * 272 + col * 2) = h1;
            acc[rg][nb][0] = 0.f; acc[rg][nb][1] = 0.f;
            acc[rg][nb][2] = 0.f; acc[rg][nb][3] = 0.f;
        }
    }
    __syncthreads();

    {
        const uint2* B2 = (const uint2*)(smem + N_A0);
#pragma unroll
        for (int K16 = 0; K16 < 8; K16++) {
            uint32_t a[2][4];
#pragma unroll
            for (int rg = 0; rg < 2; rg++) {
                const char* p = hbuf + (wr * 32 + rg * 16 + g) * 272 + K16 * 32 + t * 4;
                a[rg][0] = *(const uint32_t*)p;
                a[rg][1] = *(const uint32_t*)(p + 8 * 272);
                a[rg][2] = *(const uint32_t*)(p + 16);
                a[rg][3] = *(const uint32_t*)(p + 8 * 272 + 16);
            }
#pragma unroll
            for (int nb = 0; nb < 8; nb++) {
                uint2 b = B2[(K16 * 16 + wc * 8 + nb) * 32 + lane];
                mma_bf16(acc[0][nb], a[0], b.x, b.y);
                mma_bf16(acc[1][nb], a[1], b.x, b.y);
            }
        }
    }

#pragma unroll
    for (int rg = 0; rg < 2; rg++) {
        int r0 = wr * 32 + rg * 16 + g;
#pragma unroll
        for (int h = 0; h < 2; h++) {
            int n = n0 + r0 + 8 * h;
            if (n >= NN) continue;
#pragma unroll
            for (int nb = 0; nb < 8; nb++) {
                int col = wc * 64 + nb * 8 + 2 * t;
                float2 res = *(const float2*)(nf + (size_t)n * D + col);
                float a0 = (h ? acc[rg][nb][2] : acc[rg][nb][0]) + bn2s[col] + res.x;
                float a1 = (h ? acc[rg][nb][3] : acc[rg][nb][1]) + bn2s[col + 1] + res.y;
                *(float2*)(out + (size_t)n * D + col) = make_float2(a0, a1);
            }
        }
    }
}

// ===========================================================================
// Launch 6: idx passthrough + cleanup for next call
// ===========================================================================
__global__ void idx_cleanup_kernel(const int4* __restrict__ ei,
                                   float4* __restrict__ out) {
    int i = blockIdx.x * blockDim.x + threadIdx.x;
    if (i < (2 * NE) / 4) {
        int4 v = ei[i];
        out[i] = make_float4((float)v.x, (float)v.y, (float)v.z, (float)v.w);
    }
    float4 z4 = make_float4(0.f, 0.f, 0.f, 0.f);
    for (int j = i; j < NN * DM / 4; j += 400128)
        ((float4*)g_agg)[j] = z4;
    if (i < NN) { g_hist[i] = 0; g_cnt[i] = 0; }
}

// ---------------------------------------------------------------------------
extern "C" void kernel_launch(void* const* d_in, const int* in_sizes, int n_in,
                              void* d_out, int out_size) {
    const float* nf  = (const float*)d_in[0];
    const int*   ei  = (const int*)d_in[1];
    const float* ef  = (const float*)d_in[2];
    const float* We1 = (const float*)d_in[3];
    const float* be1 = (const float*)d_in[4];
    const float* We2 = (const float*)d_in[5];
    const float* be2 = (const float*)d_in[6];
    const float* Wi  = (const float*)d_in[7];
    const float* bi  = (const float*)d_in[8];
    const float* Wn1 = (const float*)d_in[9];
    const float* bn1 = (const float*)d_in[10];
    const float* Wn2 = (const float*)d_in[11];
    const float* bn2 = (const float*)d_in[12];
    float* out = (float*)d_out;

    cudaFuncSetAttribute(edge_kernel, cudaFuncAttributeMaxDynamicSharedMemorySize, E_SMEM_BYTES);
    cudaFuncSetAttribute(node_kernel, cudaFuncAttributeMaxDynamicSharedMemorySize, N_SMEM_BYTES);
    cudaFuncSetAttribute(pp_kernel, cudaFuncAttributeMaxDynamicSharedMemorySize, P_SMEM_BYTES);

    void *aggp, *pp;
    cudaGetSymbolAddress(&aggp, g_agg);
    cudaGetSymbolAddress(&pp, g_P);

    hist_pack_kernel<<<3125, 256>>>(ei, We1, We2, Wn1, Wn2);              // k1
    scan_kernel<<<1, 1024>>>();                                           // k2
    pp_kernel<<<PP_PBLK + 3125, 256, P_SMEM_BYTES>>>(ei, nf, (float*)pp); // k3
    edge_kernel<<<NE / 64, 256, E_SMEM_BYTES>>>(nf, ei, ef, (const float*)pp,
                                                be1, be2, Wi, bi, (float*)aggp); // k4
    node_kernel<<<(NN + 127) / 128, 256, N_SMEM_BYTES>>>(nf, (const float*)aggp,
                                                         bn1, bn2, out);          // k5
    idx_cleanup_kernel<<<1563, 256>>>((const int4*)ei,
                                      (float4*)(out + (size_t)NN * D));           // k6
    cudaMemcpyAsync(out + (size_t)NN * D + 2ull * NE, d_in[2],
                    (size_t)NE * DE * sizeof(float), cudaMemcpyDeviceToDevice);
}

// round 15
// speedup vs baseline: 1.4701x; 1.0971x over previous
#include <cuda_runtime.h>
#include <cstdint>

#define NN 50000
#define NE 800000
#define D  128
#define DE 16
#define DM 128

// ---------------------------------------------------------------------------
// Global scratch (g_hist/g_cnt/g_agg zero at module load; each call re-zeros
// them at the END for the next call)
// ---------------------------------------------------------------------------
__device__ float g_agg[NN * DM];
__device__ float g_P[NN * 256];
__device__ int   g_hist[NN];
__device__ int   g_off[NN];
__device__ int   g_cnt[NN];
__device__ int   g_perm[NE];
__device__ __align__(16) uint2 g_wsb[8 * 16 * 32];    // We1 rows 0..127
__device__ __align__(16) uint2 g_web[8 * 16 * 32];    // We1 rows 128..255
__device__ __align__(16) uint2 g_wefb[2 * 16 * 32];   // We1 rows 256..271 (pad 32)
__device__ __align__(16) uint2 g_w2b[8 * 16 * 32];    // We2
__device__ __align__(16) uint2 g_wn1b[16 * 16 * 32];  // Wn1
__device__ __align__(16) uint2 g_wn2b[8 * 16 * 32];   // Wn2

// ---------------------------------------------------------------------------
// helpers
// ---------------------------------------------------------------------------
__device__ __forceinline__ float siluf(float x) { return x / (1.0f + __expf(-x)); }
__device__ __forceinline__ float sigmoidf_(float x) { return 1.0f / (1.0f + __expf(-x)); }

__device__ __forceinline__ uint32_t bf2(float lo, float hi) {
    uint32_t r;
    asm("cvt.rn.bf16x2.f32 %0, %1, %2;" : "=r"(r) : "f"(hi), "f"(lo));
    return r;
}
__device__ __forceinline__ float bflo(uint32_t u) { return __uint_as_float(u << 16); }
__device__ __forceinline__ float bfhi(uint32_t u) { return __uint_as_float(u & 0xffff0000u); }
__device__ __forceinline__ void mma_bf16(float c[4], const uint32_t a[4],
                                         uint32_t b0, uint32_t b1) {
    asm volatile("mma.sync.aligned.m16n8k16.row.col.f32.bf16.bf16.f32 "
        "{%0,%1,%2,%3}, {%4,%5,%6,%7}, {%8,%9}, {%0,%1,%2,%3};"
        : "+f"(c[0]), "+f"(c[1]), "+f"(c[2]), "+f"(c[3])
        : "r"(a[0]), "r"(a[1]), "r"(a[2]), "r"(a[3]), "r"(b0), "r"(b1));
}
__device__ __forceinline__ void ldsm_x4(uint32_t a[4], uint32_t saddr) {
    asm volatile("ldmatrix.sync.aligned.m8n8.x4.shared.b16 {%0,%1,%2,%3}, [%4];"
        : "=r"(a[0]), "=r"(a[1]), "=r"(a[2]), "=r"(a[3]) : "r"(saddr));
}
__device__ __forceinline__ uint32_t smem_u32(const void* p) {
    return (uint32_t)__cvta_generic_to_shared(p);
}
__device__ __forceinline__ void red_add_v2(float* p, float a, float b) {
    asm volatile("red.global.add.v2.f32 [%0], {%1, %2};"
                 :: "l"(p), "f"(a), "f"(b) : "memory");
}

__device__ __forceinline__ void store_A(char* Ab, int tid, const float4 va[4]) {
#pragma unroll
    for (int it = 0; it < 4; it++) {
        int seg = tid + it * 256;
        int e = seg >> 3, s8 = seg & 7;
        uint2 u = make_uint2(bf2(va[it].x, va[it].y), bf2(va[it].z, va[it].w));
        *(uint2*)(Ab + e * 80 + s8 * 8) = u;
    }
}

// ===========================================================================
// EDGE KERNEL — 64-edge tiles, 4 CTAs/SM, warp = 32 rows x 32 cols
// SMEM (53760 B):
//   SB  bf16 [64 x 272B] : S -> h -> m, all in place    0..17408
//   W2S 32768 (staged in phase A, persistent to GEMM2)  17408..50176
//   misc @ 50176 (3584)
// 6 syncthreads per tile. ef MMA operands come straight from global.
// ===========================================================================
#define E_SB     0
#define E_W2S    17408
#define E_MISC   50176
#define E_STARTS (E_MISC)
#define E_ENDS   (E_MISC + 256)
#define E_EIDX   (E_MISC + 512)
#define E_BE1    (E_MISC + 768)
#define E_BE2    (E_MISC + 1280)
#define E_WIS    (E_MISC + 1792)
#define E_GATES  (E_MISC + 2304)
#define E_GPART  (E_MISC + 2560)          // 64 rows x 4 quarters = 1024B
#define E_SMEM_BYTES (E_MISC + 3584)      // 53760

__global__ void __launch_bounds__(256, 4)
edge_kernel(const float* __restrict__ nf, const int* __restrict__ ei,
            const float* __restrict__ ef, const float* __restrict__ P,
            const float* __restrict__ be1, const float* __restrict__ be2,
            const float* __restrict__ Wi, const float* __restrict__ bi,
            float* __restrict__ agg) {
    extern __shared__ char smem[];
    char*  SB     = smem + E_SB;                  // 272B row stride, bf16
    int*   starts = (int*)(smem + E_STARTS);
    int*   ends   = (int*)(smem + E_ENDS);
    int*   eidx   = (int*)(smem + E_EIDX);
    float* be1s   = (float*)(smem + E_BE1);
    float* be2s   = (float*)(smem + E_BE2);
    float* wis    = (float*)(smem + E_WIS);
    float* gates  = (float*)(smem + E_GATES);
    float* gpart  = (float*)(smem + E_GPART);

    const int tid  = threadIdx.x;
    const int lane = tid & 31;
    const int wid  = tid >> 5;
    const int wr   = wid & 1;        // row half: rows wr*32 .. +31
    const int wc   = wid >> 1;       // col quarter: cols wc*32 .. +31
    const int g    = lane >> 2;
    const int t    = lane & 3;
    const int e0   = blockIdx.x * 64;
    const float bi0 = __ldg(bi);
    const int lm_row = lane & 15;
    const int lm_off = (lane >> 4) << 4;

    if (tid < 64) {
        int e = g_perm[e0 + tid];
        eidx[tid]   = e;
        starts[tid] = ei[e];
        ends[tid]   = ei[NE + e];
    }
    if (tid < 128) {
        be1s[tid] = be1[tid];
        be2s[tid] = be2[tid];
        wis[tid]  = Wi[tid];
    }
    __syncthreads();                                   // sync 1

    // ---- phase A: W2 staging + P gather-add -> SB (bf16) ----
    {
        const float4* w2 = (const float4*)g_w2b;
        float4* d2 = (float4*)(smem + E_W2S);
#pragma unroll
        for (int it = 0; it < 8; it++) d2[tid + it * 256] = w2[tid + it * 256];
    }
#pragma unroll
    for (int it = 0; it < 8; it++) {
        int seg = tid + it * 256;              // 0..2047
        int row = seg >> 5, c4 = (seg & 31) * 4;
        int s = starts[row], e_ = ends[row];
        float4 a = *(const float4*)(P + (size_t)s * 256 + c4);
        float4 b = *(const float4*)(P + (size_t)e_ * 256 + 128 + c4);
        uint2 u = make_uint2(bf2(a.x + b.x, a.y + b.y),
                             bf2(a.z + b.z, a.w + b.w));
        *(uint2*)(SB + row * 272 + c4 * 2) = u;
    }

    float acc[2][4][4];
#pragma unroll
    for (int rg = 0; rg < 2; rg++)
#pragma unroll
        for (int nb = 0; nb < 4; nb++)
#pragma unroll
            for (int i = 0; i < 4; i++) acc[rg][nb][i] = 0.0f;

    // ---- ef MMA (K=16): A from global ef, B from global g_wefb ----
#pragma unroll
    for (int rg = 0; rg < 2; rg++) {
        const int R = wr * 32 + rg * 16;
        int ea = eidx[R + g];
        int eb = eidx[R + 8 + g];
        float2 v0 = *(const float2*)(ef + (size_t)ea * DE + 2 * t);
        float2 v1 = *(const float2*)(ef + (size_t)eb * DE + 2 * t);
        float2 v2 = *(const float2*)(ef + (size_t)ea * DE + 8 + 2 * t);
        float2 v3 = *(const float2*)(ef + (size_t)eb * DE + 8 + 2 * t);
        uint32_t a[4] = { bf2(v0.x, v0.y), bf2(v1.x, v1.y),
                          bf2(v2.x, v2.y), bf2(v3.x, v3.y) };
#pragma unroll
        for (int nb = 0; nb < 4; nb++) {
            uint2 b = g_wefb[(wc * 4 + nb) * 32 + lane];
            mma_bf16(acc[rg][nb], a, b.x, b.y);
        }
    }
    __syncthreads();                                   // sync 2 (SB + W2S ready)

    // ---- Epilogue 1: h = silu(acc + S + be1), IN PLACE over SB ----
#pragma unroll
    for (int rg = 0; rg < 2; rg++) {
        const int r0 = wr * 32 + rg * 16 + g;
#pragma unroll
        for (int nb = 0; nb < 4; nb++) {
            int col = wc * 32 + nb * 8 + 2 * t;
            uint32_t s0 = *(const uint32_t*)(SB + r0 * 272 + col * 2);
            uint32_t s1 = *(const uint32_t*)(SB + (r0 + 8) * 272 + col * 2);
            float b0 = be1s[col], b1 = be1s[col + 1];
            uint32_t h0 = bf2(siluf(acc[rg][nb][0] + bflo(s0) + b0),
                              siluf(acc[rg][nb][1] + bfhi(s0) + b1));
            uint32_t h1 = bf2(siluf(acc[rg][nb][2] + bflo(s1) + b0),
                              siluf(acc[rg][nb][3] + bfhi(s1) + b1));
            *(uint32_t*)(SB + r0 * 272 + col * 2) = h0;
            *(uint32_t*)(SB + (r0 + 8) * 272 + col * 2) = h1;
            acc[rg][nb][0] = 0.f; acc[rg][nb][1] = 0.f;
            acc[rg][nb][2] = 0.f; acc[rg][nb][3] = 0.f;
        }
    }
    __syncthreads();                                   // sync 3 (h ready)

    // ---- GEMM2: D2 = h @ We2 (K=128, ldsm A from SB, B from W2S) ----
    {
        const uint2* B2 = (const uint2*)(smem + E_W2S);
#pragma unroll
        for (int K16 = 0; K16 < 8; K16++) {
            uint32_t a[2][4];
#pragma unroll
            for (int rg = 0; rg < 2; rg++) {
                uint32_t sa = smem_u32(SB + (wr * 32 + rg * 16 + lm_row) * 272
                                       + K16 * 32 + lm_off);
                ldsm_x4(a[rg], sa);
            }
#pragma unroll
            for (int nb = 0; nb < 4; nb++) {
                uint2 b = B2[(K16 * 16 + wc * 4 + nb) * 32 + lane];
                mma_bf16(acc[0][nb], a[0], b.x, b.y);
                mma_bf16(acc[1][nb], a[1], b.x, b.y);
            }
        }
    }
    __syncthreads();                                   // sync 4 (all h reads done)

    // ---- Epilogue 2: m = D2 + be2 -> SB IN PLACE (bf16); gate partials ----
#pragma unroll
    for (int rg = 0; rg < 2; rg++) {
        const int r0 = wr * 32 + rg * 16 + g;
        float p0 = 0.f, p1 = 0.f;
#pragma unroll
        for (int nb = 0; nb < 4; nb++) {
            int col = wc * 32 + nb * 8 + 2 * t;
            float b0 = be2s[col], b1 = be2s[col + 1];
            float m0x = acc[rg][nb][0] + b0, m0y = acc[rg][nb][1] + b1;
            float m1x = acc[rg][nb][2] + b0, m1y = acc[rg][nb][3] + b1;
            *(uint32_t*)(SB + r0 * 272 + col * 2) = bf2(m0x, m0y);
            *(uint32_t*)(SB + (r0 + 8) * 272 + col * 2) = bf2(m1x, m1y);
            float w0 = wis[col], w1 = wis[col + 1];
            p0 += m0x * w0 + m0y * w1;
            p1 += m1x * w0 + m1y * w1;
        }
        p0 += __shfl_xor_sync(0xffffffffu, p0, 1);
        p0 += __shfl_xor_sync(0xffffffffu, p0, 2);
        p1 += __shfl_xor_sync(0xffffffffu, p1, 1);
        p1 += __shfl_xor_sync(0xffffffffu, p1, 2);
        if (t == 0) {
            gpart[r0 * 4 + wc] = p0;
            gpart[(r0 + 8) * 4 + wc] = p1;
        }
    }
    __syncthreads();                                   // sync 5
    if (tid < 64)
        gates[tid] = sigmoidf_(gpart[4 * tid] + gpart[4 * tid + 1]
                               + gpart[4 * tid + 2] + gpart[4 * tid + 3] + bi0);
    __syncthreads();                                   // sync 6

    // ---- segmented gated scatter from bf16 SB (rows sorted by start) ----
    {
        const int cp = tid & 63;          // column pair: cols 2cp, 2cp+1
        const int q  = tid >> 6;          // row quarter: rows q*16 .. +15
        const int rbase = q * 16;
        float a0 = 0.f, a1 = 0.f;
        int sprev = starts[rbase];
#pragma unroll
        for (int i = 0; i < 16; i++) {
            int r = rbase + i;
            int s = starts[r];
            if (s != sprev) {
                red_add_v2(agg + (size_t)sprev * DM + 2 * cp, a0, a1);
                a0 = 0.f; a1 = 0.f;
                sprev = s;
            }
            uint32_t u = *(const uint32_t*)(SB + r * 272 + cp * 4);
            float gt = gates[r];
            a0 += bflo(u) * gt;
            a1 += bfhi(u) * gt;
        }
        red_add_v2(agg + (size_t)sprev * DM + 2 * cp, a0, a1);
    }
}

// ===========================================================================
// Launch 1: hist + weight pack
// ===========================================================================
__device__ __forceinline__ uint2 pack_frag2(const float* W, int idx, int row0, int rowlim) {
    int lane = idx & 31;
    int nbk = idx >> 5;
    int k0 = (nbk >> 4) * 16;
    int n = (nbk & 15) * 8 + (lane >> 2);
    int t2 = (lane & 3) * 2;
    int r = row0 + k0 + t2;
    float v00 = (r     < rowlim) ? W[(size_t)r * 128 + n] : 0.0f;
    float v01 = (r + 1 < rowlim) ? W[(size_t)(r + 1) * 128 + n] : 0.0f;
    float v10 = (r + 8 < rowlim) ? W[(size_t)(r + 8) * 128 + n] : 0.0f;
    float v11 = (r + 9 < rowlim) ? W[(size_t)(r + 9) * 128 + n] : 0.0f;
    return make_uint2(bf2(v00, v01), bf2(v10, v11));
}

__global__ void hist_pack_kernel(const int* __restrict__ ei,
                                 const float* __restrict__ We1, const float* __restrict__ We2,
                                 const float* __restrict__ Wn1, const float* __restrict__ Wn2) {
    int i = blockIdx.x * 256 + threadIdx.x;
    if (i < 4096)        g_wsb[i] = pack_frag2(We1, i, 0, 272);
    else if (i < 8192)   g_web[i - 4096] = pack_frag2(We1, i - 4096, 128, 272);
    else if (i < 9216)   g_wefb[i - 8192] = pack_frag2(We1, i - 8192, 256, 272);
    else if (i < 13312)  g_w2b[i - 9216] = pack_frag2(We2, i - 9216, 0, 128);
    else if (i < 21504)  g_wn1b[i - 13312] = pack_frag2(Wn1, i - 13312, 0, 256);
    else if (i < 25600)  g_wn2b[i - 21504] = pack_frag2(Wn2, i - 21504, 0, 128);
    if (i < NE) atomicAdd(&g_hist[ei[i]], 1);
}

// ===========================================================================
// Launch 2: scan
// ===========================================================================
__global__ void scan_kernel() {
    const int CH = 49;
    __shared__ int ws[32];
    int t = threadIdx.x;
    int base = t * CH;
    int sum = 0;
#pragma unroll 7
    for (int i = 0; i < CH; i++) {
        int idx = base + i;
        if (idx < NN) sum += g_hist[idx];
    }
    int lane = t & 31, wid = t >> 5;
    int v = sum;
#pragma unroll
    for (int o = 1; o < 32; o <<= 1) {
        int u = __shfl_up_sync(0xffffffffu, v, o);
        if (lane >= o) v += u;
    }
    if (lane == 31) ws[wid] = v;
    __syncthreads();
    if (wid == 0) {
        int w = ws[lane];
#pragma unroll
        for (int o = 1; o < 32; o <<= 1) {
            int u = __shfl_up_sync(0xffffffffu, w, o);
            if (lane >= o) w += u;
        }
        ws[lane] = w;
    }
    __syncthreads();
    int pre = v - sum + (wid > 0 ? ws[wid - 1] : 0);
    int run = pre;
    for (int i = 0; i < CH; i++) {
        int idx = base + i;
        if (idx < NN) {
            int h = g_hist[idx];
            g_off[idx] = run;
            run += h;
        }
    }
}

// ===========================================================================
// Launch 3: fused permute + P GEMM
// ===========================================================================
#define PP_PBLK 782
#define P_A 0
#define P_B 34816
#define P_SMEM_BYTES 67584

__global__ void __launch_bounds__(256, 2)
pp_kernel(const int* __restrict__ ei, const float* __restrict__ nf,
          float* __restrict__ P) {
    extern __shared__ char smem[];
    const int tid = threadIdx.x;

    if (blockIdx.x >= PP_PBLK) {
        int e = (blockIdx.x - PP_PBLK) * 256 + tid;
        if (e < NE) {
            int s = ei[e];
            int pos = g_off[s] + atomicAdd(&g_cnt[s], 1);
            g_perm[pos] = e;
        }
        return;
    }

    char* Ab = smem + P_A;
    const int lane = tid & 31;
    const int wid  = tid >> 5;
    const int wr   = wid & 3;
    const int wc   = wid >> 2;
    const int g    = lane >> 2;
    const int t    = lane & 3;
    const int n0   = (blockIdx.x % 391) * 128;
    const int half = blockIdx.x / 391;

    {
        const float4* src = (const float4*)(half ? g_web : g_wsb);
        float4* dst = (float4*)(smem + P_B);
#pragma unroll
        for (int it = 0; it < 8; it++) dst[tid + it * 256] = src[tid + it * 256];
    }
#pragma unroll
    for (int it = 0; it < 8; it++) {
        int seg = tid + it * 256;
        int row = seg >> 4, c8 = seg & 15;
        int n = n0 + row; if (n >= NN) n = NN - 1;
        float4 f0 = *(const float4*)(nf + (size_t)n * D + c8 * 8);
        float4 f1 = *(const float4*)(nf + (size_t)n * D + c8 * 8 + 4);
        uint4 u = make_uint4(bf2(f0.x, f0.y), bf2(f0.z, f0.w),
                             bf2(f1.x, f1.y), bf2(f1.z, f1.w));
        *(uint4*)(Ab + row * 272 + c8 * 16) = u;
    }
    __syncthreads();

    float acc[2][8][4];
#pragma unroll
    for (int rg = 0; rg < 2; rg++)
#pragma unroll
        for (int nb = 0; nb < 8; nb++)
#pragma unroll
            for (int i = 0; i < 4; i++) acc[rg][nb][i] = 0.0f;

    {
        const uint2* Bs = (const uint2*)(smem + P_B);
#pragma unroll
        for (int K16 = 0; K16 < 8; K16++) {
            uint32_t a[2][4];
#pragma unroll
            for (int rg = 0; rg < 2; rg++) {
                const char* p = Ab + (wr * 32 + rg * 16 + g) * 272 + K16 * 32 + t * 4;
                a[rg][0] = *(const uint32_t*)p;
                a[rg][1] = *(const uint32_t*)(p + 8 * 272);
                a[rg][2] = *(const uint32_t*)(p + 16);
                a[rg][3] = *(const uint32_t*)(p + 8 * 272 + 16);
            }
#pragma unroll
            for (int nb = 0; nb < 8; nb++) {
                uint2 b = Bs[(K16 * 16 + wc * 8 + nb) * 32 + lane];
                mma_bf16(acc[0][nb], a[0], b.x, b.y);
                mma_bf16(acc[1][nb], a[1], b.x, b.y);
            }
        }
    }

#pragma unroll
    for (int rg = 0; rg < 2; rg++) {
        int r0 = wr * 32 + rg * 16 + g;
#pragma unroll
        for (int h = 0; h < 2; h++) {
            int n = n0 + r0 + 8 * h;
            if (n >= NN) continue;
#pragma unroll
            for (int nb = 0; nb < 8; nb++) {
                int col = wc * 64 + nb * 8 + 2 * t;
                float a0 = h ? acc[rg][nb][2] : acc[rg][nb][0];
                float a1 = h ? acc[rg][nb][3] : acc[rg][nb][1];
                *(float2*)(P + (size_t)n * 256 + half * 128 + col) = make_float2(a0, a1);
            }
        }
    }
}

// ===========================================================================
// Launch 5: node kernel — bf16 mma, fp32 residual (validated R7-R14)
// ===========================================================================
#define N_A0  0
#define N_A1  10240
#define N_B0  20480
#define N_B1  28672
#define N_HB  36864
#define N_BN1 71680
#define N_BN2 72192
#define N_SMEM_BYTES 72704

__global__ void __launch_bounds__(256, 2)
node_kernel(const float* __restrict__ nf, const float* __restrict__ agg,
            const float* __restrict__ bn1, const float* __restrict__ bn2,
            float* __restrict__ out) {
    extern __shared__ char smem[];
    char*  hbuf  = smem + N_HB;
    float* bn1s  = (float*)(smem + N_BN1);
    float* bn2s  = (float*)(smem + N_BN2);

    const int tid  = threadIdx.x;
    const int lane = tid & 31;
    const int wid  = tid >> 5;
    const int wr   = wid & 3;
    const int wc   = wid >> 2;
    const int g    = lane >> 2;
    const int t    = lane & 3;
    const int n0   = blockIdx.x * 128;

    if (tid < 128) { bn1s[tid] = bn1[tid]; bn2s[tid] = bn2[tid]; }

    float acc[2][8][4];
#pragma unroll
    for (int rg = 0; rg < 2; rg++)
#pragma unroll
        for (int nb = 0; nb < 8; nb++)
#pragma unroll
            for (int i = 0; i < 4; i++) acc[rg][nb][i] = 0.0f;

    {
        float4 va[4], vb[2];
        const float4* w1 = (const float4*)g_wn1b;
#pragma unroll
        for (int it = 0; it < 4; it++) {
            int seg = tid + it * 256;
            int e = seg >> 3, s8 = seg & 7;
            int n = n0 + e; if (n >= NN) n = NN - 1;
            va[it] = *(const float4*)(nf + (size_t)n * D + s8 * 4);
        }
#pragma unroll
        for (int it = 0; it < 2; it++) vb[it] = w1[tid + it * 256];
        store_A(smem + N_A0, tid, va);
        {
            float4* dst = (float4*)(smem + N_B0);
#pragma unroll
            for (int it = 0; it < 2; it++) dst[tid + it * 256] = vb[it];
        }
        __syncthreads();

        for (int c = 0; c < 8; c++) {
            const int buf = c & 1;
            if (c < 7) {
                int cn = c + 1;
#pragma unroll
                for (int it = 0; it < 4; it++) {
                    int seg = tid + it * 256;
                    int e = seg >> 3, s8 = seg & 7;
                    int n = n0 + e; if (n >= NN) n = NN - 1;
                    const float* src = (cn < 4)
                        ? nf  + (size_t)n * D  + cn * 32 + s8 * 4
                        : agg + (size_t)n * DM + (cn - 4) * 32 + s8 * 4;
                    va[it] = *(const float4*)src;
                }
#pragma unroll
                for (int it = 0; it < 2; it++)
                    vb[it] = w1[cn * 512 + tid + it * 256];
            }
            const char* Ab = smem + (buf ? N_A1 : N_A0);
            const uint2* Bs = (const uint2*)(smem + (buf ? N_B1 : N_B0));
#pragma unroll
            for (int kcl = 0; kcl < 2; kcl++) {
                uint32_t a[2][4];
#pragma unroll
                for (int rg = 0; rg < 2; rg++) {
                    const char* p = Ab + (wr * 32 + rg * 16 + g) * 80 + kcl * 32 + t * 4;
                    a[rg][0] = *(const uint32_t*)p;
                    a[rg][1] = *(const uint32_t*)(p + 8 * 80);
                    a[rg][2] = *(const uint32_t*)(p + 16);
                    a[rg][3] = *(const uint32_t*)(p + 8 * 80 + 16);
                }
#pragma unroll
                for (int nb = 0; nb < 8; nb++) {
                    uint2 b = Bs[(kcl * 16 + wc * 8 + nb) * 32 + lane];
                    mma_bf16(acc[0][nb], a[0], b.x, b.y);
                    mma_bf16(acc[1][nb], a[1], b.x, b.y);
                }
            }
            __syncthreads();
            if (c < 7) {
                store_A(smem + (((c + 1) & 1) ? N_A1 : N_A0), tid, va);
                float4* dst = (float4*)(smem + (((c + 1) & 1) ? N_B1 : N_B0));
#pragma unroll
                for (int it = 0; it < 2; it++) dst[tid + it * 256] = vb[it];
                __syncthreads();
            }
        }
    }

    {
        const float4* src = (const float4*)g_wn2b;
        float4* dst = (float4*)(smem + N_A0);
#pragma unroll
        for (int it = 0; it < 8; it++) dst[tid + it * 256] = src[tid + it * 256];
    }
#pragma unroll
    for (int rg = 0; rg < 2; rg++) {
        int row0 = wr * 32 + rg * 16 + g;
#pragma unroll
        for (int nb = 0; nb < 8; nb++) {
            int col = wc * 64 + nb * 8 + 2 * t;
            float b0 = bn1s[col], b1 = bn1s[col + 1];
            uint32_t h0 = bf2(siluf(acc[rg][nb][0] + b0), siluf(acc[rg][nb][1] + b1));
            uint32_t h1 = bf2(siluf(acc[rg][nb][2] + b0), siluf(acc[rg][nb][3] + b1));
            *(uint32_t*)(hbuf + row0 * 272 + col * 2) = h0;
            *(uint32_t*)(hbuf + (row0 + 8) * 272 + col * 2) = h1;
            acc[rg][nb][0] = 0.f; acc[rg][nb][1] = 0.f;
            acc[rg][nb][2] = 0.f; acc[rg][nb][3] = 0.f;
        }
    }
    __syncthreads();

    {
        const uint2* B2 = (const uint2*)(smem + N_A0);
#pragma unroll
        for (int K16 = 0; K16 < 8; K16++) {
            uint32_t a[2][4];
#pragma unroll
            for (int rg = 0; rg < 2; rg++) {
                const char* p = hbuf + (wr * 32 + rg * 16 + g) * 272 + K16 * 32 + t * 4;
                a[rg][0] = *(const uint32_t*)p;
                a[rg][1] = *(const uint32_t*)(p + 8 * 272);
                a[rg][2] = *(const uint32_t*)(p + 16);
                a[rg][3] = *(const uint32_t*)(p + 8 * 272 + 16);
            }
#pragma unroll
            for (int nb = 0; nb < 8; nb++) {
                uint2 b = B2[(K16 * 16 + wc * 8 + nb) * 32 + lane];
                mma_bf16(acc[0][nb], a[0], b.x, b.y);
                mma_bf16(acc[1][nb], a[1], b.x, b.y);
            }
        }
    }

#pragma unroll
    for (int rg = 0; rg < 2; rg++) {
        int r0 = wr * 32 + rg * 16 + g;
#pragma unroll
        for (int h = 0; h < 2; h++) {
            int n = n0 + r0 + 8 * h;
            if (n >= NN) continue;
#pragma unroll
            for (int nb = 0; nb < 8; nb++) {
                int col = wc * 64 + nb * 8 + 2 * t;
                float2 res = *(const float2*)(nf + (size_t)n * D + col);
                float a0 = (h ? acc[rg][nb][2] : acc[rg][nb][0]) + bn2s[col] + res.x;
                float a1 = (h ? acc[rg][nb][3] : acc[rg][nb][1]) + bn2s[col + 1] + res.y;
                *(float2*)(out + (size_t)n * D + col) = make_float2(a0, a1);
            }
        }
    }
}

// ===========================================================================
// Launch 6: idx passthrough + cleanup for next call
// ===========================================================================
__global__ void idx_cleanup_kernel(const int4* __restrict__ ei,
                                   float4* __restrict__ out) {
    int i = blockIdx.x * blockDim.x + threadIdx.x;
    if (i < (2 * NE) / 4) {
        int4 v = ei[i];
        out[i] = make_float4((float)v.x, (float)v.y, (float)v.z, (float)v.w);
    }
    float4 z4 = make_float4(0.f, 0.f, 0.f, 0.f);
    for (int j = i; j < NN * DM / 4; j += 400128)
        ((float4*)g_agg)[j] = z4;
    if (i < NN) { g_hist[i] = 0; g_cnt[i] = 0; }
}

// ---------------------------------------------------------------------------
extern "C" void kernel_launch(void* const* d_in, const int* in_sizes, int n_in,
                              void* d_out, int out_size) {
    const float* nf  = (const float*)d_in[0];
    const int*   ei  = (const int*)d_in[1];
    const float* ef  = (const float*)d_in[2];
    const float* We1 = (const float*)d_in[3];
    const float* be1 = (const float*)d_in[4];
    const float* We2 = (const float*)d_in[5];
    const float* be2 = (const float*)d_in[6];
    const float* Wi  = (const float*)d_in[7];
    const float* bi  = (const float*)d_in[8];
    const float* Wn1 = (const float*)d_in[9];
    const float* bn1 = (const float*)d_in[10];
    const float* Wn2 = (const float*)d_in[11];
    const float* bn2 = (const float*)d_in[12];
    float* out = (float*)d_out;

    cudaFuncSetAttribute(edge_kernel, cudaFuncAttributeMaxDynamicSharedMemorySize, E_SMEM_BYTES);
    cudaFuncSetAttribute(node_kernel, cudaFuncAttributeMaxDynamicSharedMemorySize, N_SMEM_BYTES);
    cudaFuncSetAttribute(pp_kernel, cudaFuncAttributeMaxDynamicSharedMemorySize, P_SMEM_BYTES);

    void *aggp, *pp;
    cudaGetSymbolAddress(&aggp, g_agg);
    cudaGetSymbolAddress(&pp, g_P);

    hist_pack_kernel<<<3125, 256>>>(ei, We1, We2, Wn1, Wn2);              // k1
    scan_kernel<<<1, 1024>>>();                                           // k2
    pp_kernel<<<PP_PBLK + 3125, 256, P_SMEM_BYTES>>>(ei, nf, (float*)pp); // k3
    edge_kernel<<<NE / 64, 256, E_SMEM_BYTES>>>(nf, ei, ef, (const float*)pp,
                                                be1, be2, Wi, bi, (float*)aggp); // k4
    node_kernel<<<(NN + 127) / 128, 256, N_SMEM_BYTES>>>(nf, (const float*)aggp,
                                                         bn1, bn2, out);          // k5
    idx_cleanup_kernel<<<1563, 256>>>((const int4*)ei,
                                      (float4*)(out + (size_t)NN * D));           // k6
    cudaMemcpyAsync(out + (size_t)NN * D + 2ull * NE, d_in[2],
                    (size_t)NE * DE * sizeof(float), cudaMemcpyDeviceToDevice);
}

// round 16
// speedup vs baseline: 1.5263x; 1.0382x over previous
#include <cuda_runtime.h>
#include <cstdint>

#define NN 50000
#define NE 800000
#define D  128
#define DE 16
#define DM 128

// ---------------------------------------------------------------------------
// Global scratch (g_hist/g_cnt/g_agg zero at module load; each call re-zeros
// them at the END for the next call)
// ---------------------------------------------------------------------------
__device__ float g_agg[NN * DM];
__device__ float g_P[NN * 256];
__device__ int   g_hist[NN];
__device__ int   g_off[NN];
__device__ int   g_cnt[NN];
__device__ int   g_perm[NE];
__device__ __align__(16) uint2 g_wsb[8 * 16 * 32];    // We1 rows 0..127
__device__ __align__(16) uint2 g_web[8 * 16 * 32];    // We1 rows 128..255
__device__ __align__(16) uint2 g_wefb[2 * 16 * 32];   // We1 rows 256..271 (pad 32)
__device__ __align__(16) uint2 g_w2b[8 * 16 * 32];    // We2
__device__ __align__(16) uint2 g_wn1b[16 * 16 * 32];  // Wn1
__device__ __align__(16) uint2 g_wn2b[8 * 16 * 32];   // Wn2

// ---------------------------------------------------------------------------
// helpers
// ---------------------------------------------------------------------------
__device__ __forceinline__ float siluf(float x) { return x / (1.0f + __expf(-x)); }
__device__ __forceinline__ float sigmoidf_(float x) { return 1.0f / (1.0f + __expf(-x)); }

__device__ __forceinline__ uint32_t bf2(float lo, float hi) {
    uint32_t r;
    asm("cvt.rn.bf16x2.f32 %0, %1, %2;" : "=r"(r) : "f"(hi), "f"(lo));
    return r;
}
__device__ __forceinline__ float bflo(uint32_t u) { return __uint_as_float(u << 16); }
__device__ __forceinline__ float bfhi(uint32_t u) { return __uint_as_float(u & 0xffff0000u); }
__device__ __forceinline__ void mma_bf16(float c[4], const uint32_t a[4],
                                         uint32_t b0, uint32_t b1) {
    asm volatile("mma.sync.aligned.m16n8k16.row.col.f32.bf16.bf16.f32 "
        "{%0,%1,%2,%3}, {%4,%5,%6,%7}, {%8,%9}, {%0,%1,%2,%3};"
        : "+f"(c[0]), "+f"(c[1]), "+f"(c[2]), "+f"(c[3])
        : "r"(a[0]), "r"(a[1]), "r"(a[2]), "r"(a[3]), "r"(b0), "r"(b1));
}
__device__ __forceinline__ void ldsm_x4(uint32_t a[4], uint32_t saddr) {
    asm volatile("ldmatrix.sync.aligned.m8n8.x4.shared.b16 {%0,%1,%2,%3}, [%4];"
        : "=r"(a[0]), "=r"(a[1]), "=r"(a[2]), "=r"(a[3]) : "r"(saddr));
}
__device__ __forceinline__ uint32_t smem_u32(const void* p) {
    return (uint32_t)__cvta_generic_to_shared(p);
}
__device__ __forceinline__ void red_add_v2(float* p, float a, float b) {
    asm volatile("red.global.add.v2.f32 [%0], {%1, %2};"
                 :: "l"(p), "f"(a), "f"(b) : "memory");
}

__device__ __forceinline__ void store_A(char* Ab, int tid, const float4 va[4]) {
#pragma unroll
    for (int it = 0; it < 4; it++) {
        int seg = tid + it * 256;
        int e = seg >> 3, s8 = seg & 7;
        uint2 u = make_uint2(bf2(va[it].x, va[it].y), bf2(va[it].z, va[it].w));
        *(uint2*)(Ab + e * 80 + s8 * 8) = u;
    }
}

// ===========================================================================
// EDGE KERNEL — persistent grid-stride (592 CTAs = 4/SM), W2 staged ONCE.
// 64-edge tiles, warp = 32 rows x 32 cols, 7 syncs/tile.
// SMEM (53760 B):
//   SB  bf16 [64 x 272B] : S -> h -> m, all in place    0..17408
//   W2S 32768 (persistent across tiles)                 17408..50176
//   misc @ 50176 (3584)
// ===========================================================================
#define E_SB     0
#define E_W2S    17408
#define E_MISC   50176
#define E_STARTS (E_MISC)
#define E_ENDS   (E_MISC + 256)
#define E_EIDX   (E_MISC + 512)
#define E_BE1    (E_MISC + 768)
#define E_BE2    (E_MISC + 1280)
#define E_WIS    (E_MISC + 1792)
#define E_GATES  (E_MISC + 2304)
#define E_GPART  (E_MISC + 2560)          // 64 rows x 4 quarters = 1024B
#define E_SMEM_BYTES (E_MISC + 3584)      // 53760

#define E_GRID 592

__global__ void __launch_bounds__(256, 4)
edge_kernel(const float* __restrict__ nf, const int* __restrict__ ei,
            const float* __restrict__ ef, const float* __restrict__ P,
            const float* __restrict__ be1, const float* __restrict__ be2,
            const float* __restrict__ Wi, const float* __restrict__ bi,
            float* __restrict__ agg) {
    extern __shared__ char smem[];
    char*  SB     = smem + E_SB;                  // 272B row stride, bf16
    int*   starts = (int*)(smem + E_STARTS);
    int*   ends   = (int*)(smem + E_ENDS);
    int*   eidx   = (int*)(smem + E_EIDX);
    float* be1s   = (float*)(smem + E_BE1);
    float* be2s   = (float*)(smem + E_BE2);
    float* wis    = (float*)(smem + E_WIS);
    float* gates  = (float*)(smem + E_GATES);
    float* gpart  = (float*)(smem + E_GPART);

    const int tid  = threadIdx.x;
    const int lane = tid & 31;
    const int wid  = tid >> 5;
    const int wr   = wid & 1;        // row half: rows wr*32 .. +31
    const int wc   = wid >> 1;       // col quarter: cols wc*32 .. +31
    const int g    = lane >> 2;
    const int t    = lane & 3;
    const float bi0 = __ldg(bi);
    const int lm_row = lane & 15;
    const int lm_off = (lane >> 4) << 4;

    // ---- one-time: constants + W2 staging (persistent) ----
    if (tid < 128) {
        be1s[tid] = be1[tid];
        be2s[tid] = be2[tid];
        wis[tid]  = Wi[tid];
    }
    {
        const float4* w2 = (const float4*)g_w2b;
        float4* d2 = (float4*)(smem + E_W2S);
#pragma unroll
        for (int it = 0; it < 8; it++) d2[tid + it * 256] = w2[tid + it * 256];
    }

    for (int tile = blockIdx.x; tile < NE / 64; tile += E_GRID) {
        const int e0 = tile * 64;
        __syncthreads();                               // s1: prev scatter done
        if (tid < 64) {
            int e = g_perm[e0 + tid];
            eidx[tid]   = e;
            starts[tid] = ei[e];
            ends[tid]   = ei[NE + e];
        }
        __syncthreads();                               // s2: idx ready

        // ---- phase A: P gather-add -> SB (bf16) ----
#pragma unroll
        for (int it = 0; it < 8; it++) {
            int seg = tid + it * 256;              // 0..2047
            int row = seg >> 5, c4 = (seg & 31) * 4;
            int s = starts[row], e_ = ends[row];
            float4 a = *(const float4*)(P + (size_t)s * 256 + c4);
            float4 b = *(const float4*)(P + (size_t)e_ * 256 + 128 + c4);
            uint2 u = make_uint2(bf2(a.x + b.x, a.y + b.y),
                                 bf2(a.z + b.z, a.w + b.w));
            *(uint2*)(SB + row * 272 + c4 * 2) = u;
        }

        float acc[2][4][4];
#pragma unroll
        for (int rg = 0; rg < 2; rg++)
#pragma unroll
            for (int nb = 0; nb < 4; nb++)
#pragma unroll
                for (int i = 0; i < 4; i++) acc[rg][nb][i] = 0.0f;

        // ---- ef MMA (K=16): A from global ef, B from global g_wefb ----
#pragma unroll
        for (int rg = 0; rg < 2; rg++) {
            const int R = wr * 32 + rg * 16;
            int ea = eidx[R + g];
            int eb = eidx[R + 8 + g];
            float2 v0 = *(const float2*)(ef + (size_t)ea * DE + 2 * t);
            float2 v1 = *(const float2*)(ef + (size_t)eb * DE + 2 * t);
            float2 v2 = *(const float2*)(ef + (size_t)ea * DE + 8 + 2 * t);
            float2 v3 = *(const float2*)(ef + (size_t)eb * DE + 8 + 2 * t);
            uint32_t a[4] = { bf2(v0.x, v0.y), bf2(v1.x, v1.y),
                              bf2(v2.x, v2.y), bf2(v3.x, v3.y) };
#pragma unroll
            for (int nb = 0; nb < 4; nb++) {
                uint2 b = g_wefb[(wc * 4 + nb) * 32 + lane];
                mma_bf16(acc[rg][nb], a, b.x, b.y);
            }
        }
        __syncthreads();                               // s3: SB ready

        // ---- Epilogue 1: h = silu(acc + S + be1), IN PLACE over SB ----
#pragma unroll
        for (int rg = 0; rg < 2; rg++) {
            const int r0 = wr * 32 + rg * 16 + g;
#pragma unroll
            for (int nb = 0; nb < 4; nb++) {
                int col = wc * 32 + nb * 8 + 2 * t;
                uint32_t s0 = *(const uint32_t*)(SB + r0 * 272 + col * 2);
                uint32_t s1 = *(const uint32_t*)(SB + (r0 + 8) * 272 + col * 2);
                float b0 = be1s[col], b1 = be1s[col + 1];
                uint32_t h0 = bf2(siluf(acc[rg][nb][0] + bflo(s0) + b0),
                                  siluf(acc[rg][nb][1] + bfhi(s0) + b1));
                uint32_t h1 = bf2(siluf(acc[rg][nb][2] + bflo(s1) + b0),
                                  siluf(acc[rg][nb][3] + bfhi(s1) + b1));
                *(uint32_t*)(SB + r0 * 272 + col * 2) = h0;
                *(uint32_t*)(SB + (r0 + 8) * 272 + col * 2) = h1;
                acc[rg][nb][0] = 0.f; acc[rg][nb][1] = 0.f;
                acc[rg][nb][2] = 0.f; acc[rg][nb][3] = 0.f;
            }
        }
        __syncthreads();                               // s4: h ready

        // ---- GEMM2: D2 = h @ We2 (K=128, ldsm A from SB, B from W2S) ----
        {
            const uint2* B2 = (const uint2*)(smem + E_W2S);
#pragma unroll
            for (int K16 = 0; K16 < 8; K16++) {
                uint32_t a[2][4];
#pragma unroll
                for (int rg = 0; rg < 2; rg++) {
                    uint32_t sa = smem_u32(SB + (wr * 32 + rg * 16 + lm_row) * 272
                                           + K16 * 32 + lm_off);
                    ldsm_x4(a[rg], sa);
                }
#pragma unroll
                for (int nb = 0; nb < 4; nb++) {
                    uint2 b = B2[(K16 * 16 + wc * 4 + nb) * 32 + lane];
                    mma_bf16(acc[0][nb], a[0], b.x, b.y);
                    mma_bf16(acc[1][nb], a[1], b.x, b.y);
                }
            }
        }
        __syncthreads();                               // s5: all h reads done

        // ---- Epilogue 2: m = D2 + be2 -> SB IN PLACE (bf16); gate partials ----
#pragma unroll
        for (int rg = 0; rg < 2; rg++) {
            const int r0 = wr * 32 + rg * 16 + g;
            float p0 = 0.f, p1 = 0.f;
#pragma unroll
            for (int nb = 0; nb < 4; nb++) {
                int col = wc * 32 + nb * 8 + 2 * t;
                float b0 = be2s[col], b1 = be2s[col + 1];
                float m0x = acc[rg][nb][0] + b0, m0y = acc[rg][nb][1] + b1;
                float m1x = acc[rg][nb][2] + b0, m1y = acc[rg][nb][3] + b1;
                *(uint32_t*)(SB + r0 * 272 + col * 2) = bf2(m0x, m0y);
                *(uint32_t*)(SB + (r0 + 8) * 272 + col * 2) = bf2(m1x, m1y);
                float w0 = wis[col], w1 = wis[col + 1];
                p0 += m0x * w0 + m0y * w1;
                p1 += m1x * w0 + m1y * w1;
            }
            p0 += __shfl_xor_sync(0xffffffffu, p0, 1);
            p0 += __shfl_xor_sync(0xffffffffu, p0, 2);
            p1 += __shfl_xor_sync(0xffffffffu, p1, 1);
            p1 += __shfl_xor_sync(0xffffffffu, p1, 2);
            if (t == 0) {
                gpart[r0 * 4 + wc] = p0;
                gpart[(r0 + 8) * 4 + wc] = p1;
            }
        }
        __syncthreads();                               // s6
        if (tid < 64)
            gates[tid] = sigmoidf_(gpart[4 * tid] + gpart[4 * tid + 1]
                                   + gpart[4 * tid + 2] + gpart[4 * tid + 3] + bi0);
        __syncthreads();                               // s7

        // ---- segmented gated scatter from bf16 SB (rows sorted by start) ----
        {
            const int cp = tid & 63;          // column pair: cols 2cp, 2cp+1
            const int q  = tid >> 6;          // row quarter: rows q*16 .. +15
            const int rbase = q * 16;
            float a0 = 0.f, a1 = 0.f;
            int sprev = starts[rbase];
#pragma unroll
            for (int i = 0; i < 16; i++) {
                int r = rbase + i;
                int s = starts[r];
                if (s != sprev) {
                    red_add_v2(agg + (size_t)sprev * DM + 2 * cp, a0, a1);
                    a0 = 0.f; a1 = 0.f;
                    sprev = s;
                }
                uint32_t u = *(const uint32_t*)(SB + r * 272 + cp * 4);
                float gt = gates[r];
                a0 += bflo(u) * gt;
                a1 += bfhi(u) * gt;
            }
            red_add_v2(agg + (size_t)sprev * DM + 2 * cp, a0, a1);
        }
    }
}

// ===========================================================================
// Launch 1: hist + weight pack
// ===========================================================================
__device__ __forceinline__ uint2 pack_frag2(const float* W, int idx, int row0, int rowlim) {
    int lane = idx & 31;
    int nbk = idx >> 5;
    int k0 = (nbk >> 4) * 16;
    int n = (nbk & 15) * 8 + (lane >> 2);
    int t2 = (lane & 3) * 2;
    int r = row0 + k0 + t2;
    float v00 = (r     < rowlim) ? W[(size_t)r * 128 + n] : 0.0f;
    float v01 = (r + 1 < rowlim) ? W[(size_t)(r + 1) * 128 + n] : 0.0f;
    float v10 = (r + 8 < rowlim) ? W[(size_t)(r + 8) * 128 + n] : 0.0f;
    float v11 = (r + 9 < rowlim) ? W[(size_t)(r + 9) * 128 + n] : 0.0f;
    return make_uint2(bf2(v00, v01), bf2(v10, v11));
}

__global__ void hist_pack_kernel(const int* __restrict__ ei,
                                 const float* __restrict__ We1, const float* __restrict__ We2,
                                 const float* __restrict__ Wn1, const float* __restrict__ Wn2) {
    int i = blockIdx.x * 256 + threadIdx.x;
    if (i < 4096)        g_wsb[i] = pack_frag2(We1, i, 0, 272);
    else if (i < 8192)   g_web[i - 4096] = pack_frag2(We1, i - 4096, 128, 272);
    else if (i < 9216)   g_wefb[i - 8192] = pack_frag2(We1, i - 8192, 256, 272);
    else if (i < 13312)  g_w2b[i - 9216] = pack_frag2(We2, i - 9216, 0, 128);
    else if (i < 21504)  g_wn1b[i - 13312] = pack_frag2(Wn1, i - 13312, 0, 256);
    else if (i < 25600)  g_wn2b[i - 21504] = pack_frag2(Wn2, i - 21504, 0, 128);
    if (i < NE) atomicAdd(&g_hist[ei[i]], 1);
}

// ===========================================================================
// Launch 2: scan
// ===========================================================================
__global__ void scan_kernel() {
    const int CH = 49;
    __shared__ int ws[32];
    int t = threadIdx.x;
    int base = t * CH;
    int sum = 0;
#pragma unroll 7
    for (int i = 0; i < CH; i++) {
        int idx = base + i;
        if (idx < NN) sum += g_hist[idx];
    }
    int lane = t & 31, wid = t >> 5;
    int v = sum;
#pragma unroll
    for (int o = 1; o < 32; o <<= 1) {
        int u = __shfl_up_sync(0xffffffffu, v, o);
        if (lane >= o) v += u;
    }
    if (lane == 31) ws[wid] = v;
    __syncthreads();
    if (wid == 0) {
        int w = ws[lane];
#pragma unroll
        for (int o = 1; o < 32; o <<= 1) {
            int u = __shfl_up_sync(0xffffffffu, w, o);
            if (lane >= o) w += u;
        }
        ws[lane] = w;
    }
    __syncthreads();
    int pre = v - sum + (wid > 0 ? ws[wid - 1] : 0);
    int run = pre;
    for (int i = 0; i < CH; i++) {
        int idx = base + i;
        if (idx < NN) {
            int h = g_hist[idx];
            g_off[idx] = run;
            run += h;
        }
    }
}

// ===========================================================================
// Launch 3: fused permute + P GEMM
// ===========================================================================
#define PP_PBLK 782
#define P_A 0
#define P_B 34816
#define P_SMEM_BYTES 67584

__global__ void __launch_bounds__(256, 2)
pp_kernel(const int* __restrict__ ei, const float* __restrict__ nf,
          float* __restrict__ P) {
    extern __shared__ char smem[];
    const int tid = threadIdx.x;

    if (blockIdx.x >= PP_PBLK) {
        int e = (blockIdx.x - PP_PBLK) * 256 + tid;
        if (e < NE) {
            int s = ei[e];
            int pos = g_off[s] + atomicAdd(&g_cnt[s], 1);
            g_perm[pos] = e;
        }
        return;
    }

    char* Ab = smem + P_A;
    const int lane = tid & 31;
    const int wid  = tid >> 5;
    const int wr   = wid & 3;
    const int wc   = wid >> 2;
    const int g    = lane >> 2;
    const int t    = lane & 3;
    const int n0   = (blockIdx.x % 391) * 128;
    const int half = blockIdx.x / 391;

    {
        const float4* src = (const float4*)(half ? g_web : g_wsb);
        float4* dst = (float4*)(smem + P_B);
#pragma unroll
        for (int it = 0; it < 8; it++) dst[tid + it * 256] = src[tid + it * 256];
    }
#pragma unroll
    for (int it = 0; it < 8; it++) {
        int seg = tid + it * 256;
        int row = seg >> 4, c8 = seg & 15;
        int n = n0 + row; if (n >= NN) n = NN - 1;
        float4 f0 = *(const float4*)(nf + (size_t)n * D + c8 * 8);
        float4 f1 = *(const float4*)(nf + (size_t)n * D + c8 * 8 + 4);
        uint4 u = make_uint4(bf2(f0.x, f0.y), bf2(f0.z, f0.w),
                             bf2(f1.x, f1.y), bf2(f1.z, f1.w));
        *(uint4*)(Ab + row * 272 + c8 * 16) = u;
    }
    __syncthreads();

    float acc[2][8][4];
#pragma unroll
    for (int rg = 0; rg < 2; rg++)
#pragma unroll
        for (int nb = 0; nb < 8; nb++)
#pragma unroll
            for (int i = 0; i < 4; i++) acc[rg][nb][i] = 0.0f;

    {
        const uint2* Bs = (const uint2*)(smem + P_B);
#pragma unroll
        for (int K16 = 0; K16 < 8; K16++) {
            uint32_t a[2][4];
#pragma unroll
            for (int rg = 0; rg < 2; rg++) {
                const char* p = Ab + (wr * 32 + rg * 16 + g) * 272 + K16 * 32 + t * 4;
                a[rg][0] = *(const uint32_t*)p;
                a[rg][1] = *(const uint32_t*)(p + 8 * 272);
                a[rg][2] = *(const uint32_t*)(p + 16);
                a[rg][3] = *(const uint32_t*)(p + 8 * 272 + 16);
            }
#pragma unroll
            for (int nb = 0; nb < 8; nb++) {
                uint2 b = Bs[(K16 * 16 + wc * 8 + nb) * 32 + lane];
                mma_bf16(acc[0][nb], a[0], b.x, b.y);
                mma_bf16(acc[1][nb], a[1], b.x, b.y);
            }
        }
    }

#pragma unroll
    for (int rg = 0; rg < 2; rg++) {
        int r0 = wr * 32 + rg * 16 + g;
#pragma unroll
        for (int h = 0; h < 2; h++) {
            int n = n0 + r0 + 8 * h;
            if (n >= NN) continue;
#pragma unroll
            for (int nb = 0; nb < 8; nb++) {
                int col = wc * 64 + nb * 8 + 2 * t;
                float a0 = h ? acc[rg][nb][2] : acc[rg][nb][0];
                float a1 = h ? acc[rg][nb][3] : acc[rg][nb][1];
                *(float2*)(P + (size_t)n * 256 + half * 128 + col) = make_float2(a0, a1);
            }
        }
    }
}

// ===========================================================================
// Launch 5: node kernel — bf16 mma, fp32 residual (validated R7-R15)
// ===========================================================================
#define N_A0  0
#define N_A1  10240
#define N_B0  20480
#define N_B1  28672
#define N_HB  36864
#define N_BN1 71680
#define N_BN2 72192
#define N_SMEM_BYTES 72704

__global__ void __launch_bounds__(256, 2)
node_kernel(const float* __restrict__ nf, const float* __restrict__ agg,
            const float* __restrict__ bn1, const float* __restrict__ bn2,
            float* __restrict__ out) {
    extern __shared__ char smem[];
    char*  hbuf  = smem + N_HB;
    float* bn1s  = (float*)(smem + N_BN1);
    float* bn2s  = (float*)(smem + N_BN2);

    const int tid  = threadIdx.x;
    const int lane = tid & 31;
    const int wid  = tid >> 5;
    const int wr   = wid & 3;
    const int wc   = wid >> 2;
    const int g    = lane >> 2;
    const int t    = lane & 3;
    const int n0   = blockIdx.x * 128;

    if (tid < 128) { bn1s[tid] = bn1[tid]; bn2s[tid] = bn2[tid]; }

    float acc[2][8][4];
#pragma unroll
    for (int rg = 0; rg < 2; rg++)
#pragma unroll
        for (int nb = 0; nb < 8; nb++)
#pragma unroll
            for (int i = 0; i < 4; i++) acc[rg][nb][i] = 0.0f;

    {
        float4 va[4], vb[2];
        const float4* w1 = (const float4*)g_wn1b;
#pragma unroll
        for (int it = 0; it < 4; it++) {
            int seg = tid + it * 256;
            int e = seg >> 3, s8 = seg & 7;
            int n = n0 + e; if (n >= NN) n = NN - 1;
            va[it] = *(const float4*)(nf + (size_t)n * D + s8 * 4);
        }
#pragma unroll
        for (int it = 0; it < 2; it++) vb[it] = w1[tid + it * 256];
        store_A(smem + N_A0, tid, va);
        {
            float4* dst = (float4*)(smem + N_B0);
#pragma unroll
            for (int it = 0; it < 2; it++) dst[tid + it * 256] = vb[it];
        }
        __syncthreads();

        for (int c = 0; c < 8; c++) {
            const int buf = c & 1;
            if (c < 7) {
                int cn = c + 1;
#pragma unroll
                for (int it = 0; it < 4; it++) {
                    int seg = tid + it * 256;
                    int e = seg >> 3, s8 = seg & 7;
                    int n = n0 + e; if (n >= NN) n = NN - 1;
                    const float* src = (cn < 4)
                        ? nf  + (size_t)n * D  + cn * 32 + s8 * 4
                        : agg + (size_t)n * DM + (cn - 4) * 32 + s8 * 4;
                    va[it] = *(const float4*)src;
                }
#pragma unroll
                for (int it = 0; it < 2; it++)
                    vb[it] = w1[cn * 512 + tid + it * 256];
            }
            const char* Ab = smem + (buf ? N_A1 : N_A0);
            const uint2* Bs = (const uint2*)(smem + (buf ? N_B1 : N_B0));
#pragma unroll
            for (int kcl = 0; kcl < 2; kcl++) {
                uint32_t a[2][4];
#pragma unroll
                for (int rg = 0; rg < 2; rg++) {
                    const char* p = Ab + (wr * 32 + rg * 16 + g) * 80 + kcl * 32 + t * 4;
                    a[rg][0] = *(const uint32_t*)p;
                    a[rg][1] = *(const uint32_t*)(p + 8 * 80);
                    a[rg][2] = *(const uint32_t*)(p + 16);
                    a[rg][3] = *(const uint32_t*)(p + 8 * 80 + 16);
                }
#pragma unroll
                for (int nb = 0; nb < 8; nb++) {
                    uint2 b = Bs[(kcl * 16 + wc * 8 + nb) * 32 + lane];
                    mma_bf16(acc[0][nb], a[0], b.x, b.y);
                    mma_bf16(acc[1][nb], a[1], b.x, b.y);
                }
            }
            __syncthreads();
            if (c < 7) {
                store_A(smem + (((c + 1) & 1) ? N_A1 : N_A0), tid, va);
                float4* dst = (float4*)(smem + (((c + 1) & 1) ? N_B1 : N_B0));
#pragma unroll
                for (int it = 0; it < 2; it++) dst[tid + it * 256] = vb[it];
                __syncthreads();
            }
        }
    }

    {
        const float4* src = (const float4*)g_wn2b;
        float4* dst = (float4*)(smem + N_A0);
#pragma unroll
        for (int it = 0; it < 8; it++) dst[tid + it * 256] = src[tid + it * 256];
    }
#pragma unroll
    for (int rg = 0; rg < 2; rg++) {
        int row0 = wr * 32 + rg * 16 + g;
#pragma unroll
        for (int nb = 0; nb < 8; nb++) {
            int col = wc * 64 + nb * 8 + 2 * t;
            float b0 = bn1s[col], b1 = bn1s[col + 1];
            uint32_t h0 = bf2(siluf(acc[rg][nb][0] + b0), siluf(acc[rg][nb][1] + b1));
            uint32_t h1 = bf2(siluf(acc[rg][nb][2] + b0), siluf(acc[rg][nb][3] + b1));
            *(uint32_t*)(hbuf + row0 * 272 + col * 2) = h0;
            *(uint32_t*)(hbuf + (row0 + 8) * 272 + col * 2) = h1;
            acc[rg][nb][0] = 0.f; acc[rg][nb][1] = 0.f;
            acc[rg][nb][2] = 0.f; acc[rg][nb][3] = 0.f;
        }
    }
    __syncthreads();

    {
        const uint2* B2 = (const uint2*)(smem + N_A0);
#pragma unroll
        for (int K16 = 0; K16 < 8; K16++) {
            uint32_t a[2][4];
#pragma unroll
            for (int rg = 0; rg < 2; rg++) {
                const char* p = hbuf + (wr * 32 + rg * 16 + g) * 272 + K16 * 32 + t * 4;
                a[rg][0] = *(const uint32_t*)p;
                a[rg][1] = *(const uint32_t*)(p + 8 * 272);
                a[rg][2] = *(const uint32_t*)(p + 16);
                a[rg][3] = *(const uint32_t*)(p + 8 * 272 + 16);
            }
#pragma unroll
            for (int nb = 0; nb < 8; nb++) {
                uint2 b = B2[(K16 * 16 + wc * 8 + nb) * 32 + lane];
                mma_bf16(acc[0][nb], a[0], b.x, b.y);
                mma_bf16(acc[1][nb], a[1], b.x, b.y);
            }
        }
    }

#pragma unroll
    for (int rg = 0; rg < 2; rg++) {
        int r0 = wr * 32 + rg * 16 + g;
#pragma unroll
        for (int h = 0; h < 2; h++) {
            int n = n0 + r0 + 8 * h;
            if (n >= NN) continue;
#pragma unroll
            for (int nb = 0; nb < 8; nb++) {
                int col = wc * 64 + nb * 8 + 2 * t;
                float2 res = *(const float2*)(nf + (size_t)n * D + col);
                float a0 = (h ? acc[rg][nb][2] : acc[rg][nb][0]) + bn2s[col] + res.x;
                float a1 = (h ? acc[rg][nb][3] : acc[rg][nb][1]) + bn2s[col + 1] + res.y;
                *(float2*)(out + (size_t)n * D + col) = make_float2(a0, a1);
            }
        }
    }
}

// ===========================================================================
// Launch 6: idx passthrough + cleanup for next call
// ===========================================================================
__global__ void idx_cleanup_kernel(const int4* __restrict__ ei,
                                   float4* __restrict__ out) {
    int i = blockIdx.x * blockDim.x + threadIdx.x;
    if (i < (2 * NE) / 4) {
        int4 v = ei[i];
        out[i] = make_float4((float)v.x, (float)v.y, (float)v.z, (float)v.w);
    }
    float4 z4 = make_float4(0.f, 0.f, 0.f, 0.f);
    for (int j = i; j < NN * DM / 4; j += 400128)
        ((float4*)g_agg)[j] = z4;
    if (i < NN) { g_hist[i] = 0; g_cnt[i] = 0; }
}

// ---------------------------------------------------------------------------
extern "C" void kernel_launch(void* const* d_in, const int* in_sizes, int n_in,
                              void* d_out, int out_size) {
    const float* nf  = (const float*)d_in[0];
    const int*   ei  = (const int*)d_in[1];
    const float* ef  = (const float*)d_in[2];
    const float* We1 = (const float*)d_in[3];
    const float* be1 = (const float*)d_in[4];
    const float* We2 = (const float*)d_in[5];
    const float* be2 = (const float*)d_in[6];
    const float* Wi  = (const float*)d_in[7];
    const float* bi  = (const float*)d_in[8];
    const float* Wn1 = (const float*)d_in[9];
    const float* bn1 = (const float*)d_in[10];
    const float* Wn2 = (const float*)d_in[11];
    const float* bn2 = (const float*)d_in[12];
    float* out = (float*)d_out;

    cudaFuncSetAttribute(edge_kernel, cudaFuncAttributeMaxDynamicSharedMemorySize, E_SMEM_BYTES);
    cudaFuncSetAttribute(node_kernel, cudaFuncAttributeMaxDynamicSharedMemorySize, N_SMEM_BYTES);
    cudaFuncSetAttribute(pp_kernel, cudaFuncAttributeMaxDynamicSharedMemorySize, P_SMEM_BYTES);

    void *aggp, *pp;
    cudaGetSymbolAddress(&aggp, g_agg);
    cudaGetSymbolAddress(&pp, g_P);

    hist_pack_kernel<<<3125, 256>>>(ei, We1, We2, Wn1, Wn2);              // k1
    scan_kernel<<<1, 1024>>>();                                           // k2
    pp_kernel<<<PP_PBLK + 3125, 256, P_SMEM_BYTES>>>(ei, nf, (float*)pp); // k3
    edge_kernel<<<E_GRID, 256, E_SMEM_BYTES>>>(nf, ei, ef, (const float*)pp,
                                               be1, be2, Wi, bi, (float*)aggp);  // k4
    node_kernel<<<(NN + 127) / 128, 256, N_SMEM_BYTES>>>(nf, (const float*)aggp,
                                                         bn1, bn2, out);          // k5
    idx_cleanup_kernel<<<1563, 256>>>((const int4*)ei,
                                      (float4*)(out + (size_t)NN * D));           // k6
    cudaMemcpyAsync(out + (size_t)NN * D + 2ull * NE, d_in[2],
                    (size_t)NE * DE * sizeof(float), cudaMemcpyDeviceToDevice);
}